// round 5
// baseline (speedup 1.0000x reference)
#include <cuda_runtime.h>
#include <math.h>

#define B 2
#define S 2048
#define E 768
#define H 12
#define D 64
#define BSZ (B*S)
#define QKV_ELEMS (B*H*S*D)

// Scratch (allocation-free rule: device globals)
__device__ float g_Q[QKV_ELEMS];
__device__ float g_K[QKV_ELEMS];
__device__ float g_V[QKV_ELEMS];
__device__ float g_att[BSZ*E];
__device__ float g_maskadd[BSZ];
__device__ float g_kbias[B*H*S];

// ---------------------------------------------------------------------------
// helpers
// ---------------------------------------------------------------------------
__device__ __forceinline__ unsigned f2tf(float f) {
    unsigned u;
    asm("cvt.rna.tf32.f32 %0, %1;" : "=r"(u) : "f"(f));
    return u;
}
// 3xTF32 operand split: x ~= hi + lo, both tf32
__device__ __forceinline__ void splt(float f, unsigned& hi, unsigned& lo) {
    hi = f2tf(f);
    lo = f2tf(f - __uint_as_float(hi));
}

// D(16x8,f32) += A(16x8,tf32,row) * B(8x8,tf32,col)
__device__ __forceinline__ void mma8(float* c, const unsigned* a,
                                     unsigned b0, unsigned b1) {
    asm volatile(
        "mma.sync.aligned.m16n8k8.row.col.f32.tf32.tf32.f32 "
        "{%0,%1,%2,%3},{%4,%5,%6,%7},{%8,%9},{%0,%1,%2,%3};"
        : "+f"(c[0]), "+f"(c[1]), "+f"(c[2]), "+f"(c[3])
        : "r"(a[0]), "r"(a[1]), "r"(a[2]), "r"(a[3]), "r"(b0), "r"(b1));
}

// ---------------------------------------------------------------------------
// Mask normalization (dtype-agnostic) -> g_maskadd
// ---------------------------------------------------------------------------
__global__ void mask_prep_kernel(const unsigned char* __restrict__ m)
{
    __shared__ int cls[4];
    int tid = threadIdx.x;
    if (tid < 4) cls[tid] = 0;
    __syncthreads();
    for (int i = tid; i < BSZ; i += blockDim.x)
        if (m[i]) atomicAdd(&cls[i & 3], 1);
    __syncthreads();
    int mode = 0;                                              // u8
    if (cls[1] == 0 && cls[2] == 0 && cls[3] == 0) mode = 1;   // int32
    else if (cls[0] == 0 && cls[1] == 0)           mode = 2;   // float32
    for (int i = tid; i < BSZ; i += blockDim.x) {
        bool v;
        if (mode == 1)      v = ((const int*)m)[i] != 0;
        else if (mode == 2) v = ((const float*)m)[i] != 0.0f;
        else                v = m[i] != 0;
        g_maskadd[i] = v ? 0.0f : -1e30f;
    }
}

__global__ void kbias_kernel(const float* __restrict__ pb,
                             const float* __restrict__ coeff)
{
    int idx = blockIdx.x * 256 + threadIdx.x;
    int bh = idx / S, k = idx - bh * S;
    int b = bh / H, h = bh - b * H;
    g_kbias[idx] = -coeff[h] * pb[b * S + k] + g_maskadd[b * S + k];
}

// ---------------------------------------------------------------------------
// GEMM smem layout (qkv / oproj):
//   per row: 16 k-values x 2 planes interleaved,
//   element d -> word (d>>3)*16 + (d&3)*4 + ((d&4)?2:0) + plane, pitch 48.
//   As @0 (128x48), Bs @6144, total 12288 words = 49152 B dynamic smem.
// ---------------------------------------------------------------------------
#define GPITCH 48
#define GB_OFF 6144
#define GEMM_SMEM_WORDS 12288

__device__ __forceinline__ void g_stage(unsigned* smbase, int r, int c4,
                                        float4 v) {
    unsigned* p = smbase + r * GPITCH + ((c4 >> 3) << 4) + ((c4 & 4) ? 2 : 0);
    unsigned hi, lo;
    splt(v.x, hi, lo); p[0]  = hi; p[1]  = lo;
    splt(v.y, hi, lo); p[4]  = hi; p[5]  = lo;
    splt(v.z, hi, lo); p[8]  = hi; p[9]  = lo;
    splt(v.w, hi, lo); p[12] = hi; p[13] = lo;
}

// ---------------------------------------------------------------------------
// QKV projection, 3xTF32, vectorized fragment loads, reg-prefetch k-slices.
// ---------------------------------------------------------------------------
__global__ __launch_bounds__(256)
void qkv_kernel(const float* __restrict__ Xq, const float* __restrict__ Xk,
                const float* __restrict__ Xv,
                const float* __restrict__ Wq, const float* __restrict__ Wk,
                const float* __restrict__ Wv,
                const float* __restrict__ bq, const float* __restrict__ bk,
                const float* __restrict__ bv)
{
    const int z = blockIdx.z;
    const float* X    = (z == 0) ? Xq : (z == 1) ? Xk : Xv;
    const float* W    = (z == 0) ? Wq : (z == 1) ? Wk : Wv;
    const float* bias = (z == 0) ? bq : (z == 1) ? bk : bv;
    float* out        = (z == 0) ? g_Q : (z == 1) ? g_K : g_V;
    const bool rope = (z < 2);

    extern __shared__ unsigned gsm[];

    const int tid = threadIdx.x;
    const int w = tid >> 5, wm = w >> 2, wn = w & 3;
    const int lane = tid & 31, g = lane >> 2, tig = lane & 3;
    const int m0 = blockIdx.y * 128, n0 = blockIdx.x * 128;

    // staging coordinates: two slots per thread cover 128 rows x 16 cols
    int srow[2], scol[2];
    #pragma unroll
    for (int t = 0; t < 2; t++) {
        int i = tid + t * 256;
        srow[t] = i >> 2;            // 0..127
        scol[t] = (i & 3) << 2;      // 0,4,8,12
    }

    float acc[4][4][4];
    #pragma unroll
    for (int a = 0; a < 4; a++)
        #pragma unroll
        for (int b2 = 0; b2 < 4; b2++)
            #pragma unroll
            for (int c = 0; c < 4; c++) acc[a][b2][c] = 0.0f;

    float4 areg[2], breg[2];
    #pragma unroll
    for (int t = 0; t < 2; t++) {
        areg[t] = *(const float4*)(X + (size_t)(m0 + srow[t]) * E + scol[t]);
        breg[t] = *(const float4*)(W + (size_t)(n0 + srow[t]) * E + scol[t]);
    }

    for (int k0 = 0; k0 < E; k0 += 16) {
        #pragma unroll
        for (int t = 0; t < 2; t++) {
            g_stage(gsm, srow[t], scol[t], areg[t]);
            g_stage(gsm + GB_OFF, srow[t], scol[t], breg[t]);
        }
        __syncthreads();
        if (k0 + 16 < E) {
            #pragma unroll
            for (int t = 0; t < 2; t++) {
                areg[t] = *(const float4*)(X + (size_t)(m0 + srow[t]) * E +
                                           k0 + 16 + scol[t]);
                breg[t] = *(const float4*)(W + (size_t)(n0 + srow[t]) * E +
                                           k0 + 16 + scol[t]);
            }
        }
        #pragma unroll
        for (int grp = 0; grp < 2; grp++) {
            unsigned afh[4][4], afl[4][4], bh0[4], bl0[4], bh1[4], bl1[4];
            #pragma unroll
            for (int fm = 0; fm < 4; fm++) {
                int rb = wm * 64 + fm * 16 + g;
                uint4 ua = *(uint4*)&gsm[rb * GPITCH + grp * 16 + tig * 4];
                uint4 ub = *(uint4*)&gsm[(rb + 8) * GPITCH + grp * 16 + tig * 4];
                afh[fm][0] = ua.x; afh[fm][1] = ub.x;
                afh[fm][2] = ua.z; afh[fm][3] = ub.z;
                afl[fm][0] = ua.y; afl[fm][1] = ub.y;
                afl[fm][2] = ua.w; afl[fm][3] = ub.w;
            }
            #pragma unroll
            for (int fn = 0; fn < 4; fn++) {
                int cb = wn * 32 + fn * 8 + g;
                uint4 vb = *(uint4*)&gsm[GB_OFF + cb * GPITCH + grp * 16 + tig * 4];
                bh0[fn] = vb.x; bl0[fn] = vb.y; bh1[fn] = vb.z; bl1[fn] = vb.w;
            }
            #pragma unroll
            for (int fm = 0; fm < 4; fm++)
                #pragma unroll
                for (int fn = 0; fn < 4; fn++) {
                    mma8(acc[fm][fn], afh[fm], bh0[fn], bh1[fn]);
                    mma8(acc[fm][fn], afl[fm], bh0[fn], bh1[fn]);
                    mma8(acc[fm][fn], afh[fm], bl0[fn], bl1[fn]);
                }
        }
        __syncthreads();
    }

    // epilogue: bias + RoPE + transpose to [B,H,S,D]
    #pragma unroll
    for (int fn = 0; fn < 4; fn++) {
        const int col = n0 + wn * 32 + fn * 8 + 2 * tig;   // even
        const int h = col / D, d = col % D;
        const float b0v = bias[col], b1v = bias[col + 1];
        const float invf = rope
            ? exp2f(-(float)d * (13.287712379549449f / 64.0f)) : 0.0f;
        #pragma unroll
        for (int fm = 0; fm < 4; fm++) {
            const int row = m0 + wm * 64 + fm * 16 + g;
            #pragma unroll
            for (int half = 0; half < 2; half++) {
                const int r = row + half * 8;
                const int bb = r >> 11, s = r & 2047;
                float v0 = acc[fm][fn][half * 2 + 0] + b0v;
                float v1 = acc[fm][fn][half * 2 + 1] + b1v;
                if (rope) {
                    float sn, cs;
                    sincosf((float)s * invf, &sn, &cs);
                    float t0 = v0 * cs - v1 * sn;
                    v1 = v1 * cs + v0 * sn;
                    v0 = t0;
                }
                *(float2*)&out[(((size_t)bb * H + h) * S + s) * D + d] =
                    make_float2(v0, v1);
            }
        }
    }
}

// ---------------------------------------------------------------------------
// Output projection (same scheme, no rope)
// ---------------------------------------------------------------------------
__global__ __launch_bounds__(256)
void oproj_kernel(const float* __restrict__ Wf, const float* __restrict__ bias,
                  float* __restrict__ out)
{
    extern __shared__ unsigned gsm[];

    const int tid = threadIdx.x;
    const int w = tid >> 5, wm = w >> 2, wn = w & 3;
    const int lane = tid & 31, g = lane >> 2, tig = lane & 3;
    const int m0 = blockIdx.y * 128, n0 = blockIdx.x * 128;

    int srow[2], scol[2];
    #pragma unroll
    for (int t = 0; t < 2; t++) {
        int i = tid + t * 256;
        srow[t] = i >> 2;
        scol[t] = (i & 3) << 2;
    }

    float acc[4][4][4];
    #pragma unroll
    for (int a = 0; a < 4; a++)
        #pragma unroll
        for (int b2 = 0; b2 < 4; b2++)
            #pragma unroll
            for (int c = 0; c < 4; c++) acc[a][b2][c] = 0.0f;

    float4 areg[2], breg[2];
    #pragma unroll
    for (int t = 0; t < 2; t++) {
        areg[t] = *(const float4*)(g_att + (size_t)(m0 + srow[t]) * E + scol[t]);
        breg[t] = *(const float4*)(Wf + (size_t)(n0 + srow[t]) * E + scol[t]);
    }

    for (int k0 = 0; k0 < E; k0 += 16) {
        #pragma unroll
        for (int t = 0; t < 2; t++) {
            g_stage(gsm, srow[t], scol[t], areg[t]);
            g_stage(gsm + GB_OFF, srow[t], scol[t], breg[t]);
        }
        __syncthreads();
        if (k0 + 16 < E) {
            #pragma unroll
            for (int t = 0; t < 2; t++) {
                areg[t] = *(const float4*)(g_att + (size_t)(m0 + srow[t]) * E +
                                           k0 + 16 + scol[t]);
                breg[t] = *(const float4*)(Wf + (size_t)(n0 + srow[t]) * E +
                                           k0 + 16 + scol[t]);
            }
        }
        #pragma unroll
        for (int grp = 0; grp < 2; grp++) {
            unsigned afh[4][4], afl[4][4], bh0[4], bl0[4], bh1[4], bl1[4];
            #pragma unroll
            for (int fm = 0; fm < 4; fm++) {
                int rb = wm * 64 + fm * 16 + g;
                uint4 ua = *(uint4*)&gsm[rb * GPITCH + grp * 16 + tig * 4];
                uint4 ub = *(uint4*)&gsm[(rb + 8) * GPITCH + grp * 16 + tig * 4];
                afh[fm][0] = ua.x; afh[fm][1] = ub.x;
                afh[fm][2] = ua.z; afh[fm][3] = ub.z;
                afl[fm][0] = ua.y; afl[fm][1] = ub.y;
                afl[fm][2] = ua.w; afl[fm][3] = ub.w;
            }
            #pragma unroll
            for (int fn = 0; fn < 4; fn++) {
                int cb = wn * 32 + fn * 8 + g;
                uint4 vb = *(uint4*)&gsm[GB_OFF + cb * GPITCH + grp * 16 + tig * 4];
                bh0[fn] = vb.x; bl0[fn] = vb.y; bh1[fn] = vb.z; bl1[fn] = vb.w;
            }
            #pragma unroll
            for (int fm = 0; fm < 4; fm++)
                #pragma unroll
                for (int fn = 0; fn < 4; fn++) {
                    mma8(acc[fm][fn], afh[fm], bh0[fn], bh1[fn]);
                    mma8(acc[fm][fn], afl[fm], bh0[fn], bh1[fn]);
                    mma8(acc[fm][fn], afh[fm], bl0[fn], bl1[fn]);
                }
        }
        __syncthreads();
    }

    #pragma unroll
    for (int fn = 0; fn < 4; fn++) {
        const int col = n0 + wn * 32 + fn * 8 + 2 * tig;
        const float b0v = bias[col], b1v = bias[col + 1];
        #pragma unroll
        for (int fm = 0; fm < 4; fm++) {
            const int row = m0 + wm * 64 + fm * 16 + g;
            #pragma unroll
            for (int half = 0; half < 2; half++) {
                const int r = row + half * 8;
                *(float2*)&out[(size_t)r * E + col] =
                    make_float2(acc[fm][fn][half * 2 + 0] + b0v,
                                acc[fm][fn][half * 2 + 1] + b1v);
            }
        }
    }
}

// ---------------------------------------------------------------------------
// Flash attention, 3xTF32, vectorized smem layouts + K/V register prefetch.
//  K : 32 rows x pitch 144  (8 d-groups x [hi,lo,hi+4,lo+4] x4)  @ 0
//  V : 32 rows x pitch 136  (word = d*2 + plane)                 @ 4608
//  P : per-warp 16 rows x pitch 80 (4 k-groups x 16 words)       @ 8960
// ---------------------------------------------------------------------------
#define KS_OFF 0
#define VS_OFF 4608
#define PS_OFF 8960
#define KPITCH 144
#define VPITCH 136
#define PPITCH 80
#define ATT_SMEM_WORDS 19200   // 76,800 B

__global__ __launch_bounds__(256)
void attn_kernel(const float* __restrict__ pb, const float* __restrict__ coeff)
{
    extern __shared__ unsigned sm[];

    const int tid = threadIdx.x;
    const int w = tid >> 5, lane = tid & 31, g = lane >> 2, tig = lane & 3;
    const int b = blockIdx.z, h = blockIdx.y, q0 = blockIdx.x * 128;

    const float* Qg = g_Q + (size_t)(b * H + h) * S * D;
    const float* Kg = g_K + (size_t)(b * H + h) * S * D;
    const float* Vg = g_V + (size_t)(b * H + h) * S * D;
    const float* kbp = g_kbias + (size_t)(b * H + h) * S;

    // prefetch first K/V tile while staging Q
    float4 kreg[2], vreg[2];
    #pragma unroll
    for (int t = 0; t < 2; t++) {
        int i = tid + t * 256;
        int r = i >> 4, c4 = (i & 15) << 2;
        kreg[t] = *(const float4*)(Kg + (size_t)r * D + c4);
        vreg[t] = *(const float4*)(Vg + (size_t)r * D + c4);
    }

    // ---- stage Q in 4 chunks of 32 rows through the K region ----
    unsigned qa[2][8][4];
    for (int chunk = 0; chunk < 4; chunk++) {
        #pragma unroll
        for (int t = 0; t < 2; t++) {
            int i = tid + t * 256;
            int r = i >> 4, c4 = (i & 15) << 2;
            float4 v = *(const float4*)(Qg + (size_t)(q0 + chunk * 32 + r) * D + c4);
            unsigned* p = &sm[KS_OFF + r * KPITCH + ((c4 >> 3) << 4) +
                              ((c4 & 4) ? 2 : 0)];
            unsigned hi, lo;
            splt(v.x, hi, lo); p[0]  = hi; p[1]  = lo;
            splt(v.y, hi, lo); p[4]  = hi; p[5]  = lo;
            splt(v.z, hi, lo); p[8]  = hi; p[9]  = lo;
            splt(v.w, hi, lo); p[12] = hi; p[13] = lo;
        }
        __syncthreads();
        if ((w >> 1) == chunk) {
            int lrq = (w & 1) * 16 + g;
            #pragma unroll
            for (int kk = 0; kk < 8; kk++) {
                uint4 ua = *(uint4*)&sm[KS_OFF + lrq * KPITCH + kk * 16 + tig * 4];
                uint4 ub = *(uint4*)&sm[KS_OFF + (lrq + 8) * KPITCH + kk * 16 + tig * 4];
                qa[0][kk][0] = ua.x; qa[0][kk][1] = ub.x;
                qa[0][kk][2] = ua.z; qa[0][kk][3] = ub.z;
                qa[1][kk][0] = ua.y; qa[1][kk][1] = ub.y;
                qa[1][kk][2] = ua.w; qa[1][kk][3] = ub.w;
            }
        }
        __syncthreads();
    }

    const float coeff_h = coeff[h];
    float rowb[2];
    rowb[0] = coeff_h * pb[b * S + q0 + w * 16 + g];
    rowb[1] = coeff_h * pb[b * S + q0 + w * 16 + g + 8];

    float mi[2] = {-1e30f, -1e30f}, li[2] = {0.0f, 0.0f};
    float o[8][4];
    #pragma unroll
    for (int nf = 0; nf < 8; nf++)
        #pragma unroll
        for (int c = 0; c < 4; c++) o[nf][c] = 0.0f;

    const int psw = PS_OFF + w * 1280;

    for (int k0 = 0; k0 < S; k0 += 32) {
        // ---- store prefetched K/V tile into interleaved smem ----
        #pragma unroll
        for (int t = 0; t < 2; t++) {
            int i = tid + t * 256;
            int r = i >> 4, c4 = (i & 15) << 2;
            unsigned* kp = &sm[KS_OFF + r * KPITCH + ((c4 >> 3) << 4) +
                               ((c4 & 4) ? 2 : 0)];
            unsigned hi, lo;
            splt(kreg[t].x, hi, lo); kp[0]  = hi; kp[1]  = lo;
            splt(kreg[t].y, hi, lo); kp[4]  = hi; kp[5]  = lo;
            splt(kreg[t].z, hi, lo); kp[8]  = hi; kp[9]  = lo;
            splt(kreg[t].w, hi, lo); kp[12] = hi; kp[13] = lo;
            unsigned* vp = &sm[VS_OFF + r * VPITCH + c4 * 2];
            unsigned h0, l0, h1, l1;
            splt(vreg[t].x, h0, l0); splt(vreg[t].y, h1, l1);
            *(uint4*)vp = make_uint4(h0, l0, h1, l1);
            splt(vreg[t].z, h0, l0); splt(vreg[t].w, h1, l1);
            *(uint4*)(vp + 4) = make_uint4(h0, l0, h1, l1);
        }
        __syncthreads();

        // ---- prefetch next tile ----
        if (k0 + 32 < S) {
            #pragma unroll
            for (int t = 0; t < 2; t++) {
                int i = tid + t * 256;
                int r = i >> 4, c4 = (i & 15) << 2;
                kreg[t] = *(const float4*)(Kg + (size_t)(k0 + 32 + r) * D + c4);
                vreg[t] = *(const float4*)(Vg + (size_t)(k0 + 32 + r) * D + c4);
            }
        }

        // ---- S = Q K^T, 3xTF32 ----
        float sc[4][4];
        #pragma unroll
        for (int fn = 0; fn < 4; fn++)
            #pragma unroll
            for (int c = 0; c < 4; c++) sc[fn][c] = 0.0f;

        #pragma unroll
        for (int kk = 0; kk < 8; kk++) {
            #pragma unroll
            for (int fn = 0; fn < 4; fn++) {
                uint4 kb = *(uint4*)&sm[KS_OFF + (fn * 8 + g) * KPITCH +
                                        kk * 16 + tig * 4];
                mma8(sc[fn], qa[0][kk], kb.x, kb.z);
                mma8(sc[fn], qa[1][kk], kb.x, kb.z);
                mma8(sc[fn], qa[0][kk], kb.y, kb.w);
            }
        }

        // ---- scale + rel-pos bias + mask ----
        #pragma unroll
        for (int fn = 0; fn < 4; fn++) {
            int c = k0 + fn * 8 + 2 * tig;
            float cb0 = kbp[c], cb1 = kbp[c + 1];
            sc[fn][0] = sc[fn][0] * 0.125f + rowb[0] + cb0;
            sc[fn][1] = sc[fn][1] * 0.125f + rowb[0] + cb1;
            sc[fn][2] = sc[fn][2] * 0.125f + rowb[1] + cb0;
            sc[fn][3] = sc[fn][3] * 0.125f + rowb[1] + cb1;
        }

        // ---- online softmax; P stored hi/lo interleaved ----
        #pragma unroll
        for (int rh = 0; rh < 2; rh++) {
            float tm = -1e30f;
            #pragma unroll
            for (int fn = 0; fn < 4; fn++)
                tm = fmaxf(tm, fmaxf(sc[fn][2 * rh], sc[fn][2 * rh + 1]));
            tm = fmaxf(tm, __shfl_xor_sync(0xffffffffu, tm, 1));
            tm = fmaxf(tm, __shfl_xor_sync(0xffffffffu, tm, 2));
            float mnew = fmaxf(fmaxf(mi[rh], tm), -1e20f);
            float psum = 0.0f;
            const int prow = psw + (g + rh * 8) * PPITCH;
            const int hoff = (tig & 2) ? 2 : 0;
            #pragma unroll
            for (int fn = 0; fn < 4; fn++) {
                float p0 = __expf(sc[fn][2 * rh] - mnew);
                float p1 = __expf(sc[fn][2 * rh + 1] - mnew);
                psum += p0 + p1;
                unsigned hi, lo;
                splt(p0, hi, lo);
                *(uint2*)&sm[prow + fn * 16 + ((2 * tig) & 3) * 4 + hoff] =
                    make_uint2(hi, lo);
                splt(p1, hi, lo);
                *(uint2*)&sm[prow + fn * 16 + ((2 * tig + 1) & 3) * 4 + hoff] =
                    make_uint2(hi, lo);
            }
            psum += __shfl_xor_sync(0xffffffffu, psum, 1);
            psum += __shfl_xor_sync(0xffffffffu, psum, 2);
            float scale = __expf(mi[rh] - mnew);
            li[rh] = li[rh] * scale + psum;
            mi[rh] = mnew;
            #pragma unroll
            for (int nf = 0; nf < 8; nf++) {
                o[nf][2 * rh]     *= scale;
                o[nf][2 * rh + 1] *= scale;
            }
        }
        __syncwarp();

        // ---- O += P V, 3xTF32 ----
        #pragma unroll
        for (int ks = 0; ks < 4; ks++) {
            uint4 pr0 = *(uint4*)&sm[psw + g * PPITCH + ks * 16 + tig * 4];
            uint4 pr1 = *(uint4*)&sm[psw + (g + 8) * PPITCH + ks * 16 + tig * 4];
            unsigned pah[4] = {pr0.x, pr1.x, pr0.z, pr1.z};
            unsigned pal[4] = {pr0.y, pr1.y, pr0.w, pr1.w};
            #pragma unroll
            for (int nf = 0; nf < 8; nf++) {
                uint2 v0 = *(uint2*)&sm[VS_OFF + (ks * 8 + tig) * VPITCH +
                                        (nf * 8 + g) * 2];
                uint2 v1 = *(uint2*)&sm[VS_OFF + (ks * 8 + tig + 4) * VPITCH +
                                        (nf * 8 + g) * 2];
                mma8(o[nf], pah, v0.x, v1.x);
                mma8(o[nf], pal, v0.x, v1.x);
                mma8(o[nf], pah, v0.y, v1.y);
            }
        }
        __syncthreads();
    }

    // ---- normalize + store to [B,S,E] ----
    const float inv0 = 1.0f / li[0], inv1 = 1.0f / li[1];
    const int qg = q0 + w * 16 + g;
    #pragma unroll
    for (int nf = 0; nf < 8; nf++) {
        int d = nf * 8 + 2 * tig;
        *(float2*)&g_att[(size_t)(b * S + qg) * E + h * D + d] =
            make_float2(o[nf][0] * inv0, o[nf][1] * inv0);
        *(float2*)&g_att[(size_t)(b * S + qg + 8) * E + h * D + d] =
            make_float2(o[nf][2] * inv1, o[nf][3] * inv1);
    }
}

// ---------------------------------------------------------------------------
extern "C" void kernel_launch(void* const* d_in, const int* in_sizes, int n_in,
                              void* d_out, int out_size)
{
    const float* query = (const float*)d_in[0];
    const float* key   = (const float*)d_in[1];
    const float* value = (const float*)d_in[2];
    const float* pb    = (const float*)d_in[3];
    const unsigned char* mask = (const unsigned char*)d_in[4];
    const float* wq_w = (const float*)d_in[5];
    const float* wq_b = (const float*)d_in[6];
    const float* wk_w = (const float*)d_in[7];
    const float* wk_b = (const float*)d_in[8];
    const float* wv_w = (const float*)d_in[9];
    const float* wv_b = (const float*)d_in[10];
    const float* fc_w = (const float*)d_in[11];
    const float* fc_b = (const float*)d_in[12];
    const float* coeff = (const float*)d_in[13];
    float* out = (float*)d_out;

    const int attn_smem = ATT_SMEM_WORDS * (int)sizeof(unsigned);  // 76,800 B
    const int gemm_smem = GEMM_SMEM_WORDS * (int)sizeof(unsigned); // 49,152 B
    cudaFuncSetAttribute(attn_kernel,
                         cudaFuncAttributeMaxDynamicSharedMemorySize, attn_smem);
    cudaFuncSetAttribute(qkv_kernel,
                         cudaFuncAttributeMaxDynamicSharedMemorySize, gemm_smem);
    cudaFuncSetAttribute(oproj_kernel,
                         cudaFuncAttributeMaxDynamicSharedMemorySize, gemm_smem);

    mask_prep_kernel<<<1, 256>>>(mask);
    kbias_kernel<<<(B * H * S) / 256, 256>>>(pb, coeff);

    dim3 g1(E / 128, BSZ / 128, 3);   // (6, 32, 3)
    qkv_kernel<<<g1, 256, gemm_smem>>>(query, key, value, wq_w, wk_w, wv_w,
                                       wq_b, wk_b, wv_b);

    dim3 g2(S / 128, H, B);           // (16, 12, 2)
    attn_kernel<<<g2, 256, attn_smem>>>(pb, coeff);

    dim3 g3(E / 128, BSZ / 128);      // (6, 32)
    oproj_kernel<<<g3, 256, gemm_smem>>>(fc_w, fc_b, out);
}

// round 6
// speedup vs baseline: 1.2763x; 1.2763x over previous
#include <cuda_runtime.h>
#include <math.h>

#define B 2
#define S 2048
#define E 768
#define H 12
#define D 64
#define BSZ (B*S)
#define QKV_ELEMS (B*H*S*D)

// Scratch (allocation-free rule: device globals)
__device__ float g_Q[QKV_ELEMS];
__device__ float g_K[QKV_ELEMS];
__device__ float g_V[QKV_ELEMS];
__device__ float g_att[BSZ*E];
__device__ float g_maskadd[BSZ];
__device__ float g_kbias[B*H*S];

// ---------------------------------------------------------------------------
// helpers
// ---------------------------------------------------------------------------
__device__ __forceinline__ unsigned f2tf(float f) {
    unsigned u;
    asm("cvt.rna.tf32.f32 %0, %1;" : "=r"(u) : "f"(f));
    return u;
}
// 3xTF32 operand split: x ~= hi + lo, both tf32
__device__ __forceinline__ void splt(float f, unsigned& hi, unsigned& lo) {
    hi = f2tf(f);
    lo = f2tf(f - __uint_as_float(hi));
}

// D(16x8,f32) += A(16x8,tf32,row) * B(8x8,tf32,col)
__device__ __forceinline__ void mma8(float* c, const unsigned* a,
                                     unsigned b0, unsigned b1) {
    asm volatile(
        "mma.sync.aligned.m16n8k8.row.col.f32.tf32.tf32.f32 "
        "{%0,%1,%2,%3},{%4,%5,%6,%7},{%8,%9},{%0,%1,%2,%3};"
        : "+f"(c[0]), "+f"(c[1]), "+f"(c[2]), "+f"(c[3])
        : "r"(a[0]), "r"(a[1]), "r"(a[2]), "r"(a[3]), "r"(b0), "r"(b1));
}

// ---------------------------------------------------------------------------
// Mask normalization (dtype-agnostic) -> g_maskadd
// ---------------------------------------------------------------------------
__global__ void mask_prep_kernel(const unsigned char* __restrict__ m)
{
    __shared__ int cls[4];
    int tid = threadIdx.x;
    if (tid < 4) cls[tid] = 0;
    __syncthreads();
    for (int i = tid; i < BSZ; i += blockDim.x)
        if (m[i]) atomicAdd(&cls[i & 3], 1);
    __syncthreads();
    int mode = 0;                                              // u8
    if (cls[1] == 0 && cls[2] == 0 && cls[3] == 0) mode = 1;   // int32
    else if (cls[0] == 0 && cls[1] == 0)           mode = 2;   // float32
    for (int i = tid; i < BSZ; i += blockDim.x) {
        bool v;
        if (mode == 1)      v = ((const int*)m)[i] != 0;
        else if (mode == 2) v = ((const float*)m)[i] != 0.0f;
        else                v = m[i] != 0;
        g_maskadd[i] = v ? 0.0f : -1e30f;
    }
}

__global__ void kbias_kernel(const float* __restrict__ pb,
                             const float* __restrict__ coeff)
{
    int idx = blockIdx.x * 256 + threadIdx.x;
    int bh = idx / S, k = idx - bh * S;
    int b = bh / H, h = bh - b * H;
    g_kbias[idx] = -coeff[h] * pb[b * S + k] + g_maskadd[b * S + k];
}

// ---------------------------------------------------------------------------
// QKV projection, 3xTF32. CTA 128(m) x 64(n), 8 warps = 4x2, warp tile 32x32.
// acc 32 regs/thread -> 2 CTAs/SM. Fused bias + RoPE + transpose to [B,H,S,D].
// ---------------------------------------------------------------------------
__global__ __launch_bounds__(256, 2)
void qkv_kernel(const float* __restrict__ Xq, const float* __restrict__ Xk,
                const float* __restrict__ Xv,
                const float* __restrict__ Wq, const float* __restrict__ Wk,
                const float* __restrict__ Wv,
                const float* __restrict__ bq, const float* __restrict__ bk,
                const float* __restrict__ bv)
{
    const int z = blockIdx.z;
    const float* X    = (z == 0) ? Xq : (z == 1) ? Xk : Xv;
    const float* W    = (z == 0) ? Wq : (z == 1) ? Wk : Wv;
    const float* bias = (z == 0) ? bq : (z == 1) ? bk : bv;
    float* out        = (z == 0) ? g_Q : (z == 1) ? g_K : g_V;
    const bool rope = (z < 2);

    __shared__ unsigned As[2][128][20];   // [plane][row][k]
    __shared__ unsigned Bs[2][64][20];

    const int tid = threadIdx.x;
    const int w = tid >> 5, wm = w >> 1, wn = w & 1;
    const int lane = tid & 31, g = lane >> 2, tig = lane & 3;
    const int m0 = blockIdx.y * 128, n0 = blockIdx.x * 64;

    float acc[2][4][4];
    #pragma unroll
    for (int a = 0; a < 2; a++)
        #pragma unroll
        for (int b2 = 0; b2 < 4; b2++)
            #pragma unroll
            for (int c = 0; c < 4; c++) acc[a][b2][c] = 0.0f;

    // staging: A two float4/thread (128x16), B one float4/thread (64x16)
    const int ar0 = tid >> 2, ac = (tid & 3) << 2;   // ar0: 0..63 (+64 second)
    const int br  = tid >> 2;                         // 0..63

    for (int k0 = 0; k0 < E; k0 += 16) {
        #pragma unroll
        for (int t = 0; t < 2; t++) {
            int r = ar0 + t * 64;
            float4 av = *(const float4*)(X + (size_t)(m0 + r) * E + k0 + ac);
            splt(av.x, As[0][r][ac + 0], As[1][r][ac + 0]);
            splt(av.y, As[0][r][ac + 1], As[1][r][ac + 1]);
            splt(av.z, As[0][r][ac + 2], As[1][r][ac + 2]);
            splt(av.w, As[0][r][ac + 3], As[1][r][ac + 3]);
        }
        {
            float4 bv4 = *(const float4*)(W + (size_t)(n0 + br) * E + k0 + ac);
            splt(bv4.x, Bs[0][br][ac + 0], Bs[1][br][ac + 0]);
            splt(bv4.y, Bs[0][br][ac + 1], Bs[1][br][ac + 1]);
            splt(bv4.z, Bs[0][br][ac + 2], Bs[1][br][ac + 2]);
            splt(bv4.w, Bs[0][br][ac + 3], Bs[1][br][ac + 3]);
        }
        __syncthreads();
        #pragma unroll
        for (int kk = 0; kk < 16; kk += 8) {
            unsigned afh[2][4], afl[2][4], bh0[4], bl0[4], bh1[4], bl1[4];
            #pragma unroll
            for (int fm = 0; fm < 2; fm++) {
                int rb = wm * 32 + fm * 16 + g;
                afh[fm][0] = As[0][rb][kk + tig];
                afh[fm][1] = As[0][rb + 8][kk + tig];
                afh[fm][2] = As[0][rb][kk + tig + 4];
                afh[fm][3] = As[0][rb + 8][kk + tig + 4];
                afl[fm][0] = As[1][rb][kk + tig];
                afl[fm][1] = As[1][rb + 8][kk + tig];
                afl[fm][2] = As[1][rb][kk + tig + 4];
                afl[fm][3] = As[1][rb + 8][kk + tig + 4];
            }
            #pragma unroll
            for (int fn = 0; fn < 4; fn++) {
                int cb = wn * 32 + fn * 8 + g;
                bh0[fn] = Bs[0][cb][kk + tig];
                bh1[fn] = Bs[0][cb][kk + tig + 4];
                bl0[fn] = Bs[1][cb][kk + tig];
                bl1[fn] = Bs[1][cb][kk + tig + 4];
            }
            #pragma unroll
            for (int fm = 0; fm < 2; fm++)
                #pragma unroll
                for (int fn = 0; fn < 4; fn++) {
                    mma8(acc[fm][fn], afh[fm], bh0[fn], bh1[fn]);
                    mma8(acc[fm][fn], afl[fm], bh0[fn], bh1[fn]);
                    mma8(acc[fm][fn], afh[fm], bl0[fn], bl1[fn]);
                }
        }
        __syncthreads();
    }

    // epilogue: bias + RoPE + transpose to [B,H,S,D]
    #pragma unroll
    for (int fn = 0; fn < 4; fn++) {
        const int col = n0 + wn * 32 + fn * 8 + 2 * tig;   // even
        const int h = col / D, d = col % D;
        const float b0v = bias[col], b1v = bias[col + 1];
        const float invf = rope
            ? exp2f(-(float)d * (13.287712379549449f / 64.0f)) : 0.0f;
        #pragma unroll
        for (int fm = 0; fm < 2; fm++) {
            const int row = m0 + wm * 32 + fm * 16 + g;
            #pragma unroll
            for (int half = 0; half < 2; half++) {
                const int r = row + half * 8;
                const int bb = r >> 11, s = r & 2047;
                float v0 = acc[fm][fn][half * 2 + 0] + b0v;
                float v1 = acc[fm][fn][half * 2 + 1] + b1v;
                if (rope) {
                    float sn, cs;
                    sincosf((float)s * invf, &sn, &cs);
                    float t0 = v0 * cs - v1 * sn;
                    v1 = v1 * cs + v0 * sn;
                    v0 = t0;
                }
                *(float2*)&out[(((size_t)bb * H + h) * S + s) * D + d] =
                    make_float2(v0, v1);
            }
        }
    }
}

// ---------------------------------------------------------------------------
// Output projection (same scheme, no rope)
// ---------------------------------------------------------------------------
__global__ __launch_bounds__(256, 2)
void oproj_kernel(const float* __restrict__ Wf, const float* __restrict__ bias,
                  float* __restrict__ out)
{
    __shared__ unsigned As[2][128][20];
    __shared__ unsigned Bs[2][64][20];

    const int tid = threadIdx.x;
    const int w = tid >> 5, wm = w >> 1, wn = w & 1;
    const int lane = tid & 31, g = lane >> 2, tig = lane & 3;
    const int m0 = blockIdx.y * 128, n0 = blockIdx.x * 64;

    float acc[2][4][4];
    #pragma unroll
    for (int a = 0; a < 2; a++)
        #pragma unroll
        for (int b2 = 0; b2 < 4; b2++)
            #pragma unroll
            for (int c = 0; c < 4; c++) acc[a][b2][c] = 0.0f;

    const int ar0 = tid >> 2, ac = (tid & 3) << 2;
    const int br  = tid >> 2;

    for (int k0 = 0; k0 < E; k0 += 16) {
        #pragma unroll
        for (int t = 0; t < 2; t++) {
            int r = ar0 + t * 64;
            float4 av = *(const float4*)(g_att + (size_t)(m0 + r) * E + k0 + ac);
            splt(av.x, As[0][r][ac + 0], As[1][r][ac + 0]);
            splt(av.y, As[0][r][ac + 1], As[1][r][ac + 1]);
            splt(av.z, As[0][r][ac + 2], As[1][r][ac + 2]);
            splt(av.w, As[0][r][ac + 3], As[1][r][ac + 3]);
        }
        {
            float4 bv4 = *(const float4*)(Wf + (size_t)(n0 + br) * E + k0 + ac);
            splt(bv4.x, Bs[0][br][ac + 0], Bs[1][br][ac + 0]);
            splt(bv4.y, Bs[0][br][ac + 1], Bs[1][br][ac + 1]);
            splt(bv4.z, Bs[0][br][ac + 2], Bs[1][br][ac + 2]);
            splt(bv4.w, Bs[0][br][ac + 3], Bs[1][br][ac + 3]);
        }
        __syncthreads();
        #pragma unroll
        for (int kk = 0; kk < 16; kk += 8) {
            unsigned afh[2][4], afl[2][4], bh0[4], bl0[4], bh1[4], bl1[4];
            #pragma unroll
            for (int fm = 0; fm < 2; fm++) {
                int rb = wm * 32 + fm * 16 + g;
                afh[fm][0] = As[0][rb][kk + tig];
                afh[fm][1] = As[0][rb + 8][kk + tig];
                afh[fm][2] = As[0][rb][kk + tig + 4];
                afh[fm][3] = As[0][rb + 8][kk + tig + 4];
                afl[fm][0] = As[1][rb][kk + tig];
                afl[fm][1] = As[1][rb + 8][kk + tig];
                afl[fm][2] = As[1][rb][kk + tig + 4];
                afl[fm][3] = As[1][rb + 8][kk + tig + 4];
            }
            #pragma unroll
            for (int fn = 0; fn < 4; fn++) {
                int cb = wn * 32 + fn * 8 + g;
                bh0[fn] = Bs[0][cb][kk + tig];
                bh1[fn] = Bs[0][cb][kk + tig + 4];
                bl0[fn] = Bs[1][cb][kk + tig];
                bl1[fn] = Bs[1][cb][kk + tig + 4];
            }
            #pragma unroll
            for (int fm = 0; fm < 2; fm++)
                #pragma unroll
                for (int fn = 0; fn < 4; fn++) {
                    mma8(acc[fm][fn], afh[fm], bh0[fn], bh1[fn]);
                    mma8(acc[fm][fn], afl[fm], bh0[fn], bh1[fn]);
                    mma8(acc[fm][fn], afh[fm], bl0[fn], bl1[fn]);
                }
        }
        __syncthreads();
    }

    #pragma unroll
    for (int fn = 0; fn < 4; fn++) {
        const int col = n0 + wn * 32 + fn * 8 + 2 * tig;
        const float b0v = bias[col], b1v = bias[col + 1];
        #pragma unroll
        for (int fm = 0; fm < 2; fm++) {
            const int row = m0 + wm * 32 + fm * 16 + g;
            #pragma unroll
            for (int half = 0; half < 2; half++) {
                const int r = row + half * 8;
                *(float2*)&out[(size_t)r * E + col] =
                    make_float2(acc[fm][fn][half * 2 + 0] + b0v,
                                acc[fm][fn][half * 2 + 1] + b1v);
            }
        }
    }
}

// ---------------------------------------------------------------------------
// Flash attention, 3xTF32 (Round-3 structure).  Q-lo plane lives in smem
// (loaded per k-tile) instead of registers -> ~120 regs -> 2 CTAs/SM.
//  KH [32][76] @0, KL @2432, VH [32][72] @4864, VL @7168,
//  QP @9472 (128x76: Q-hi staging, then per-warp P hi/lo 16x36 x2),
//  QLO @19200 (128x68, persistent Q-lo plane).
// ---------------------------------------------------------------------------
#define KH_OFF 0
#define KL_OFF 2432
#define VH_OFF 4864
#define VL_OFF 7168
#define QP_OFF 9472
#define QLO_OFF 19200
#define QLP 68
#define ATT_SMEM_WORDS 27904   // 111,616 B

__global__ __launch_bounds__(256, 2)
void attn_kernel(const float* __restrict__ pb, const float* __restrict__ coeff)
{
    extern __shared__ unsigned sm[];

    const int tid = threadIdx.x;
    const int w = tid >> 5, lane = tid & 31, g = lane >> 2, tig = lane & 3;
    const int b = blockIdx.z, h = blockIdx.y, q0 = blockIdx.x * 128;

    const float* Qg = g_Q + (size_t)(b * H + h) * S * D;
    const float* Kg = g_K + (size_t)(b * H + h) * S * D;
    const float* Vg = g_V + (size_t)(b * H + h) * S * D;
    const float* kbp = g_kbias + (size_t)(b * H + h) * S;

    // ---- stage Q: hi -> QP (pitch 76), lo -> QLO (pitch 68, persistent) ----
    #pragma unroll
    for (int t = 0; t < 8; t++) {
        int i = tid + t * 256;
        int r = i >> 4, c4 = (i & 15) << 2;
        float4 v = *(const float4*)(Qg + (size_t)(q0 + r) * D + c4);
        unsigned* ph = &sm[QP_OFF + r * 76 + c4];
        unsigned* pl = &sm[QLO_OFF + r * QLP + c4];
        unsigned hi, lo;
        splt(v.x, hi, lo); ph[0] = hi; pl[0] = lo;
        splt(v.y, hi, lo); ph[1] = hi; pl[1] = lo;
        splt(v.z, hi, lo); ph[2] = hi; pl[2] = lo;
        splt(v.w, hi, lo); ph[3] = hi; pl[3] = lo;
    }
    __syncthreads();

    // Q-hi fragments -> registers (32 regs)
    unsigned qa[8][4];
    {
        const int qb = QP_OFF + (w * 16 + g) * 76;
        #pragma unroll
        for (int kk = 0; kk < 8; kk++) {
            qa[kk][0] = sm[qb + kk * 8 + tig];
            qa[kk][1] = sm[qb + 8 * 76 + kk * 8 + tig];
            qa[kk][2] = sm[qb + kk * 8 + tig + 4];
            qa[kk][3] = sm[qb + 8 * 76 + kk * 8 + tig + 4];
        }
    }
    __syncthreads();

    const float coeff_h = coeff[h];
    float rowb[2];
    rowb[0] = coeff_h * pb[b * S + q0 + w * 16 + g];
    rowb[1] = coeff_h * pb[b * S + q0 + w * 16 + g + 8];

    float mi[2] = {-1e30f, -1e30f}, li[2] = {0.0f, 0.0f};
    float o[8][4];
    #pragma unroll
    for (int nf = 0; nf < 8; nf++)
        #pragma unroll
        for (int c = 0; c < 4; c++) o[nf][c] = 0.0f;

    const int psH = QP_OFF + w * 1152;        // P hi: 16 x 36
    const int psL = psH + 576;                // P lo: 16 x 36
    const int qlb = QLO_OFF + (w * 16 + g) * QLP;

    for (int k0 = 0; k0 < S; k0 += 32) {
        // ---- load K,V tiles, split hi/lo ----
        #pragma unroll
        for (int t = 0; t < 2; t++) {
            int i = tid + t * 256;
            int r = i >> 4, c4 = (i & 15) << 2;
            float4 kv = *(const float4*)(Kg + (size_t)(k0 + r) * D + c4);
            unsigned* kh = &sm[KH_OFF + r * 76 + c4];
            unsigned* kl = &sm[KL_OFF + r * 76 + c4];
            splt(kv.x, kh[0], kl[0]); splt(kv.y, kh[1], kl[1]);
            splt(kv.z, kh[2], kl[2]); splt(kv.w, kh[3], kl[3]);
            float4 vv = *(const float4*)(Vg + (size_t)(k0 + r) * D + c4);
            unsigned* vh = &sm[VH_OFF + r * 72 + c4];
            unsigned* vl = &sm[VL_OFF + r * 72 + c4];
            splt(vv.x, vh[0], vl[0]); splt(vv.y, vh[1], vl[1]);
            splt(vv.z, vh[2], vl[2]); splt(vv.w, vh[3], vl[3]);
        }
        __syncthreads();

        // ---- S = Q K^T, 3xTF32 (Q-lo fragment from smem per kk) ----
        float sc[4][4];
        #pragma unroll
        for (int fn = 0; fn < 4; fn++)
            #pragma unroll
            for (int c = 0; c < 4; c++) sc[fn][c] = 0.0f;

        #pragma unroll
        for (int kk = 0; kk < 8; kk++) {
            unsigned ql[4];
            ql[0] = sm[qlb + kk * 8 + tig];
            ql[1] = sm[qlb + 8 * QLP + kk * 8 + tig];
            ql[2] = sm[qlb + kk * 8 + tig + 4];
            ql[3] = sm[qlb + 8 * QLP + kk * 8 + tig + 4];
            #pragma unroll
            for (int fn = 0; fn < 4; fn++) {
                int kb = (fn * 8 + g) * 76 + kk * 8 + tig;
                unsigned kh0 = sm[KH_OFF + kb], kh1 = sm[KH_OFF + kb + 4];
                unsigned kl0 = sm[KL_OFF + kb], kl1 = sm[KL_OFF + kb + 4];
                mma8(sc[fn], qa[kk], kh0, kh1);
                mma8(sc[fn], ql,     kh0, kh1);
                mma8(sc[fn], qa[kk], kl0, kl1);
            }
        }

        // ---- scale + rel-pos bias + mask ----
        #pragma unroll
        for (int fn = 0; fn < 4; fn++) {
            int c = k0 + fn * 8 + 2 * tig;
            float cb0 = kbp[c], cb1 = kbp[c + 1];
            sc[fn][0] = sc[fn][0] * 0.125f + rowb[0] + cb0;
            sc[fn][1] = sc[fn][1] * 0.125f + rowb[0] + cb1;
            sc[fn][2] = sc[fn][2] * 0.125f + rowb[1] + cb0;
            sc[fn][3] = sc[fn][3] * 0.125f + rowb[1] + cb1;
        }

        // ---- online softmax; P stored split hi/lo ----
        #pragma unroll
        for (int rh = 0; rh < 2; rh++) {
            float tm = -1e30f;
            #pragma unroll
            for (int fn = 0; fn < 4; fn++)
                tm = fmaxf(tm, fmaxf(sc[fn][2 * rh], sc[fn][2 * rh + 1]));
            tm = fmaxf(tm, __shfl_xor_sync(0xffffffffu, tm, 1));
            tm = fmaxf(tm, __shfl_xor_sync(0xffffffffu, tm, 2));
            float mnew = fmaxf(fmaxf(mi[rh], tm), -1e20f);
            float psum = 0.0f;
            const int pro = (g + rh * 8) * 36;
            #pragma unroll
            for (int fn = 0; fn < 4; fn++) {
                float p0 = __expf(sc[fn][2 * rh] - mnew);
                float p1 = __expf(sc[fn][2 * rh + 1] - mnew);
                psum += p0 + p1;
                unsigned hi, lo;
                splt(p0, hi, lo);
                sm[psH + pro + fn * 8 + 2 * tig] = hi;
                sm[psL + pro + fn * 8 + 2 * tig] = lo;
                splt(p1, hi, lo);
                sm[psH + pro + fn * 8 + 2 * tig + 1] = hi;
                sm[psL + pro + fn * 8 + 2 * tig + 1] = lo;
            }
            psum += __shfl_xor_sync(0xffffffffu, psum, 1);
            psum += __shfl_xor_sync(0xffffffffu, psum, 2);
            float scale = __expf(mi[rh] - mnew);
            li[rh] = li[rh] * scale + psum;
            mi[rh] = mnew;
            #pragma unroll
            for (int nf = 0; nf < 8; nf++) {
                o[nf][2 * rh]     *= scale;
                o[nf][2 * rh + 1] *= scale;
            }
        }
        __syncwarp();

        // ---- O += P V, 3xTF32 ----
        #pragma unroll
        for (int ks = 0; ks < 4; ks++) {
            unsigned pah[4], pal[4];
            pah[0] = sm[psH + g * 36 + ks * 8 + tig];
            pah[1] = sm[psH + (g + 8) * 36 + ks * 8 + tig];
            pah[2] = sm[psH + g * 36 + ks * 8 + tig + 4];
            pah[3] = sm[psH + (g + 8) * 36 + ks * 8 + tig + 4];
            pal[0] = sm[psL + g * 36 + ks * 8 + tig];
            pal[1] = sm[psL + (g + 8) * 36 + ks * 8 + tig];
            pal[2] = sm[psL + g * 36 + ks * 8 + tig + 4];
            pal[3] = sm[psL + (g + 8) * 36 + ks * 8 + tig + 4];
            #pragma unroll
            for (int nf = 0; nf < 8; nf++) {
                int vb0i = (ks * 8 + tig) * 72 + nf * 8 + g;
                int vb1i = (ks * 8 + tig + 4) * 72 + nf * 8 + g;
                unsigned vh0 = sm[VH_OFF + vb0i], vh1 = sm[VH_OFF + vb1i];
                unsigned vl0 = sm[VL_OFF + vb0i], vl1 = sm[VL_OFF + vb1i];
                mma8(o[nf], pah, vh0, vh1);
                mma8(o[nf], pal, vh0, vh1);
                mma8(o[nf], pah, vl0, vl1);
            }
        }
        __syncthreads();
    }

    // ---- normalize + store to [B,S,E] ----
    const float inv0 = 1.0f / li[0], inv1 = 1.0f / li[1];
    const int qg = q0 + w * 16 + g;
    #pragma unroll
    for (int nf = 0; nf < 8; nf++) {
        int d = nf * 8 + 2 * tig;
        *(float2*)&g_att[(size_t)(b * S + qg) * E + h * D + d] =
            make_float2(o[nf][0] * inv0, o[nf][1] * inv0);
        *(float2*)&g_att[(size_t)(b * S + qg + 8) * E + h * D + d] =
            make_float2(o[nf][2] * inv1, o[nf][3] * inv1);
    }
}

// ---------------------------------------------------------------------------
extern "C" void kernel_launch(void* const* d_in, const int* in_sizes, int n_in,
                              void* d_out, int out_size)
{
    const float* query = (const float*)d_in[0];
    const float* key   = (const float*)d_in[1];
    const float* value = (const float*)d_in[2];
    const float* pb    = (const float*)d_in[3];
    const unsigned char* mask = (const unsigned char*)d_in[4];
    const float* wq_w = (const float*)d_in[5];
    const float* wq_b = (const float*)d_in[6];
    const float* wk_w = (const float*)d_in[7];
    const float* wk_b = (const float*)d_in[8];
    const float* wv_w = (const float*)d_in[9];
    const float* wv_b = (const float*)d_in[10];
    const float* fc_w = (const float*)d_in[11];
    const float* fc_b = (const float*)d_in[12];
    const float* coeff = (const float*)d_in[13];
    float* out = (float*)d_out;

    const int attn_smem = ATT_SMEM_WORDS * (int)sizeof(unsigned);  // 111,616 B
    cudaFuncSetAttribute(attn_kernel,
                         cudaFuncAttributeMaxDynamicSharedMemorySize, attn_smem);

    mask_prep_kernel<<<1, 256>>>(mask);
    kbias_kernel<<<(B * H * S) / 256, 256>>>(pb, coeff);

    dim3 g1(E / 64, BSZ / 128, 3);    // (12, 32, 3)
    qkv_kernel<<<g1, 256>>>(query, key, value, wq_w, wk_w, wv_w,
                            wq_b, wk_b, wv_b);

    dim3 g2(S / 128, H, B);           // (16, 12, 2)
    attn_kernel<<<g2, 256, attn_smem>>>(pb, coeff);

    dim3 g3(E / 64, BSZ / 128);       // (12, 32)
    oproj_kernel<<<g3, 256>>>(fc_w, fc_b, out);
}

// round 7
// speedup vs baseline: 1.3207x; 1.0348x over previous
#include <cuda_runtime.h>
#include <math.h>

#define B 2
#define S 2048
#define E 768
#define H 12
#define D 64
#define BSZ (B*S)
#define QKV_ELEMS (B*H*S*D)
#define XN (BSZ*E)        // 3,145,728
#define WN (E*E)          // 589,824

// Scratch (allocation-free rule: device globals) — all split hi/lo tf32 planes
__device__ unsigned g_Xhi[3*XN], g_Xlo[3*XN];     // query,key,value
__device__ unsigned g_Whi[4*WN], g_Wlo[4*WN];     // wq,wk,wv,fc
__device__ unsigned g_Qhi[QKV_ELEMS], g_Qlo[QKV_ELEMS];
__device__ unsigned g_Khi[QKV_ELEMS], g_Klo[QKV_ELEMS];
__device__ unsigned g_Vhi[QKV_ELEMS], g_Vlo[QKV_ELEMS];
__device__ unsigned g_atthi[XN], g_attlo[XN];
__device__ float g_maskadd[BSZ];
__device__ float g_kbias[B*H*S];

// ---------------------------------------------------------------------------
// helpers
// ---------------------------------------------------------------------------
__device__ __forceinline__ unsigned f2tf(float f) {
    unsigned u;
    asm("cvt.rna.tf32.f32 %0, %1;" : "=r"(u) : "f"(f));
    return u;
}
__device__ __forceinline__ void splt(float f, unsigned& hi, unsigned& lo) {
    hi = f2tf(f);
    lo = f2tf(f - __uint_as_float(hi));
}
__device__ __forceinline__ void mma8(float* c, const unsigned* a,
                                     unsigned b0, unsigned b1) {
    asm volatile(
        "mma.sync.aligned.m16n8k8.row.col.f32.tf32.tf32.f32 "
        "{%0,%1,%2,%3},{%4,%5,%6,%7},{%8,%9},{%0,%1,%2,%3};"
        : "+f"(c[0]), "+f"(c[1]), "+f"(c[2]), "+f"(c[3])
        : "r"(a[0]), "r"(a[1]), "r"(a[2]), "r"(a[3]), "r"(b0), "r"(b1));
}
__device__ __forceinline__ void cpa16(void* s, const void* g) {
    unsigned sa = (unsigned)__cvta_generic_to_shared(s);
    asm volatile("cp.async.cg.shared.global [%0], [%1], 16;"
                 :: "r"(sa), "l"(g));
}
#define CP_COMMIT_WAIT() do { \
    asm volatile("cp.async.commit_group;"); \
    asm volatile("cp.async.wait_group 0;" ::: "memory"); } while (0)

// ---------------------------------------------------------------------------
// One-time hi/lo split of a float array (n4 = n/4 float4 chunks)
// ---------------------------------------------------------------------------
__global__ void split_kernel(const float* __restrict__ src,
                             unsigned* __restrict__ hi_,
                             unsigned* __restrict__ lo_, int n4)
{
    int i = blockIdx.x * 256 + threadIdx.x;
    if (i < n4) {
        float4 v = ((const float4*)src)[i];
        uint4 hh, ll;
        splt(v.x, hh.x, ll.x); splt(v.y, hh.y, ll.y);
        splt(v.z, hh.z, ll.z); splt(v.w, hh.w, ll.w);
        ((uint4*)hi_)[i] = hh;
        ((uint4*)lo_)[i] = ll;
    }
}

// ---------------------------------------------------------------------------
// Mask normalization (dtype-agnostic) + per-(b,h,k) column bias
// ---------------------------------------------------------------------------
__global__ void mask_prep_kernel(const unsigned char* __restrict__ m)
{
    __shared__ int cls[4];
    int tid = threadIdx.x;
    if (tid < 4) cls[tid] = 0;
    __syncthreads();
    for (int i = tid; i < BSZ; i += blockDim.x)
        if (m[i]) atomicAdd(&cls[i & 3], 1);
    __syncthreads();
    int mode = 0;
    if (cls[1] == 0 && cls[2] == 0 && cls[3] == 0) mode = 1;   // int32
    else if (cls[0] == 0 && cls[1] == 0)           mode = 2;   // float32
    for (int i = tid; i < BSZ; i += blockDim.x) {
        bool v;
        if (mode == 1)      v = ((const int*)m)[i] != 0;
        else if (mode == 2) v = ((const float*)m)[i] != 0.0f;
        else                v = m[i] != 0;
        g_maskadd[i] = v ? 0.0f : -1e30f;
    }
}

__global__ void kbias_kernel(const float* __restrict__ pb,
                             const float* __restrict__ coeff)
{
    int idx = blockIdx.x * 256 + threadIdx.x;
    int bh = idx / S, k = idx - bh * S;
    int b = bh / H, h = bh - b * H;
    g_kbias[idx] = -coeff[h] * pb[b * S + k] + g_maskadd[b * S + k];
}

// ---------------------------------------------------------------------------
// QKV projection, 3xTF32, pre-split operands, cp.async staging.
// CTA 128(m) x 64(n), 8 warps = 4x2, warp tile 32x32. Fused bias+RoPE.
// Outputs g_{Q,K,V}hi/lo in [B,H,S,D].
// ---------------------------------------------------------------------------
__global__ __launch_bounds__(256, 2)
void qkv_kernel(const float* __restrict__ bq, const float* __restrict__ bk,
                const float* __restrict__ bv)
{
    const int z = blockIdx.z;
    const unsigned* Xhi = g_Xhi + (size_t)z * XN;
    const unsigned* Xlo = g_Xlo + (size_t)z * XN;
    const unsigned* Whi = g_Whi + (size_t)z * WN;
    const unsigned* Wlo = g_Wlo + (size_t)z * WN;
    const float* bias = (z == 0) ? bq : (z == 1) ? bk : bv;
    unsigned* ohi = (z == 0) ? g_Qhi : (z == 1) ? g_Khi : g_Vhi;
    unsigned* olo = (z == 0) ? g_Qlo : (z == 1) ? g_Klo : g_Vlo;
    const bool rope = (z < 2);

    __shared__ unsigned As[2][128][20];
    __shared__ unsigned Bs[2][64][20];

    const int tid = threadIdx.x;
    const int w = tid >> 5, wm = w >> 1, wn = w & 1;
    const int lane = tid & 31, g = lane >> 2, tig = lane & 3;
    const int m0 = blockIdx.y * 128, n0 = blockIdx.x * 64;
    const int ar0 = tid >> 2, ac = (tid & 3) << 2;   // ar0 0..63, ac 0/4/8/12

    float acc[2][4][4];
    #pragma unroll
    for (int a = 0; a < 2; a++)
        #pragma unroll
        for (int b2 = 0; b2 < 4; b2++)
            #pragma unroll
            for (int c = 0; c < 4; c++) acc[a][b2][c] = 0.0f;

    for (int k0 = 0; k0 < E; k0 += 16) {
        #pragma unroll
        for (int t = 0; t < 2; t++) {
            int r = ar0 + t * 64;
            size_t gi = (size_t)(m0 + r) * E + k0 + ac;
            cpa16(&As[0][r][ac], Xhi + gi);
            cpa16(&As[1][r][ac], Xlo + gi);
        }
        {
            size_t gi = (size_t)(n0 + ar0) * E + k0 + ac;
            cpa16(&Bs[0][ar0][ac], Whi + gi);
            cpa16(&Bs[1][ar0][ac], Wlo + gi);
        }
        CP_COMMIT_WAIT();
        __syncthreads();
        #pragma unroll
        for (int kk = 0; kk < 16; kk += 8) {
            unsigned afh[2][4], afl[2][4], bh0[4], bl0[4], bh1[4], bl1[4];
            #pragma unroll
            for (int fm = 0; fm < 2; fm++) {
                int rb = wm * 32 + fm * 16 + g;
                afh[fm][0] = As[0][rb][kk + tig];
                afh[fm][1] = As[0][rb + 8][kk + tig];
                afh[fm][2] = As[0][rb][kk + tig + 4];
                afh[fm][3] = As[0][rb + 8][kk + tig + 4];
                afl[fm][0] = As[1][rb][kk + tig];
                afl[fm][1] = As[1][rb + 8][kk + tig];
                afl[fm][2] = As[1][rb][kk + tig + 4];
                afl[fm][3] = As[1][rb + 8][kk + tig + 4];
            }
            #pragma unroll
            for (int fn = 0; fn < 4; fn++) {
                int cb = wn * 32 + fn * 8 + g;
                bh0[fn] = Bs[0][cb][kk + tig];
                bh1[fn] = Bs[0][cb][kk + tig + 4];
                bl0[fn] = Bs[1][cb][kk + tig];
                bl1[fn] = Bs[1][cb][kk + tig + 4];
            }
            #pragma unroll
            for (int fm = 0; fm < 2; fm++)
                #pragma unroll
                for (int fn = 0; fn < 4; fn++) {
                    mma8(acc[fm][fn], afh[fm], bh0[fn], bh1[fn]);
                    mma8(acc[fm][fn], afl[fm], bh0[fn], bh1[fn]);
                    mma8(acc[fm][fn], afh[fm], bl0[fn], bl1[fn]);
                }
        }
        __syncthreads();
    }

    // epilogue: bias + RoPE (fp32) -> split -> hi/lo planes in [B,H,S,D]
    #pragma unroll
    for (int fn = 0; fn < 4; fn++) {
        const int col = n0 + wn * 32 + fn * 8 + 2 * tig;   // even
        const int h = col / D, d = col % D;
        const float b0v = bias[col], b1v = bias[col + 1];
        const float invf = rope
            ? exp2f(-(float)d * (13.287712379549449f / 64.0f)) : 0.0f;
        #pragma unroll
        for (int fm = 0; fm < 2; fm++) {
            const int row = m0 + wm * 32 + fm * 16 + g;
            #pragma unroll
            for (int half = 0; half < 2; half++) {
                const int r = row + half * 8;
                const int bb = r >> 11, s = r & 2047;
                float v0 = acc[fm][fn][half * 2 + 0] + b0v;
                float v1 = acc[fm][fn][half * 2 + 1] + b1v;
                if (rope) {
                    float sn, cs;
                    sincosf((float)s * invf, &sn, &cs);
                    float t0 = v0 * cs - v1 * sn;
                    v1 = v1 * cs + v0 * sn;
                    v0 = t0;
                }
                const size_t idx = (((size_t)bb * H + h) * S + s) * D + d;
                unsigned h0, l0, h1, l1;
                splt(v0, h0, l0); splt(v1, h1, l1);
                *(uint2*)&ohi[idx] = make_uint2(h0, h1);
                *(uint2*)&olo[idx] = make_uint2(l0, l1);
            }
        }
    }
}

// ---------------------------------------------------------------------------
// Output projection: d_out = att @ fc_w^T + fc_b (pre-split operands)
// ---------------------------------------------------------------------------
__global__ __launch_bounds__(256, 2)
void oproj_kernel(const float* __restrict__ bias, float* __restrict__ out)
{
    const unsigned* Ahi = g_atthi;
    const unsigned* Alo = g_attlo;
    const unsigned* Whi = g_Whi + (size_t)3 * WN;
    const unsigned* Wlo = g_Wlo + (size_t)3 * WN;

    __shared__ unsigned As[2][128][20];
    __shared__ unsigned Bs[2][64][20];

    const int tid = threadIdx.x;
    const int w = tid >> 5, wm = w >> 1, wn = w & 1;
    const int lane = tid & 31, g = lane >> 2, tig = lane & 3;
    const int m0 = blockIdx.y * 128, n0 = blockIdx.x * 64;
    const int ar0 = tid >> 2, ac = (tid & 3) << 2;

    float acc[2][4][4];
    #pragma unroll
    for (int a = 0; a < 2; a++)
        #pragma unroll
        for (int b2 = 0; b2 < 4; b2++)
            #pragma unroll
            for (int c = 0; c < 4; c++) acc[a][b2][c] = 0.0f;

    for (int k0 = 0; k0 < E; k0 += 16) {
        #pragma unroll
        for (int t = 0; t < 2; t++) {
            int r = ar0 + t * 64;
            size_t gi = (size_t)(m0 + r) * E + k0 + ac;
            cpa16(&As[0][r][ac], Ahi + gi);
            cpa16(&As[1][r][ac], Alo + gi);
        }
        {
            size_t gi = (size_t)(n0 + ar0) * E + k0 + ac;
            cpa16(&Bs[0][ar0][ac], Whi + gi);
            cpa16(&Bs[1][ar0][ac], Wlo + gi);
        }
        CP_COMMIT_WAIT();
        __syncthreads();
        #pragma unroll
        for (int kk = 0; kk < 16; kk += 8) {
            unsigned afh[2][4], afl[2][4], bh0[4], bl0[4], bh1[4], bl1[4];
            #pragma unroll
            for (int fm = 0; fm < 2; fm++) {
                int rb = wm * 32 + fm * 16 + g;
                afh[fm][0] = As[0][rb][kk + tig];
                afh[fm][1] = As[0][rb + 8][kk + tig];
                afh[fm][2] = As[0][rb][kk + tig + 4];
                afh[fm][3] = As[0][rb + 8][kk + tig + 4];
                afl[fm][0] = As[1][rb][kk + tig];
                afl[fm][1] = As[1][rb + 8][kk + tig];
                afl[fm][2] = As[1][rb][kk + tig + 4];
                afl[fm][3] = As[1][rb + 8][kk + tig + 4];
            }
            #pragma unroll
            for (int fn = 0; fn < 4; fn++) {
                int cb = wn * 32 + fn * 8 + g;
                bh0[fn] = Bs[0][cb][kk + tig];
                bh1[fn] = Bs[0][cb][kk + tig + 4];
                bl0[fn] = Bs[1][cb][kk + tig];
                bl1[fn] = Bs[1][cb][kk + tig + 4];
            }
            #pragma unroll
            for (int fm = 0; fm < 2; fm++)
                #pragma unroll
                for (int fn = 0; fn < 4; fn++) {
                    mma8(acc[fm][fn], afh[fm], bh0[fn], bh1[fn]);
                    mma8(acc[fm][fn], afl[fm], bh0[fn], bh1[fn]);
                    mma8(acc[fm][fn], afh[fm], bl0[fn], bl1[fn]);
                }
        }
        __syncthreads();
    }

    #pragma unroll
    for (int fn = 0; fn < 4; fn++) {
        const int col = n0 + wn * 32 + fn * 8 + 2 * tig;
        const float b0v = bias[col], b1v = bias[col + 1];
        #pragma unroll
        for (int fm = 0; fm < 2; fm++) {
            const int row = m0 + wm * 32 + fm * 16 + g;
            #pragma unroll
            for (int half = 0; half < 2; half++) {
                const int r = row + half * 8;
                *(float2*)&out[(size_t)r * E + col] =
                    make_float2(acc[fm][fn][half * 2 + 0] + b0v,
                                acc[fm][fn][half * 2 + 1] + b1v);
            }
        }
    }
}

// ---------------------------------------------------------------------------
// Flash attention, 3xTF32 scores, 2xTF32 PV (P-hi only).
// Pre-split Q/K/V planes, cp.async staging.
//  KH [32][76] @0, KL @2432, VH [32][72] @4864, VL @7168,
//  QP @9472 (Q-hi staging 128x76, then per-warp P-hi 16x36),
//  QLO @19200 (128x68, persistent Q-lo).
// ---------------------------------------------------------------------------
#define KH_OFF 0
#define KL_OFF 2432
#define VH_OFF 4864
#define VL_OFF 7168
#define QP_OFF 9472
#define QLO_OFF 19200
#define QLP 68
#define ATT_SMEM_WORDS 27904   // 111,616 B

__global__ __launch_bounds__(256, 2)
void attn_kernel(const float* __restrict__ pb, const float* __restrict__ coeff)
{
    extern __shared__ unsigned sm[];

    const int tid = threadIdx.x;
    const int w = tid >> 5, lane = tid & 31, g = lane >> 2, tig = lane & 3;
    const int b = blockIdx.z, h = blockIdx.y, q0 = blockIdx.x * 128;

    const size_t hbase = (size_t)(b * H + h) * S * D;
    const float* kbp = g_kbias + (size_t)(b * H + h) * S;

    // ---- stage Q (hi->QP pitch 76, lo->QLO pitch 68) via cp.async ----
    #pragma unroll
    for (int t = 0; t < 8; t++) {
        int i = tid + t * 256;
        int r = i >> 4, c4 = (i & 15) << 2;
        size_t gi = hbase + (size_t)(q0 + r) * D + c4;
        cpa16(&sm[QP_OFF + r * 76 + c4], g_Qhi + gi);
        cpa16(&sm[QLO_OFF + r * QLP + c4], g_Qlo + gi);
    }
    CP_COMMIT_WAIT();
    __syncthreads();

    // Q-hi fragments -> registers
    unsigned qa[8][4];
    {
        const int qb = QP_OFF + (w * 16 + g) * 76;
        #pragma unroll
        for (int kk = 0; kk < 8; kk++) {
            qa[kk][0] = sm[qb + kk * 8 + tig];
            qa[kk][1] = sm[qb + 8 * 76 + kk * 8 + tig];
            qa[kk][2] = sm[qb + kk * 8 + tig + 4];
            qa[kk][3] = sm[qb + 8 * 76 + kk * 8 + tig + 4];
        }
    }
    __syncthreads();

    const float coeff_h = coeff[h];
    float rowb[2];
    rowb[0] = coeff_h * pb[b * S + q0 + w * 16 + g];
    rowb[1] = coeff_h * pb[b * S + q0 + w * 16 + g + 8];

    float mi[2] = {-1e30f, -1e30f}, li[2] = {0.0f, 0.0f};
    float o[8][4];
    #pragma unroll
    for (int nf = 0; nf < 8; nf++)
        #pragma unroll
        for (int c = 0; c < 4; c++) o[nf][c] = 0.0f;

    const int psH = QP_OFF + w * 576;             // per-warp P-hi 16x36
    const int qlb = QLO_OFF + (w * 16 + g) * QLP;

    for (int k0 = 0; k0 < S; k0 += 32) {
        // ---- stage K,V tiles via cp.async (pre-split planes) ----
        #pragma unroll
        for (int t = 0; t < 2; t++) {
            int i = tid + t * 256;
            int r = i >> 4, c4 = (i & 15) << 2;
            size_t gi = hbase + (size_t)(k0 + r) * D + c4;
            cpa16(&sm[KH_OFF + r * 76 + c4], g_Khi + gi);
            cpa16(&sm[KL_OFF + r * 76 + c4], g_Klo + gi);
            cpa16(&sm[VH_OFF + r * 72 + c4], g_Vhi + gi);
            cpa16(&sm[VL_OFF + r * 72 + c4], g_Vlo + gi);
        }
        CP_COMMIT_WAIT();
        __syncthreads();

        // ---- S = Q K^T, 3xTF32 ----
        float sc[4][4];
        #pragma unroll
        for (int fn = 0; fn < 4; fn++)
            #pragma unroll
            for (int c = 0; c < 4; c++) sc[fn][c] = 0.0f;

        #pragma unroll
        for (int kk = 0; kk < 8; kk++) {
            unsigned ql[4];
            ql[0] = sm[qlb + kk * 8 + tig];
            ql[1] = sm[qlb + 8 * QLP + kk * 8 + tig];
            ql[2] = sm[qlb + kk * 8 + tig + 4];
            ql[3] = sm[qlb + 8 * QLP + kk * 8 + tig + 4];
            #pragma unroll
            for (int fn = 0; fn < 4; fn++) {
                int kb = (fn * 8 + g) * 76 + kk * 8 + tig;
                unsigned kh0 = sm[KH_OFF + kb], kh1 = sm[KH_OFF + kb + 4];
                unsigned kl0 = sm[KL_OFF + kb], kl1 = sm[KL_OFF + kb + 4];
                mma8(sc[fn], qa[kk], kh0, kh1);
                mma8(sc[fn], ql,     kh0, kh1);
                mma8(sc[fn], qa[kk], kl0, kl1);
            }
        }

        // ---- scale + rel-pos bias + mask ----
        #pragma unroll
        for (int fn = 0; fn < 4; fn++) {
            int c = k0 + fn * 8 + 2 * tig;
            float cb0 = kbp[c], cb1 = kbp[c + 1];
            sc[fn][0] = sc[fn][0] * 0.125f + rowb[0] + cb0;
            sc[fn][1] = sc[fn][1] * 0.125f + rowb[0] + cb1;
            sc[fn][2] = sc[fn][2] * 0.125f + rowb[1] + cb0;
            sc[fn][3] = sc[fn][3] * 0.125f + rowb[1] + cb1;
        }

        // ---- online softmax; P stored hi-only ----
        #pragma unroll
        for (int rh = 0; rh < 2; rh++) {
            float tm = -1e30f;
            #pragma unroll
            for (int fn = 0; fn < 4; fn++)
                tm = fmaxf(tm, fmaxf(sc[fn][2 * rh], sc[fn][2 * rh + 1]));
            tm = fmaxf(tm, __shfl_xor_sync(0xffffffffu, tm, 1));
            tm = fmaxf(tm, __shfl_xor_sync(0xffffffffu, tm, 2));
            float mnew = fmaxf(fmaxf(mi[rh], tm), -1e20f);
            float psum = 0.0f;
            const int pro = (g + rh * 8) * 36;
            #pragma unroll
            for (int fn = 0; fn < 4; fn++) {
                float p0 = __expf(sc[fn][2 * rh] - mnew);
                float p1 = __expf(sc[fn][2 * rh + 1] - mnew);
                psum += p0 + p1;
                sm[psH + pro + fn * 8 + 2 * tig]     = f2tf(p0);
                sm[psH + pro + fn * 8 + 2 * tig + 1] = f2tf(p1);
            }
            psum += __shfl_xor_sync(0xffffffffu, psum, 1);
            psum += __shfl_xor_sync(0xffffffffu, psum, 2);
            float scale = __expf(mi[rh] - mnew);
            li[rh] = li[rh] * scale + psum;
            mi[rh] = mnew;
            #pragma unroll
            for (int nf = 0; nf < 8; nf++) {
                o[nf][2 * rh]     *= scale;
                o[nf][2 * rh + 1] *= scale;
            }
        }
        __syncwarp();

        // ---- O += P V, 2xTF32 (P-hi x V-hi + P-hi x V-lo) ----
        #pragma unroll
        for (int ks = 0; ks < 4; ks++) {
            unsigned pah[4];
            pah[0] = sm[psH + g * 36 + ks * 8 + tig];
            pah[1] = sm[psH + (g + 8) * 36 + ks * 8 + tig];
            pah[2] = sm[psH + g * 36 + ks * 8 + tig + 4];
            pah[3] = sm[psH + (g + 8) * 36 + ks * 8 + tig + 4];
            #pragma unroll
            for (int nf = 0; nf < 8; nf++) {
                int vb0i = (ks * 8 + tig) * 72 + nf * 8 + g;
                int vb1i = (ks * 8 + tig + 4) * 72 + nf * 8 + g;
                unsigned vh0 = sm[VH_OFF + vb0i], vh1 = sm[VH_OFF + vb1i];
                unsigned vl0 = sm[VL_OFF + vb0i], vl1 = sm[VL_OFF + vb1i];
                mma8(o[nf], pah, vh0, vh1);
                mma8(o[nf], pah, vl0, vl1);
            }
        }
        __syncthreads();
    }

    // ---- normalize + split + store to hi/lo planes [B,S,E] ----
    const float inv0 = 1.0f / li[0], inv1 = 1.0f / li[1];
    const int qg = q0 + w * 16 + g;
    #pragma unroll
    for (int nf = 0; nf < 8; nf++) {
        int d = nf * 8 + 2 * tig;
        size_t i0 = (size_t)(b * S + qg) * E + h * D + d;
        size_t i1 = (size_t)(b * S + qg + 8) * E + h * D + d;
        unsigned h0, l0, h1, l1;
        splt(o[nf][0] * inv0, h0, l0); splt(o[nf][1] * inv0, h1, l1);
        *(uint2*)&g_atthi[i0] = make_uint2(h0, h1);
        *(uint2*)&g_attlo[i0] = make_uint2(l0, l1);
        splt(o[nf][2] * inv1, h0, l0); splt(o[nf][3] * inv1, h1, l1);
        *(uint2*)&g_atthi[i1] = make_uint2(h0, h1);
        *(uint2*)&g_attlo[i1] = make_uint2(l0, l1);
    }
}

// ---------------------------------------------------------------------------
extern "C" void kernel_launch(void* const* d_in, const int* in_sizes, int n_in,
                              void* d_out, int out_size)
{
    const float* query = (const float*)d_in[0];
    const float* key   = (const float*)d_in[1];
    const float* value = (const float*)d_in[2];
    const float* pb    = (const float*)d_in[3];
    const unsigned char* mask = (const unsigned char*)d_in[4];
    const float* wq_w = (const float*)d_in[5];
    const float* wq_b = (const float*)d_in[6];
    const float* wk_w = (const float*)d_in[7];
    const float* wk_b = (const float*)d_in[8];
    const float* wv_w = (const float*)d_in[9];
    const float* wv_b = (const float*)d_in[10];
    const float* fc_w = (const float*)d_in[11];
    const float* fc_b = (const float*)d_in[12];
    const float* coeff = (const float*)d_in[13];
    float* out = (float*)d_out;

    const int attn_smem = ATT_SMEM_WORDS * (int)sizeof(unsigned);  // 111,616 B
    cudaFuncSetAttribute(attn_kernel,
                         cudaFuncAttributeMaxDynamicSharedMemorySize, attn_smem);

    mask_prep_kernel<<<1, 256>>>(mask);
    kbias_kernel<<<(B * H * S) / 256, 256>>>(pb, coeff);

    // one-time hi/lo splits (device globals resolved via symbol addresses
    // at compile time — device-side pointers of __device__ arrays are valid
    // kernel arguments when taken in device code; here we use the mapped
    // symbols directly through small launcher lambdas is not allowed, so we
    // obtain them with cudaGetSymbolAddress-free trick: pass via kernels
    // that reference the globals. Instead: split_kernel takes raw pointers,
    // and we get them from the device symbols below.)
    static unsigned *xhi = nullptr, *xlo = nullptr, *whi = nullptr, *wlo = nullptr;
    if (!xhi) {
        cudaGetSymbolAddress((void**)&xhi, g_Xhi);
        cudaGetSymbolAddress((void**)&xlo, g_Xlo);
        cudaGetSymbolAddress((void**)&whi, g_Whi);
        cudaGetSymbolAddress((void**)&wlo, g_Wlo);
    }
    split_kernel<<<(XN/4 + 255)/256, 256>>>(query, xhi + 0*XN, xlo + 0*XN, XN/4);
    split_kernel<<<(XN/4 + 255)/256, 256>>>(key,   xhi + 1*XN, xlo + 1*XN, XN/4);
    split_kernel<<<(XN/4 + 255)/256, 256>>>(value, xhi + 2*XN, xlo + 2*XN, XN/4);
    split_kernel<<<(WN/4 + 255)/256, 256>>>(wq_w, whi + 0*WN, wlo + 0*WN, WN/4);
    split_kernel<<<(WN/4 + 255)/256, 256>>>(wk_w, whi + 1*WN, wlo + 1*WN, WN/4);
    split_kernel<<<(WN/4 + 255)/256, 256>>>(wv_w, whi + 2*WN, wlo + 2*WN, WN/4);
    split_kernel<<<(WN/4 + 255)/256, 256>>>(fc_w, whi + 3*WN, wlo + 3*WN, WN/4);

    dim3 g1(E / 64, BSZ / 128, 3);    // (12, 32, 3)
    qkv_kernel<<<g1, 256>>>(wq_b, wk_b, wv_b);

    dim3 g2(S / 128, H, B);           // (16, 12, 2)
    attn_kernel<<<g2, 256, attn_smem>>>(pb, coeff);

    dim3 g3(E / 64, BSZ / 128);       // (12, 32)
    oproj_kernel<<<g3, 256>>>(fc_b, out);
}

// round 9
// speedup vs baseline: 1.6177x; 1.2249x over previous
#include <cuda_runtime.h>
#include <math.h>

#define B 2
#define S 2048
#define E 768
#define H 12
#define D 64
#define BSZ (B*S)
#define QKV_ELEMS (B*H*S*D)
#define XN (BSZ*E)
#define WN (E*E)

// Scratch (allocation-free rule: device globals)
__device__ unsigned g_Xhi[3*XN], g_Xlo[3*XN];
__device__ unsigned g_Whi[4*WN], g_Wlo[4*WN];
__device__ unsigned g_Qhi[QKV_ELEMS], g_Qlo[QKV_ELEMS];
__device__ unsigned g_Khi[QKV_ELEMS], g_Klo[QKV_ELEMS];
__device__ unsigned g_Vhi[QKV_ELEMS], g_Vlo[QKV_ELEMS];
__device__ unsigned g_att[XN];           // attention output, tf32-hi plane
__device__ float g_maskadd[BSZ];
__device__ float g_kbias[B*H*S];

// ---------------------------------------------------------------------------
__device__ __forceinline__ unsigned f2tf(float f) {
    unsigned u;
    asm("cvt.rna.tf32.f32 %0, %1;" : "=r"(u) : "f"(f));
    return u;
}
__device__ __forceinline__ void splt(float f, unsigned& hi, unsigned& lo) {
    hi = f2tf(f);
    lo = f2tf(f - __uint_as_float(hi));
}
__device__ __forceinline__ void mma8(float* c, const unsigned* a,
                                     unsigned b0, unsigned b1) {
    asm volatile(
        "mma.sync.aligned.m16n8k8.row.col.f32.tf32.tf32.f32 "
        "{%0,%1,%2,%3},{%4,%5,%6,%7},{%8,%9},{%0,%1,%2,%3};"
        : "+f"(c[0]), "+f"(c[1]), "+f"(c[2]), "+f"(c[3])
        : "r"(a[0]), "r"(a[1]), "r"(a[2]), "r"(a[3]), "r"(b0), "r"(b1));
}
__device__ __forceinline__ void cpa16(void* s, const void* g) {
    unsigned sa = (unsigned)__cvta_generic_to_shared(s);
    asm volatile("cp.async.cg.shared.global [%0], [%1], 16;"
                 :: "r"(sa), "l"(g));
}
#define CP_COMMIT() asm volatile("cp.async.commit_group;")
#define CP_WAIT0()  asm volatile("cp.async.wait_group 0;" ::: "memory")

// ---------------------------------------------------------------------------
__global__ void split_kernel(const float* __restrict__ src,
                             unsigned* __restrict__ hi_,
                             unsigned* __restrict__ lo_, int n4)
{
    int i = blockIdx.x * 256 + threadIdx.x;
    if (i < n4) {
        float4 v = ((const float4*)src)[i];
        uint4 hh, ll;
        splt(v.x, hh.x, ll.x); splt(v.y, hh.y, ll.y);
        splt(v.z, hh.z, ll.z); splt(v.w, hh.w, ll.w);
        ((uint4*)hi_)[i] = hh;
        ((uint4*)lo_)[i] = ll;
    }
}

__global__ void mask_prep_kernel(const unsigned char* __restrict__ m)
{
    __shared__ int cls[4];
    int tid = threadIdx.x;
    if (tid < 4) cls[tid] = 0;
    __syncthreads();
    for (int i = tid; i < BSZ; i += blockDim.x)
        if (m[i]) atomicAdd(&cls[i & 3], 1);
    __syncthreads();
    int mode = 0;
    if (cls[1] == 0 && cls[2] == 0 && cls[3] == 0) mode = 1;
    else if (cls[0] == 0 && cls[1] == 0)           mode = 2;
    for (int i = tid; i < BSZ; i += blockDim.x) {
        bool v;
        if (mode == 1)      v = ((const int*)m)[i] != 0;
        else if (mode == 2) v = ((const float*)m)[i] != 0.0f;
        else                v = m[i] != 0;
        g_maskadd[i] = v ? 0.0f : -1e30f;
    }
}

__global__ void kbias_kernel(const float* __restrict__ pb,
                             const float* __restrict__ coeff)
{
    int idx = blockIdx.x * 256 + threadIdx.x;
    int bh = idx / S, k = idx - bh * S;
    int b = bh / H, h = bh - b * H;
    g_kbias[idx] = -coeff[h] * pb[b * S + k] + g_maskadd[b * S + k];
}

// ---------------------------------------------------------------------------
// QKV projection, 3xTF32, double-buffered cp.async pipeline.
// CTA 128x64, 8 warps (32x32 tiles). smem layout (words):
//   A[stage][plane][128][20] @0 (10240), B[stage][plane][64][20] @10240 (5120)
// ---------------------------------------------------------------------------
#define GA(s,p,r,c) (((s) * 2 + (p)) * 2560 + (r) * 20 + (c))
#define GB(s,p,r,c) (10240 + ((s) * 2 + (p)) * 1280 + (r) * 20 + (c))
#define QKV_SMEM_WORDS 15360   // 61,440 B

__global__ __launch_bounds__(256, 2)
void qkv_kernel(const float* __restrict__ bq, const float* __restrict__ bk,
                const float* __restrict__ bv)
{
    const int z = blockIdx.z;
    const unsigned* Xhi = g_Xhi + (size_t)z * XN;
    const unsigned* Xlo = g_Xlo + (size_t)z * XN;
    const unsigned* Whi = g_Whi + (size_t)z * WN;
    const unsigned* Wlo = g_Wlo + (size_t)z * WN;
    const float* bias = (z == 0) ? bq : (z == 1) ? bk : bv;
    unsigned* ohi = (z == 0) ? g_Qhi : (z == 1) ? g_Khi : g_Vhi;
    unsigned* olo = (z == 0) ? g_Qlo : (z == 1) ? g_Klo : g_Vlo;
    const bool rope = (z < 2);

    extern __shared__ unsigned gsm[];

    const int tid = threadIdx.x;
    const int w = tid >> 5, wm = w >> 1, wn = w & 1;
    const int lane = tid & 31, g = lane >> 2, tig = lane & 3;
    const int m0 = blockIdx.y * 128, n0 = blockIdx.x * 64;
    const int ar0 = tid >> 2, ac = (tid & 3) << 2;

    float acc[2][4][4];
    #pragma unroll
    for (int a = 0; a < 2; a++)
        #pragma unroll
        for (int b2 = 0; b2 < 4; b2++)
            #pragma unroll
            for (int c = 0; c < 4; c++) acc[a][b2][c] = 0.0f;

    auto issueg = [&](int k0, int s) {
        #pragma unroll
        for (int t = 0; t < 2; t++) {
            int r = ar0 + t * 64;
            size_t gi = (size_t)(m0 + r) * E + k0 + ac;
            cpa16(&gsm[GA(s, 0, r, ac)], Xhi + gi);
            cpa16(&gsm[GA(s, 1, r, ac)], Xlo + gi);
        }
        size_t gi = (size_t)(n0 + ar0) * E + k0 + ac;
        cpa16(&gsm[GB(s, 0, ar0, ac)], Whi + gi);
        cpa16(&gsm[GB(s, 1, ar0, ac)], Wlo + gi);
        CP_COMMIT();
    };

    issueg(0, 0);
    for (int it = 0; it < E / 16; it++) {
        CP_WAIT0();
        __syncthreads();
        if (it + 1 < E / 16) issueg((it + 1) * 16, (it + 1) & 1);
        const int s = it & 1;
        #pragma unroll
        for (int kk = 0; kk < 16; kk += 8) {
            unsigned afh[2][4], afl[2][4], bh0[4], bl0[4], bh1[4], bl1[4];
            #pragma unroll
            for (int fm = 0; fm < 2; fm++) {
                int rb = wm * 32 + fm * 16 + g;
                afh[fm][0] = gsm[GA(s, 0, rb,     kk + tig)];
                afh[fm][1] = gsm[GA(s, 0, rb + 8, kk + tig)];
                afh[fm][2] = gsm[GA(s, 0, rb,     kk + tig + 4)];
                afh[fm][3] = gsm[GA(s, 0, rb + 8, kk + tig + 4)];
                afl[fm][0] = gsm[GA(s, 1, rb,     kk + tig)];
                afl[fm][1] = gsm[GA(s, 1, rb + 8, kk + tig)];
                afl[fm][2] = gsm[GA(s, 1, rb,     kk + tig + 4)];
                afl[fm][3] = gsm[GA(s, 1, rb + 8, kk + tig + 4)];
            }
            #pragma unroll
            for (int fn = 0; fn < 4; fn++) {
                int cb = wn * 32 + fn * 8 + g;
                bh0[fn] = gsm[GB(s, 0, cb, kk + tig)];
                bh1[fn] = gsm[GB(s, 0, cb, kk + tig + 4)];
                bl0[fn] = gsm[GB(s, 1, cb, kk + tig)];
                bl1[fn] = gsm[GB(s, 1, cb, kk + tig + 4)];
            }
            #pragma unroll
            for (int fm = 0; fm < 2; fm++)
                #pragma unroll
                for (int fn = 0; fn < 4; fn++) {
                    mma8(acc[fm][fn], afh[fm], bh0[fn], bh1[fn]);
                    mma8(acc[fm][fn], afl[fm], bh0[fn], bh1[fn]);
                    mma8(acc[fm][fn], afh[fm], bl0[fn], bl1[fn]);
                }
        }
    }

    // epilogue: bias + RoPE (fp32) -> split -> hi/lo planes [B,H,S,D]
    #pragma unroll
    for (int fn = 0; fn < 4; fn++) {
        const int col = n0 + wn * 32 + fn * 8 + 2 * tig;
        const int h = col / D, d = col % D;
        const float b0v = bias[col], b1v = bias[col + 1];
        const float invf = rope
            ? exp2f(-(float)d * (13.287712379549449f / 64.0f)) : 0.0f;
        #pragma unroll
        for (int fm = 0; fm < 2; fm++) {
            const int row = m0 + wm * 32 + fm * 16 + g;
            #pragma unroll
            for (int half = 0; half < 2; half++) {
                const int r = row + half * 8;
                const int bb = r >> 11, sdx = r & 2047;
                float v0 = acc[fm][fn][half * 2 + 0] + b0v;
                float v1 = acc[fm][fn][half * 2 + 1] + b1v;
                if (rope) {
                    float sn, cs;
                    sincosf((float)sdx * invf, &sn, &cs);
                    float t0 = v0 * cs - v1 * sn;
                    v1 = v1 * cs + v0 * sn;
                    v0 = t0;
                }
                const size_t idx = (((size_t)bb * H + h) * S + sdx) * D + d;
                unsigned h0, l0, h1, l1;
                splt(v0, h0, l0); splt(v1, h1, l1);
                *(uint2*)&ohi[idx] = make_uint2(h0, h1);
                *(uint2*)&olo[idx] = make_uint2(l0, l1);
            }
        }
    }
}

// ---------------------------------------------------------------------------
// Output projection: A = g_att (tf32-hi only), W hi/lo compensated.
// smem: A[stage][128][20] @0 (5120), B[stage][plane][64][20] @5120 (5120)
// ---------------------------------------------------------------------------
#define OA(s,r,c)   ((s) * 2560 + (r) * 20 + (c))
#define OB(s,p,r,c) (5120 + ((s) * 2 + (p)) * 1280 + (r) * 20 + (c))

__global__ __launch_bounds__(256, 2)
void oproj_kernel(const float* __restrict__ bias, float* __restrict__ out)
{
    const unsigned* Whi = g_Whi + (size_t)3 * WN;
    const unsigned* Wlo = g_Wlo + (size_t)3 * WN;

    __shared__ unsigned osm[10240];   // 40,960 B

    const int tid = threadIdx.x;
    const int w = tid >> 5, wm = w >> 1, wn = w & 1;
    const int lane = tid & 31, g = lane >> 2, tig = lane & 3;
    const int m0 = blockIdx.y * 128, n0 = blockIdx.x * 64;
    const int ar0 = tid >> 2, ac = (tid & 3) << 2;

    float acc[2][4][4];
    #pragma unroll
    for (int a = 0; a < 2; a++)
        #pragma unroll
        for (int b2 = 0; b2 < 4; b2++)
            #pragma unroll
            for (int c = 0; c < 4; c++) acc[a][b2][c] = 0.0f;

    auto issueg = [&](int k0, int s) {
        #pragma unroll
        for (int t = 0; t < 2; t++) {
            int r = ar0 + t * 64;
            cpa16(&osm[OA(s, r, ac)], g_att + (size_t)(m0 + r) * E + k0 + ac);
        }
        size_t gi = (size_t)(n0 + ar0) * E + k0 + ac;
        cpa16(&osm[OB(s, 0, ar0, ac)], Whi + gi);
        cpa16(&osm[OB(s, 1, ar0, ac)], Wlo + gi);
        CP_COMMIT();
    };

    issueg(0, 0);
    for (int it = 0; it < E / 16; it++) {
        CP_WAIT0();
        __syncthreads();
        if (it + 1 < E / 16) issueg((it + 1) * 16, (it + 1) & 1);
        const int s = it & 1;
        #pragma unroll
        for (int kk = 0; kk < 16; kk += 8) {
            unsigned afh[2][4], bh0[4], bl0[4], bh1[4], bl1[4];
            #pragma unroll
            for (int fm = 0; fm < 2; fm++) {
                int rb = wm * 32 + fm * 16 + g;
                afh[fm][0] = osm[OA(s, rb,     kk + tig)];
                afh[fm][1] = osm[OA(s, rb + 8, kk + tig)];
                afh[fm][2] = osm[OA(s, rb,     kk + tig + 4)];
                afh[fm][3] = osm[OA(s, rb + 8, kk + tig + 4)];
            }
            #pragma unroll
            for (int fn = 0; fn < 4; fn++) {
                int cb = wn * 32 + fn * 8 + g;
                bh0[fn] = osm[OB(s, 0, cb, kk + tig)];
                bh1[fn] = osm[OB(s, 0, cb, kk + tig + 4)];
                bl0[fn] = osm[OB(s, 1, cb, kk + tig)];
                bl1[fn] = osm[OB(s, 1, cb, kk + tig + 4)];
            }
            #pragma unroll
            for (int fm = 0; fm < 2; fm++)
                #pragma unroll
                for (int fn = 0; fn < 4; fn++) {
                    mma8(acc[fm][fn], afh[fm], bh0[fn], bh1[fn]);
                    mma8(acc[fm][fn], afh[fm], bl0[fn], bl1[fn]);
                }
        }
    }

    #pragma unroll
    for (int fn = 0; fn < 4; fn++) {
        const int col = n0 + wn * 32 + fn * 8 + 2 * tig;
        const float b0v = bias[col], b1v = bias[col + 1];
        #pragma unroll
        for (int fm = 0; fm < 2; fm++) {
            const int row = m0 + wm * 32 + fm * 16 + g;
            #pragma unroll
            for (int half = 0; half < 2; half++) {
                const int r = row + half * 8;
                *(float2*)&out[(size_t)r * E + col] =
                    make_float2(acc[fm][fn][half * 2 + 0] + b0v,
                                acc[fm][fn][half * 2 + 1] + b1v);
            }
        }
    }
}

// ---------------------------------------------------------------------------
// Flash attention, 3xTF32 scores, 1-plane-V PV, double-buffered K/V tiles.
// smem (words): stage s @ s*7168: KH[32][76], KL @+2432, VH[32][72] @+4864.
//   P @14336 (per-warp 16x36), QLO @18944 (128x68). Total 27648 w = 110,592 B
// ---------------------------------------------------------------------------
#define STGW 7168
#define P_OFF 14336
#define QL_OFF 18944
#define QLP 68
#define ATT_SMEM_WORDS 27648

__global__ __launch_bounds__(256, 2)
void attn_kernel(const float* __restrict__ pb, const float* __restrict__ coeff)
{
    extern __shared__ unsigned sm[];

    const int tid = threadIdx.x;
    const int w = tid >> 5, lane = tid & 31, g = lane >> 2, tig = lane & 3;
    const int b = blockIdx.z, h = blockIdx.y, q0 = blockIdx.x * 128;

    const size_t hbase = (size_t)(b * H + h) * S * D;
    const float* kbp = g_kbias + (size_t)(b * H + h) * S;

    // ---- prologue: stage Q-hi (pitch 76 over buf region) + Q-lo (QLO) ----
    #pragma unroll
    for (int t = 0; t < 8; t++) {
        int i = tid + t * 256;
        int r = i >> 4, c4 = (i & 15) << 2;
        size_t gi = hbase + (size_t)(q0 + r) * D + c4;
        cpa16(&sm[r * 76 + c4], g_Qhi + gi);
        cpa16(&sm[QL_OFF + r * QLP + c4], g_Qlo + gi);
    }
    CP_COMMIT();
    CP_WAIT0();
    __syncthreads();

    unsigned qa[8][4];
    {
        const int qb = (w * 16 + g) * 76;
        #pragma unroll
        for (int kk = 0; kk < 8; kk++) {
            qa[kk][0] = sm[qb + kk * 8 + tig];
            qa[kk][1] = sm[qb + 8 * 76 + kk * 8 + tig];
            qa[kk][2] = sm[qb + kk * 8 + tig + 4];
            qa[kk][3] = sm[qb + 8 * 76 + kk * 8 + tig + 4];
        }
    }
    __syncthreads();

    const float coeff_h = coeff[h];
    float rowb[2];
    rowb[0] = coeff_h * pb[b * S + q0 + w * 16 + g];
    rowb[1] = coeff_h * pb[b * S + q0 + w * 16 + g + 8];

    float mi[2] = {-1e30f, -1e30f}, li[2] = {0.0f, 0.0f};
    float o[8][4];
    #pragma unroll
    for (int nf = 0; nf < 8; nf++)
        #pragma unroll
        for (int c = 0; c < 4; c++) o[nf][c] = 0.0f;

    const int psH = P_OFF + w * 576;
    const int qlb = QL_OFF + (w * 16 + g) * QLP;

    auto issuet = [&](int k0, int sb) {
        #pragma unroll
        for (int t = 0; t < 2; t++) {
            int i = tid + t * 256;
            int r = i >> 4, c4 = (i & 15) << 2;
            size_t gi = hbase + (size_t)(k0 + r) * D + c4;
            cpa16(&sm[sb + r * 76 + c4], g_Khi + gi);
            cpa16(&sm[sb + 2432 + r * 76 + c4], g_Klo + gi);
            cpa16(&sm[sb + 4864 + r * 72 + c4], g_Vhi + gi);
        }
        CP_COMMIT();
    };

    issuet(0, 0);
    for (int it = 0; it < S / 32; it++) {
        const int k0 = it * 32;
        CP_WAIT0();
        __syncthreads();
        if (it + 1 < S / 32) issuet(k0 + 32, ((it + 1) & 1) * STGW);
        const int sb = (it & 1) * STGW;

        // ---- S = Q K^T, 3xTF32 ----
        float sc[4][4];
        #pragma unroll
        for (int fn = 0; fn < 4; fn++)
            #pragma unroll
            for (int c = 0; c < 4; c++) sc[fn][c] = 0.0f;

        #pragma unroll
        for (int kk = 0; kk < 8; kk++) {
            unsigned ql[4];
            ql[0] = sm[qlb + kk * 8 + tig];
            ql[1] = sm[qlb + 8 * QLP + kk * 8 + tig];
            ql[2] = sm[qlb + kk * 8 + tig + 4];
            ql[3] = sm[qlb + 8 * QLP + kk * 8 + tig + 4];
            #pragma unroll
            for (int fn = 0; fn < 4; fn++) {
                int kb = sb + (fn * 8 + g) * 76 + kk * 8 + tig;
                unsigned kh0 = sm[kb], kh1 = sm[kb + 4];
                unsigned kl0 = sm[kb + 2432], kl1 = sm[kb + 2432 + 4];
                mma8(sc[fn], qa[kk], kh0, kh1);
                mma8(sc[fn], ql,     kh0, kh1);
                mma8(sc[fn], qa[kk], kl0, kl1);
            }
        }

        // ---- scale + rel-pos bias + mask ----
        #pragma unroll
        for (int fn = 0; fn < 4; fn++) {
            int c = k0 + fn * 8 + 2 * tig;
            float cb0 = kbp[c], cb1 = kbp[c + 1];
            sc[fn][0] = sc[fn][0] * 0.125f + rowb[0] + cb0;
            sc[fn][1] = sc[fn][1] * 0.125f + rowb[0] + cb1;
            sc[fn][2] = sc[fn][2] * 0.125f + rowb[1] + cb0;
            sc[fn][3] = sc[fn][3] * 0.125f + rowb[1] + cb1;
        }

        // ---- online softmax; P-hi only ----
        #pragma unroll
        for (int rh = 0; rh < 2; rh++) {
            float tm = -1e30f;
            #pragma unroll
            for (int fn = 0; fn < 4; fn++)
                tm = fmaxf(tm, fmaxf(sc[fn][2 * rh], sc[fn][2 * rh + 1]));
            tm = fmaxf(tm, __shfl_xor_sync(0xffffffffu, tm, 1));
            tm = fmaxf(tm, __shfl_xor_sync(0xffffffffu, tm, 2));
            float mnew = fmaxf(fmaxf(mi[rh], tm), -1e20f);
            float psum = 0.0f;
            const int pro = (g + rh * 8) * 36;
            #pragma unroll
            for (int fn = 0; fn < 4; fn++) {
                float p0 = __expf(sc[fn][2 * rh] - mnew);
                float p1 = __expf(sc[fn][2 * rh + 1] - mnew);
                psum += p0 + p1;
                sm[psH + pro + fn * 8 + 2 * tig]     = f2tf(p0);
                sm[psH + pro + fn * 8 + 2 * tig + 1] = f2tf(p1);
            }
            psum += __shfl_xor_sync(0xffffffffu, psum, 1);
            psum += __shfl_xor_sync(0xffffffffu, psum, 2);
            float scale = __expf(mi[rh] - mnew);
            li[rh] = li[rh] * scale + psum;
            mi[rh] = mnew;
            #pragma unroll
            for (int nf = 0; nf < 8; nf++) {
                o[nf][2 * rh]     *= scale;
                o[nf][2 * rh + 1] *= scale;
            }
        }
        __syncwarp();

        // ---- O += P V (V-hi only) ----
        #pragma unroll
        for (int ks = 0; ks < 4; ks++) {
            unsigned pah[4];
            pah[0] = sm[psH + g * 36 + ks * 8 + tig];
            pah[1] = sm[psH + (g + 8) * 36 + ks * 8 + tig];
            pah[2] = sm[psH + g * 36 + ks * 8 + tig + 4];
            pah[3] = sm[psH + (g + 8) * 36 + ks * 8 + tig + 4];
            #pragma unroll
            for (int nf = 0; nf < 8; nf++) {
                unsigned vh0 = sm[sb + 4864 + (ks * 8 + tig) * 72 + nf * 8 + g];
                unsigned vh1 = sm[sb + 4864 + (ks * 8 + tig + 4) * 72 + nf * 8 + g];
                mma8(o[nf], pah, vh0, vh1);
            }
        }
        __syncwarp();
    }

    // ---- normalize + store tf32-hi att plane [B,S,E] ----
    const float inv0 = 1.0f / li[0], inv1 = 1.0f / li[1];
    const int qg = q0 + w * 16 + g;
    #pragma unroll
    for (int nf = 0; nf < 8; nf++) {
        int d = nf * 8 + 2 * tig;
        size_t i0 = (size_t)(b * S + qg) * E + h * D + d;
        size_t i1 = (size_t)(b * S + qg + 8) * E + h * D + d;
        *(uint2*)&g_att[i0] = make_uint2(f2tf(o[nf][0] * inv0),
                                         f2tf(o[nf][1] * inv0));
        *(uint2*)&g_att[i1] = make_uint2(f2tf(o[nf][2] * inv1),
                                         f2tf(o[nf][3] * inv1));
    }
}

// ---------------------------------------------------------------------------
extern "C" void kernel_launch(void* const* d_in, const int* in_sizes, int n_in,
                              void* d_out, int out_size)
{
    const float* query = (const float*)d_in[0];
    const float* key   = (const float*)d_in[1];
    const float* value = (const float*)d_in[2];
    const float* pb    = (const float*)d_in[3];
    const unsigned char* mask = (const unsigned char*)d_in[4];
    const float* wq_w = (const float*)d_in[5];
    const float* wq_b = (const float*)d_in[6];
    const float* wk_w = (const float*)d_in[7];
    const float* wk_b = (const float*)d_in[8];
    const float* wv_w = (const float*)d_in[9];
    const float* wv_b = (const float*)d_in[10];
    const float* fc_w = (const float*)d_in[11];
    const float* fc_b = (const float*)d_in[12];
    const float* coeff = (const float*)d_in[13];
    float* out = (float*)d_out;

    const int attn_smem = ATT_SMEM_WORDS * (int)sizeof(unsigned);  // 110,592 B
    const int qkv_smem  = QKV_SMEM_WORDS * (int)sizeof(unsigned);  // 61,440 B
    cudaFuncSetAttribute(attn_kernel,
                         cudaFuncAttributeMaxDynamicSharedMemorySize, attn_smem);
    cudaFuncSetAttribute(qkv_kernel,
                         cudaFuncAttributeMaxDynamicSharedMemorySize, qkv_smem);

    mask_prep_kernel<<<1, 256>>>(mask);
    kbias_kernel<<<(B * H * S) / 256, 256>>>(pb, coeff);

    static unsigned *xhi = nullptr, *xlo = nullptr, *whi = nullptr, *wlo = nullptr;
    if (!xhi) {
        cudaGetSymbolAddress((void**)&xhi, g_Xhi);
        cudaGetSymbolAddress((void**)&xlo, g_Xlo);
        cudaGetSymbolAddress((void**)&whi, g_Whi);
        cudaGetSymbolAddress((void**)&wlo, g_Wlo);
    }
    split_kernel<<<(XN/4 + 255)/256, 256>>>(query, xhi + 0*XN, xlo + 0*XN, XN/4);
    split_kernel<<<(XN/4 + 255)/256, 256>>>(key,   xhi + 1*XN, xlo + 1*XN, XN/4);
    split_kernel<<<(XN/4 + 255)/256, 256>>>(value, xhi + 2*XN, xlo + 2*XN, XN/4);
    split_kernel<<<(WN/4 + 255)/256, 256>>>(wq_w, whi + 0*WN, wlo + 0*WN, WN/4);
    split_kernel<<<(WN/4 + 255)/256, 256>>>(wk_w, whi + 1*WN, wlo + 1*WN, WN/4);
    split_kernel<<<(WN/4 + 255)/256, 256>>>(wv_w, whi + 2*WN, wlo + 2*WN, WN/4);
    split_kernel<<<(WN/4 + 255)/256, 256>>>(fc_w, whi + 3*WN, wlo + 3*WN, WN/4);

    dim3 g1(E / 64, BSZ / 128, 3);    // (12, 32, 3)
    qkv_kernel<<<g1, 256, qkv_smem>>>(wq_b, wk_b, wv_b);

    dim3 g2(S / 128, H, B);           // (16, 12, 2)
    attn_kernel<<<g2, 256, attn_smem>>>(pb, coeff);

    dim3 g3(E / 64, BSZ / 128);       // (12, 32)
    oproj_kernel<<<g3, 256>>>(fc_b, out);
}

// round 10
// speedup vs baseline: 1.6370x; 1.0119x over previous
#include <cuda_runtime.h>
#include <math.h>

#define B 2
#define S 2048
#define E 768
#define H 12
#define D 64
#define BSZ (B*S)
#define QKV_ELEMS (B*H*S*D)
#define XN (BSZ*E)
#define WN (E*E)

// Scratch (allocation-free rule: device globals)
__device__ unsigned g_Xhi[3*XN], g_Xlo[3*XN];
__device__ unsigned g_Whi[4*WN], g_Wlo[4*WN];
__device__ unsigned g_Qhi[QKV_ELEMS], g_Qlo[QKV_ELEMS];
__device__ unsigned g_Khi[QKV_ELEMS], g_Klo[QKV_ELEMS];
__device__ unsigned g_Vhi[QKV_ELEMS], g_Vlo[QKV_ELEMS];
__device__ unsigned g_att[XN];           // attention output, tf32-hi plane
__device__ float g_kbias[B*H*S];

// ---------------------------------------------------------------------------
__device__ __forceinline__ unsigned f2tf(float f) {
    unsigned u;
    asm("cvt.rna.tf32.f32 %0, %1;" : "=r"(u) : "f"(f));
    return u;
}
__device__ __forceinline__ void splt(float f, unsigned& hi, unsigned& lo) {
    hi = f2tf(f);
    lo = f2tf(f - __uint_as_float(hi));
}
__device__ __forceinline__ void mma8(float* c, const unsigned* a,
                                     unsigned b0, unsigned b1) {
    asm volatile(
        "mma.sync.aligned.m16n8k8.row.col.f32.tf32.tf32.f32 "
        "{%0,%1,%2,%3},{%4,%5,%6,%7},{%8,%9},{%0,%1,%2,%3};"
        : "+f"(c[0]), "+f"(c[1]), "+f"(c[2]), "+f"(c[3])
        : "r"(a[0]), "r"(a[1]), "r"(a[2]), "r"(a[3]), "r"(b0), "r"(b1));
}
__device__ __forceinline__ void cpa16(void* s, const void* g) {
    unsigned sa = (unsigned)__cvta_generic_to_shared(s);
    asm volatile("cp.async.cg.shared.global [%0], [%1], 16;"
                 :: "r"(sa), "l"(g));
}
#define CP_COMMIT() asm volatile("cp.async.commit_group;")
#define CP_WAIT0()  asm volatile("cp.async.wait_group 0;" ::: "memory")

// ---------------------------------------------------------------------------
// One-time hi/lo split of all 7 inputs in a single kernel.
// ---------------------------------------------------------------------------
#define XQ4 (XN/4)
#define WQ4 (WN/4)
#define SPLIT_TASKS (3*XQ4 + 4*WQ4)   // 2,949,120 -> /256 = 11520 CTAs exact

__global__ void split_all_kernel(const float* __restrict__ q,
                                 const float* __restrict__ k,
                                 const float* __restrict__ v,
                                 const float* __restrict__ wq,
                                 const float* __restrict__ wk,
                                 const float* __restrict__ wv,
                                 const float* __restrict__ fc)
{
    int i = blockIdx.x * 256 + threadIdx.x;
    const float* src;
    unsigned *dh, *dl;
    int off;
    if (i < 3 * XQ4) {
        int z = i / XQ4;
        off = i - z * XQ4;
        src = (z == 0) ? q : (z == 1) ? k : v;
        dh = g_Xhi + (size_t)z * XN;
        dl = g_Xlo + (size_t)z * XN;
    } else {
        int j = i - 3 * XQ4;
        int z = j / WQ4;
        off = j - z * WQ4;
        src = (z == 0) ? wq : (z == 1) ? wk : (z == 2) ? wv : fc;
        dh = g_Whi + (size_t)z * WN;
        dl = g_Wlo + (size_t)z * WN;
    }
    float4 vv = ((const float4*)src)[off];
    uint4 hh, ll;
    splt(vv.x, hh.x, ll.x); splt(vv.y, hh.y, ll.y);
    splt(vv.z, hh.z, ll.z); splt(vv.w, hh.w, ll.w);
    ((uint4*)dh)[off] = hh;
    ((uint4*)dl)[off] = ll;
}

// ---------------------------------------------------------------------------
// kbias: classifies the mask dtype inline (per CTA, redundant but cheap),
// then writes g_kbias = -coeff[h]*pb[b,k] + (mask? 0 : -1e30).
// ---------------------------------------------------------------------------
__global__ void kbias_kernel(const unsigned char* __restrict__ m,
                             const float* __restrict__ pb,
                             const float* __restrict__ coeff)
{
    __shared__ int cls[4];
    int tid = threadIdx.x;
    if (tid < 4) cls[tid] = 0;
    __syncthreads();
    for (int i = tid; i < BSZ; i += 256)
        if (m[i]) atomicAdd(&cls[i & 3], 1);
    __syncthreads();
    int mode = 0;
    if (cls[1] == 0 && cls[2] == 0 && cls[3] == 0) mode = 1;      // int32
    else if (cls[0] == 0 && cls[1] == 0)           mode = 2;      // float32

    int idx = blockIdx.x * 256 + tid;
    int bh = idx / S, k = idx - bh * S;
    int b = bh / H, h = bh - b * H;
    bool v;
    int mi = b * S + k;
    if (mode == 1)      v = ((const int*)m)[mi] != 0;
    else if (mode == 2) v = ((const float*)m)[mi] != 0.0f;
    else                v = m[mi] != 0;
    g_kbias[idx] = -coeff[h] * pb[mi] + (v ? 0.0f : -1e30f);
}

// ---------------------------------------------------------------------------
// QKV projection, 3xTF32 (2xTF32 for V), double-buffered cp.async pipeline.
// CTA 128x64, 8 warps (32x32 tiles). Q pre-scaled by 1/8 (exact).
// ---------------------------------------------------------------------------
#define GA(s,p,r,c) (((s) * 2 + (p)) * 2560 + (r) * 20 + (c))
#define GB(s,p,r,c) (10240 + ((s) * 2 + (p)) * 1280 + (r) * 20 + (c))
#define QKV_SMEM_WORDS 15360   // 61,440 B

__global__ __launch_bounds__(256, 2)
void qkv_kernel(const float* __restrict__ bq, const float* __restrict__ bk,
                const float* __restrict__ bv)
{
    const int z = blockIdx.z;
    const unsigned* Xhi = g_Xhi + (size_t)z * XN;
    const unsigned* Xlo = g_Xlo + (size_t)z * XN;
    const unsigned* Whi = g_Whi + (size_t)z * WN;
    const unsigned* Wlo = g_Wlo + (size_t)z * WN;
    const float* bias = (z == 0) ? bq : (z == 1) ? bk : bv;
    unsigned* ohi = (z == 0) ? g_Qhi : (z == 1) ? g_Khi : g_Vhi;
    unsigned* olo = (z == 0) ? g_Qlo : (z == 1) ? g_Klo : g_Vlo;
    const bool rope = (z < 2);
    const bool vproj = (z == 2);

    extern __shared__ unsigned gsm[];

    const int tid = threadIdx.x;
    const int w = tid >> 5, wm = w >> 1, wn = w & 1;
    const int lane = tid & 31, g = lane >> 2, tig = lane & 3;
    const int m0 = blockIdx.y * 128, n0 = blockIdx.x * 64;
    const int ar0 = tid >> 2, ac = (tid & 3) << 2;

    float acc[2][4][4];
    #pragma unroll
    for (int a = 0; a < 2; a++)
        #pragma unroll
        for (int b2 = 0; b2 < 4; b2++)
            #pragma unroll
            for (int c = 0; c < 4; c++) acc[a][b2][c] = 0.0f;

    auto issueg = [&](int k0, int s) {
        #pragma unroll
        for (int t = 0; t < 2; t++) {
            int r = ar0 + t * 64;
            size_t gi = (size_t)(m0 + r) * E + k0 + ac;
            cpa16(&gsm[GA(s, 0, r, ac)], Xhi + gi);
            if (!vproj) cpa16(&gsm[GA(s, 1, r, ac)], Xlo + gi);
        }
        size_t gi = (size_t)(n0 + ar0) * E + k0 + ac;
        cpa16(&gsm[GB(s, 0, ar0, ac)], Whi + gi);
        cpa16(&gsm[GB(s, 1, ar0, ac)], Wlo + gi);
        CP_COMMIT();
    };

    issueg(0, 0);
    for (int it = 0; it < E / 16; it++) {
        CP_WAIT0();
        __syncthreads();
        if (it + 1 < E / 16) issueg((it + 1) * 16, (it + 1) & 1);
        const int s = it & 1;
        #pragma unroll
        for (int kk = 0; kk < 16; kk += 8) {
            unsigned afh[2][4], afl[2][4], bh0[4], bl0[4], bh1[4], bl1[4];
            #pragma unroll
            for (int fm = 0; fm < 2; fm++) {
                int rb = wm * 32 + fm * 16 + g;
                afh[fm][0] = gsm[GA(s, 0, rb,     kk + tig)];
                afh[fm][1] = gsm[GA(s, 0, rb + 8, kk + tig)];
                afh[fm][2] = gsm[GA(s, 0, rb,     kk + tig + 4)];
                afh[fm][3] = gsm[GA(s, 0, rb + 8, kk + tig + 4)];
                if (!vproj) {
                    afl[fm][0] = gsm[GA(s, 1, rb,     kk + tig)];
                    afl[fm][1] = gsm[GA(s, 1, rb + 8, kk + tig)];
                    afl[fm][2] = gsm[GA(s, 1, rb,     kk + tig + 4)];
                    afl[fm][3] = gsm[GA(s, 1, rb + 8, kk + tig + 4)];
                }
            }
            #pragma unroll
            for (int fn = 0; fn < 4; fn++) {
                int cb = wn * 32 + fn * 8 + g;
                bh0[fn] = gsm[GB(s, 0, cb, kk + tig)];
                bh1[fn] = gsm[GB(s, 0, cb, kk + tig + 4)];
                bl0[fn] = gsm[GB(s, 1, cb, kk + tig)];
                bl1[fn] = gsm[GB(s, 1, cb, kk + tig + 4)];
            }
            #pragma unroll
            for (int fm = 0; fm < 2; fm++)
                #pragma unroll
                for (int fn = 0; fn < 4; fn++) {
                    mma8(acc[fm][fn], afh[fm], bh0[fn], bh1[fn]);
                    if (!vproj) mma8(acc[fm][fn], afl[fm], bh0[fn], bh1[fn]);
                    mma8(acc[fm][fn], afh[fm], bl0[fn], bl1[fn]);
                }
        }
    }

    // epilogue: bias + RoPE (fp32) [+ 1/8 Q-scale, exact] -> hi/lo [B,H,S,D]
    #pragma unroll
    for (int fn = 0; fn < 4; fn++) {
        const int col = n0 + wn * 32 + fn * 8 + 2 * tig;
        const int h = col / D, d = col % D;
        const float b0v = bias[col], b1v = bias[col + 1];
        const float invf = rope
            ? exp2f(-(float)d * (13.287712379549449f / 64.0f)) : 0.0f;
        #pragma unroll
        for (int fm = 0; fm < 2; fm++) {
            const int row = m0 + wm * 32 + fm * 16 + g;
            #pragma unroll
            for (int half = 0; half < 2; half++) {
                const int r = row + half * 8;
                const int bb = r >> 11, sdx = r & 2047;
                float v0 = acc[fm][fn][half * 2 + 0] + b0v;
                float v1 = acc[fm][fn][half * 2 + 1] + b1v;
                if (rope) {
                    float sn, cs;
                    sincosf((float)sdx * invf, &sn, &cs);
                    float t0 = v0 * cs - v1 * sn;
                    v1 = v1 * cs + v0 * sn;
                    v0 = t0;
                }
                if (z == 0) { v0 *= 0.125f; v1 *= 0.125f; }   // exact
                const size_t idx = (((size_t)bb * H + h) * S + sdx) * D + d;
                unsigned h0, l0, h1, l1;
                splt(v0, h0, l0); splt(v1, h1, l1);
                *(uint2*)&ohi[idx] = make_uint2(h0, h1);
                if (!vproj) *(uint2*)&olo[idx] = make_uint2(l0, l1);
            }
        }
    }
}

// ---------------------------------------------------------------------------
// Output projection: A = g_att (tf32-hi), W hi/lo. 3 CTAs/SM -> single wave.
// ---------------------------------------------------------------------------
#define OA(s,r,c)   ((s) * 2560 + (r) * 20 + (c))
#define OB(s,p,r,c) (5120 + ((s) * 2 + (p)) * 1280 + (r) * 20 + (c))

__global__ __launch_bounds__(256, 3)
void oproj_kernel(const float* __restrict__ bias, float* __restrict__ out)
{
    const unsigned* Whi = g_Whi + (size_t)3 * WN;
    const unsigned* Wlo = g_Wlo + (size_t)3 * WN;

    __shared__ unsigned osm[10240];   // 40,960 B

    const int tid = threadIdx.x;
    const int w = tid >> 5, wm = w >> 1, wn = w & 1;
    const int lane = tid & 31, g = lane >> 2, tig = lane & 3;
    const int m0 = blockIdx.y * 128, n0 = blockIdx.x * 64;
    const int ar0 = tid >> 2, ac = (tid & 3) << 2;

    float acc[2][4][4];
    #pragma unroll
    for (int a = 0; a < 2; a++)
        #pragma unroll
        for (int b2 = 0; b2 < 4; b2++)
            #pragma unroll
            for (int c = 0; c < 4; c++) acc[a][b2][c] = 0.0f;

    auto issueg = [&](int k0, int s) {
        #pragma unroll
        for (int t = 0; t < 2; t++) {
            int r = ar0 + t * 64;
            cpa16(&osm[OA(s, r, ac)], g_att + (size_t)(m0 + r) * E + k0 + ac);
        }
        size_t gi = (size_t)(n0 + ar0) * E + k0 + ac;
        cpa16(&osm[OB(s, 0, ar0, ac)], Whi + gi);
        cpa16(&osm[OB(s, 1, ar0, ac)], Wlo + gi);
        CP_COMMIT();
    };

    issueg(0, 0);
    for (int it = 0; it < E / 16; it++) {
        CP_WAIT0();
        __syncthreads();
        if (it + 1 < E / 16) issueg((it + 1) * 16, (it + 1) & 1);
        const int s = it & 1;
        #pragma unroll
        for (int kk = 0; kk < 16; kk += 8) {
            unsigned afh[2][4], bh0[4], bl0[4], bh1[4], bl1[4];
            #pragma unroll
            for (int fm = 0; fm < 2; fm++) {
                int rb = wm * 32 + fm * 16 + g;
                afh[fm][0] = osm[OA(s, rb,     kk + tig)];
                afh[fm][1] = osm[OA(s, rb + 8, kk + tig)];
                afh[fm][2] = osm[OA(s, rb,     kk + tig + 4)];
                afh[fm][3] = osm[OA(s, rb + 8, kk + tig + 4)];
            }
            #pragma unroll
            for (int fn = 0; fn < 4; fn++) {
                int cb = wn * 32 + fn * 8 + g;
                bh0[fn] = osm[OB(s, 0, cb, kk + tig)];
                bh1[fn] = osm[OB(s, 0, cb, kk + tig + 4)];
                bl0[fn] = osm[OB(s, 1, cb, kk + tig)];
                bl1[fn] = osm[OB(s, 1, cb, kk + tig + 4)];
            }
            #pragma unroll
            for (int fm = 0; fm < 2; fm++)
                #pragma unroll
                for (int fn = 0; fn < 4; fn++) {
                    mma8(acc[fm][fn], afh[fm], bh0[fn], bh1[fn]);
                    mma8(acc[fm][fn], afh[fm], bl0[fn], bl1[fn]);
                }
        }
    }

    #pragma unroll
    for (int fn = 0; fn < 4; fn++) {
        const int col = n0 + wn * 32 + fn * 8 + 2 * tig;
        const float b0v = bias[col], b1v = bias[col + 1];
        #pragma unroll
        for (int fm = 0; fm < 2; fm++) {
            const int row = m0 + wm * 32 + fm * 16 + g;
            #pragma unroll
            for (int half = 0; half < 2; half++) {
                const int r = row + half * 8;
                *(float2*)&out[(size_t)r * E + col] =
                    make_float2(acc[fm][fn][half * 2 + 0] + b0v,
                                acc[fm][fn][half * 2 + 1] + b1v);
            }
        }
    }
}

// ---------------------------------------------------------------------------
// Flash attention, 3xTF32 scores, 1-plane-V PV. CTA = 64 q-rows, 8 warps.
// Warps 0-3 process keys [0,16) of every 32-key tile, warps 4-7 keys [16,32);
// per-warp online softmax, one intra-CTA (m,l,o) merge at the end.
// smem (words): stage s @ s*7168: KH[32][76], KL @+2432, VH[32][72] @+4864.
//   P @14336 (per-warp 16x20), QLO @16896 (64x68). Total 21248 w = 84,992 B.
// ---------------------------------------------------------------------------
#define STGW 7168
#define P_OFF 14336
#define PWP 320
#define QL_OFF 16896
#define QLP 68
#define ATT_SMEM_WORDS 21248

__global__ __launch_bounds__(256, 2)
void attn_kernel(const float* __restrict__ pb, const float* __restrict__ coeff)
{
    extern __shared__ unsigned sm[];

    const int tid = threadIdx.x;
    const int w = tid >> 5, lane = tid & 31, g = lane >> 2, tig = lane & 3;
    const int wq4 = w & 3, khalf = w >> 2;
    const int b = blockIdx.z, h = blockIdx.y, q0 = blockIdx.x * 64;

    const size_t hbase = (size_t)(b * H + h) * S * D;
    const float* kbp = g_kbias + (size_t)(b * H + h) * S;

    // ---- prologue: stage Q-hi (stage0 region, pitch 76) + Q-lo (QLO) ----
    #pragma unroll
    for (int t = 0; t < 4; t++) {
        int i = tid + t * 256;
        int r = i >> 4, c4 = (i & 15) << 2;
        size_t gi = hbase + (size_t)(q0 + r) * D + c4;
        cpa16(&sm[r * 76 + c4], g_Qhi + gi);
        cpa16(&sm[QL_OFF + r * QLP + c4], g_Qlo + gi);
    }
    CP_COMMIT();
    CP_WAIT0();
    __syncthreads();

    unsigned qa[8][4];
    {
        const int qb = (wq4 * 16 + g) * 76;
        #pragma unroll
        for (int kk = 0; kk < 8; kk++) {
            qa[kk][0] = sm[qb + kk * 8 + tig];
            qa[kk][1] = sm[qb + 8 * 76 + kk * 8 + tig];
            qa[kk][2] = sm[qb + kk * 8 + tig + 4];
            qa[kk][3] = sm[qb + 8 * 76 + kk * 8 + tig + 4];
        }
    }
    __syncthreads();

    const float coeff_h = coeff[h];
    float rowb[2];
    rowb[0] = coeff_h * pb[b * S + q0 + wq4 * 16 + g];
    rowb[1] = coeff_h * pb[b * S + q0 + wq4 * 16 + g + 8];

    float mi[2] = {-1e30f, -1e30f}, li[2] = {0.0f, 0.0f};
    float o[8][4];
    #pragma unroll
    for (int nf = 0; nf < 8; nf++)
        #pragma unroll
        for (int c = 0; c < 4; c++) o[nf][c] = 0.0f;

    const int pw  = P_OFF + w * PWP;
    const int qlb = QL_OFF + (wq4 * 16 + g) * QLP;

    auto issuet = [&](int k0, int sb) {
        #pragma unroll
        for (int t = 0; t < 2; t++) {
            int i = tid + t * 256;
            int r = i >> 4, c4 = (i & 15) << 2;
            size_t gi = hbase + (size_t)(k0 + r) * D + c4;
            cpa16(&sm[sb + r * 76 + c4], g_Khi + gi);
            cpa16(&sm[sb + 2432 + r * 76 + c4], g_Klo + gi);
            cpa16(&sm[sb + 4864 + r * 72 + c4], g_Vhi + gi);
        }
        CP_COMMIT();
    };

    issuet(0, 0);
    for (int it = 0; it < S / 32; it++) {
        const int k0 = it * 32;
        CP_WAIT0();
        __syncthreads();
        if (it + 1 < S / 32) issuet(k0 + 32, ((it + 1) & 1) * STGW);
        const int sb = (it & 1) * STGW;

        // ---- S = Q K^T over this warp's 16-key half, 3xTF32 ----
        float sc[2][4];
        #pragma unroll
        for (int f = 0; f < 2; f++)
            #pragma unroll
            for (int c = 0; c < 4; c++) sc[f][c] = 0.0f;

        #pragma unroll
        for (int kk = 0; kk < 8; kk++) {
            unsigned ql[4];
            ql[0] = sm[qlb + kk * 8 + tig];
            ql[1] = sm[qlb + 8 * QLP + kk * 8 + tig];
            ql[2] = sm[qlb + kk * 8 + tig + 4];
            ql[3] = sm[qlb + 8 * QLP + kk * 8 + tig + 4];
            #pragma unroll
            for (int f = 0; f < 2; f++) {
                int kb = sb + (khalf * 16 + f * 8 + g) * 76 + kk * 8 + tig;
                unsigned kh0 = sm[kb], kh1 = sm[kb + 4];
                unsigned kl0 = sm[kb + 2432], kl1 = sm[kb + 2432 + 4];
                mma8(sc[f], qa[kk], kh0, kh1);
                mma8(sc[f], ql,     kh0, kh1);
                mma8(sc[f], qa[kk], kl0, kl1);
            }
        }

        // ---- rel-pos bias + mask (Q pre-scaled by 1/8) ----
        #pragma unroll
        for (int f = 0; f < 2; f++) {
            int c = k0 + khalf * 16 + f * 8 + 2 * tig;
            float cb0 = kbp[c], cb1 = kbp[c + 1];
            sc[f][0] += rowb[0] + cb0;
            sc[f][1] += rowb[0] + cb1;
            sc[f][2] += rowb[1] + cb0;
            sc[f][3] += rowb[1] + cb1;
        }

        // ---- online softmax over this warp's key half ----
        #pragma unroll
        for (int rh = 0; rh < 2; rh++) {
            float tm = fmaxf(fmaxf(sc[0][2 * rh], sc[0][2 * rh + 1]),
                             fmaxf(sc[1][2 * rh], sc[1][2 * rh + 1]));
            tm = fmaxf(tm, __shfl_xor_sync(0xffffffffu, tm, 1));
            tm = fmaxf(tm, __shfl_xor_sync(0xffffffffu, tm, 2));
            float mnew = fmaxf(fmaxf(mi[rh], tm), -1e20f);
            float psum = 0.0f;
            const int pro = pw + (g + rh * 8) * 20;
            #pragma unroll
            for (int f = 0; f < 2; f++) {
                float p0 = __expf(sc[f][2 * rh] - mnew);
                float p1 = __expf(sc[f][2 * rh + 1] - mnew);
                psum += p0 + p1;
                *(uint2*)&sm[pro + f * 8 + 2 * tig] =
                    make_uint2(f2tf(p0), f2tf(p1));
            }
            psum += __shfl_xor_sync(0xffffffffu, psum, 1);
            psum += __shfl_xor_sync(0xffffffffu, psum, 2);
            float scale = __expf(mi[rh] - mnew);
            li[rh] = li[rh] * scale + psum;
            mi[rh] = mnew;
            #pragma unroll
            for (int nf = 0; nf < 8; nf++) {
                o[nf][2 * rh]     *= scale;
                o[nf][2 * rh + 1] *= scale;
            }
        }
        __syncwarp();

        // ---- O += P V over the 16-key half (V-hi only) ----
        #pragma unroll
        for (int ks = 0; ks < 2; ks++) {
            unsigned pah[4];
            pah[0] = sm[pw + g * 20 + ks * 8 + tig];
            pah[1] = sm[pw + (g + 8) * 20 + ks * 8 + tig];
            pah[2] = sm[pw + g * 20 + ks * 8 + tig + 4];
            pah[3] = sm[pw + (g + 8) * 20 + ks * 8 + tig + 4];
            const int vr0 = khalf * 16 + ks * 8 + tig;
            #pragma unroll
            for (int nf = 0; nf < 8; nf++) {
                unsigned vh0 = sm[sb + 4864 + vr0 * 72 + nf * 8 + g];
                unsigned vh1 = sm[sb + 4864 + (vr0 + 4) * 72 + nf * 8 + g];
                mma8(o[nf], pah, vh0, vh1);
            }
        }
        __syncwarp();
    }

    // ---- merge key-halves across partner warps (w and w+4) ----
    __syncthreads();
    // partner dump region (stage area): per pair wq4: o 16x64 @wq4*1088,
    // m/l 16x2 @wq4*1088+1024
    const int mb = wq4 * 1088;
    if (khalf == 1) {
        #pragma unroll
        for (int rh = 0; rh < 2; rh++) {
            if (tig == 0) {
                sm[mb + 1024 + (g + rh * 8) * 2]     = __float_as_uint(mi[rh]);
                sm[mb + 1024 + (g + rh * 8) * 2 + 1] = __float_as_uint(li[rh]);
            }
            #pragma unroll
            for (int nf = 0; nf < 8; nf++)
                *(uint2*)&sm[mb + (g + rh * 8) * 64 + nf * 8 + 2 * tig] =
                    make_uint2(__float_as_uint(o[nf][2 * rh]),
                               __float_as_uint(o[nf][2 * rh + 1]));
        }
    }
    __syncthreads();
    if (khalf == 0) {
        const int qg = q0 + wq4 * 16 + g;
        #pragma unroll
        for (int rh = 0; rh < 2; rh++) {
            float m2 = __uint_as_float(sm[mb + 1024 + (g + rh * 8) * 2]);
            float l2 = __uint_as_float(sm[mb + 1024 + (g + rh * 8) * 2 + 1]);
            float mf = fmaxf(mi[rh], m2);
            float a1 = __expf(mi[rh] - mf), a2 = __expf(m2 - mf);
            float inv = 1.0f / (li[rh] * a1 + l2 * a2);
            float a1i = a1 * inv, a2i = a2 * inv;
            size_t ob = (size_t)(b * S + qg + rh * 8) * E + h * D;
            #pragma unroll
            for (int nf = 0; nf < 8; nf++) {
                uint2 o2 = *(uint2*)&sm[mb + (g + rh * 8) * 64 + nf * 8 + 2 * tig];
                float f0 = o[nf][2 * rh]     * a1i + __uint_as_float(o2.x) * a2i;
                float f1 = o[nf][2 * rh + 1] * a1i + __uint_as_float(o2.y) * a2i;
                *(uint2*)&g_att[ob + nf * 8 + 2 * tig] =
                    make_uint2(f2tf(f0), f2tf(f1));
            }
        }
    }
}

// ---------------------------------------------------------------------------
extern "C" void kernel_launch(void* const* d_in, const int* in_sizes, int n_in,
                              void* d_out, int out_size)
{
    const float* query = (const float*)d_in[0];
    const float* key   = (const float*)d_in[1];
    const float* value = (const float*)d_in[2];
    const float* pb    = (const float*)d_in[3];
    const unsigned char* mask = (const unsigned char*)d_in[4];
    const float* wq_w = (const float*)d_in[5];
    const float* wq_b = (const float*)d_in[6];
    const float* wk_w = (const float*)d_in[7];
    const float* wk_b = (const float*)d_in[8];
    const float* wv_w = (const float*)d_in[9];
    const float* wv_b = (const float*)d_in[10];
    const float* fc_w = (const float*)d_in[11];
    const float* fc_b = (const float*)d_in[12];
    const float* coeff = (const float*)d_in[13];
    float* out = (float*)d_out;

    const int attn_smem = ATT_SMEM_WORDS * (int)sizeof(unsigned);  // 84,992 B
    const int qkv_smem  = QKV_SMEM_WORDS * (int)sizeof(unsigned);  // 61,440 B
    cudaFuncSetAttribute(attn_kernel,
                         cudaFuncAttributeMaxDynamicSharedMemorySize, attn_smem);
    cudaFuncSetAttribute(qkv_kernel,
                         cudaFuncAttributeMaxDynamicSharedMemorySize, qkv_smem);

    kbias_kernel<<<(B * H * S) / 256, 256>>>(mask, pb, coeff);
    split_all_kernel<<<SPLIT_TASKS / 256, 256>>>(query, key, value,
                                                 wq_w, wk_w, wv_w, fc_w);

    dim3 g1(E / 64, BSZ / 128, 3);    // (12, 32, 3)
    qkv_kernel<<<g1, 256, qkv_smem>>>(wq_b, wk_b, wv_b);

    dim3 g2(S / 64, H, B);            // (32, 12, 2)
    attn_kernel<<<g2, 256, attn_smem>>>(pb, coeff);

    dim3 g3(E / 64, BSZ / 128);       // (12, 32)
    oproj_kernel<<<g3, 256>>>(fc_b, out);
}

// round 12
// speedup vs baseline: 1.7342x; 1.0594x over previous
#include <cuda_runtime.h>
#include <math.h>

#define B 2
#define S 2048
#define E 768
#define H 12
#define D 64
#define BSZ (B*S)
#define QKV_ELEMS (B*H*S*D)
#define XN (BSZ*E)
#define WN (E*E)
#define BHS (B*H*S)

// Scratch (allocation-free rule: device globals)
__device__ unsigned g_Xhi[3*XN], g_Xlo[3*XN];
__device__ unsigned g_Whi[4*WN], g_Wlo[4*WN];
__device__ unsigned g_Qhi[QKV_ELEMS], g_Qlo[QKV_ELEMS];
__device__ unsigned g_Khi[QKV_ELEMS], g_Klo[QKV_ELEMS];
__device__ unsigned g_Vhi[QKV_ELEMS], g_Vlo[QKV_ELEMS];
__device__ unsigned g_att[XN];            // attention output, tf32-hi plane
__device__ float g_po[2*QKV_ELEMS];       // split-KV partial O (unnormalized)
__device__ float g_pml[2*BHS*2];          // split-KV partial (m, l)
__device__ float g_kbias[B*H*S];

// ---------------------------------------------------------------------------
__device__ __forceinline__ unsigned f2tf(float f) {
    unsigned u;
    asm("cvt.rna.tf32.f32 %0, %1;" : "=r"(u) : "f"(f));
    return u;
}
__device__ __forceinline__ void splt(float f, unsigned& hi, unsigned& lo) {
    hi = f2tf(f);
    lo = f2tf(f - __uint_as_float(hi));
}
__device__ __forceinline__ void mma8(float* c, const unsigned* a,
                                     unsigned b0, unsigned b1) {
    asm volatile(
        "mma.sync.aligned.m16n8k8.row.col.f32.tf32.tf32.f32 "
        "{%0,%1,%2,%3},{%4,%5,%6,%7},{%8,%9},{%0,%1,%2,%3};"
        : "+f"(c[0]), "+f"(c[1]), "+f"(c[2]), "+f"(c[3])
        : "r"(a[0]), "r"(a[1]), "r"(a[2]), "r"(a[3]), "r"(b0), "r"(b1));
}
__device__ __forceinline__ void cpa16(void* s, const void* g) {
    unsigned sa = (unsigned)__cvta_generic_to_shared(s);
    asm volatile("cp.async.cg.shared.global [%0], [%1], 16;"
                 :: "r"(sa), "l"(g));
}
#define CP_COMMIT() asm volatile("cp.async.commit_group;")
#define CP_WAIT0()  asm volatile("cp.async.wait_group 0;" ::: "memory")

// ---------------------------------------------------------------------------
// One-time hi/lo split of all 7 inputs in a single kernel.
// ---------------------------------------------------------------------------
#define XQ4 (XN/4)
#define WQ4 (WN/4)
#define SPLIT_TASKS (3*XQ4 + 4*WQ4)

__global__ void split_all_kernel(const float* __restrict__ q,
                                 const float* __restrict__ k,
                                 const float* __restrict__ v,
                                 const float* __restrict__ wq,
                                 const float* __restrict__ wk,
                                 const float* __restrict__ wv,
                                 const float* __restrict__ fc)
{
    int i = blockIdx.x * 256 + threadIdx.x;
    const float* src;
    unsigned *dh, *dl;
    int off;
    if (i < 3 * XQ4) {
        int z = i / XQ4;
        off = i - z * XQ4;
        src = (z == 0) ? q : (z == 1) ? k : v;
        dh = g_Xhi + (size_t)z * XN;
        dl = g_Xlo + (size_t)z * XN;
    } else {
        int j = i - 3 * XQ4;
        int z = j / WQ4;
        off = j - z * WQ4;
        src = (z == 0) ? wq : (z == 1) ? wk : (z == 2) ? wv : fc;
        dh = g_Whi + (size_t)z * WN;
        dl = g_Wlo + (size_t)z * WN;
    }
    float4 vv = ((const float4*)src)[off];
    uint4 hh, ll;
    splt(vv.x, hh.x, ll.x); splt(vv.y, hh.y, ll.y);
    splt(vv.z, hh.z, ll.z); splt(vv.w, hh.w, ll.w);
    ((uint4*)dh)[off] = hh;
    ((uint4*)dl)[off] = ll;
}

// ---------------------------------------------------------------------------
__global__ void kbias_kernel(const unsigned char* __restrict__ m,
                             const float* __restrict__ pb,
                             const float* __restrict__ coeff)
{
    __shared__ int cls[4];
    int tid = threadIdx.x;
    if (tid < 4) cls[tid] = 0;
    __syncthreads();
    for (int i = tid; i < BSZ; i += 256)
        if (m[i]) atomicAdd(&cls[i & 3], 1);
    __syncthreads();
    int mode = 0;
    if (cls[1] == 0 && cls[2] == 0 && cls[3] == 0) mode = 1;      // int32
    else if (cls[0] == 0 && cls[1] == 0)           mode = 2;      // float32

    int idx = blockIdx.x * 256 + tid;
    int bh = idx / S, k = idx - bh * S;
    int b = bh / H, h = bh - b * H;
    bool v;
    int mi = b * S + k;
    if (mode == 1)      v = ((const int*)m)[mi] != 0;
    else if (mode == 2) v = ((const float*)m)[mi] != 0.0f;
    else                v = m[mi] != 0;
    g_kbias[idx] = -coeff[h] * pb[mi] + (v ? 0.0f : -1e30f);
}

// ---------------------------------------------------------------------------
// QKV projection, 3xTF32 (2xTF32 for V), double-buffered cp.async pipeline.
// CTA 128x64, 8 warps (32x32 tiles). Q pre-scaled by 1/8 (exact).
// ---------------------------------------------------------------------------
#define GA(s,p,r,c) (((s) * 2 + (p)) * 2560 + (r) * 20 + (c))
#define GB(s,p,r,c) (10240 + ((s) * 2 + (p)) * 1280 + (r) * 20 + (c))
#define QKV_SMEM_WORDS 15360   // 61,440 B

__global__ __launch_bounds__(256, 2)
void qkv_kernel(const float* __restrict__ bq, const float* __restrict__ bk,
                const float* __restrict__ bv)
{
    const int z = blockIdx.z;
    const unsigned* Xhi = g_Xhi + (size_t)z * XN;
    const unsigned* Xlo = g_Xlo + (size_t)z * XN;
    const unsigned* Whi = g_Whi + (size_t)z * WN;
    const unsigned* Wlo = g_Wlo + (size_t)z * WN;
    const float* bias = (z == 0) ? bq : (z == 1) ? bk : bv;
    unsigned* ohi = (z == 0) ? g_Qhi : (z == 1) ? g_Khi : g_Vhi;
    unsigned* olo = (z == 0) ? g_Qlo : (z == 1) ? g_Klo : g_Vlo;
    const bool rope = (z < 2);
    const bool vproj = (z == 2);

    extern __shared__ unsigned gsm[];

    const int tid = threadIdx.x;
    const int w = tid >> 5, wm = w >> 1, wn = w & 1;
    const int lane = tid & 31, g = lane >> 2, tig = lane & 3;
    const int m0 = blockIdx.y * 128, n0 = blockIdx.x * 64;
    const int ar0 = tid >> 2, ac = (tid & 3) << 2;

    float acc[2][4][4];
    #pragma unroll
    for (int a = 0; a < 2; a++)
        #pragma unroll
        for (int b2 = 0; b2 < 4; b2++)
            #pragma unroll
            for (int c = 0; c < 4; c++) acc[a][b2][c] = 0.0f;

    auto issueg = [&](int k0, int s) {
        #pragma unroll
        for (int t = 0; t < 2; t++) {
            int r = ar0 + t * 64;
            size_t gi = (size_t)(m0 + r) * E + k0 + ac;
            cpa16(&gsm[GA(s, 0, r, ac)], Xhi + gi);
            if (!vproj) cpa16(&gsm[GA(s, 1, r, ac)], Xlo + gi);
        }
        size_t gi = (size_t)(n0 + ar0) * E + k0 + ac;
        cpa16(&gsm[GB(s, 0, ar0, ac)], Whi + gi);
        cpa16(&gsm[GB(s, 1, ar0, ac)], Wlo + gi);
        CP_COMMIT();
    };

    issueg(0, 0);
    for (int it = 0; it < E / 16; it++) {
        CP_WAIT0();
        __syncthreads();
        if (it + 1 < E / 16) issueg((it + 1) * 16, (it + 1) & 1);
        const int s = it & 1;
        #pragma unroll
        for (int kk = 0; kk < 16; kk += 8) {
            unsigned afh[2][4], afl[2][4], bh0[4], bl0[4], bh1[4], bl1[4];
            #pragma unroll
            for (int fm = 0; fm < 2; fm++) {
                int rb = wm * 32 + fm * 16 + g;
                afh[fm][0] = gsm[GA(s, 0, rb,     kk + tig)];
                afh[fm][1] = gsm[GA(s, 0, rb + 8, kk + tig)];
                afh[fm][2] = gsm[GA(s, 0, rb,     kk + tig + 4)];
                afh[fm][3] = gsm[GA(s, 0, rb + 8, kk + tig + 4)];
                if (!vproj) {
                    afl[fm][0] = gsm[GA(s, 1, rb,     kk + tig)];
                    afl[fm][1] = gsm[GA(s, 1, rb + 8, kk + tig)];
                    afl[fm][2] = gsm[GA(s, 1, rb,     kk + tig + 4)];
                    afl[fm][3] = gsm[GA(s, 1, rb + 8, kk + tig + 4)];
                }
            }
            #pragma unroll
            for (int fn = 0; fn < 4; fn++) {
                int cb = wn * 32 + fn * 8 + g;
                bh0[fn] = gsm[GB(s, 0, cb, kk + tig)];
                bh1[fn] = gsm[GB(s, 0, cb, kk + tig + 4)];
                bl0[fn] = gsm[GB(s, 1, cb, kk + tig)];
                bl1[fn] = gsm[GB(s, 1, cb, kk + tig + 4)];
            }
            #pragma unroll
            for (int fm = 0; fm < 2; fm++)
                #pragma unroll
                for (int fn = 0; fn < 4; fn++) {
                    mma8(acc[fm][fn], afh[fm], bh0[fn], bh1[fn]);
                    if (!vproj) mma8(acc[fm][fn], afl[fm], bh0[fn], bh1[fn]);
                    mma8(acc[fm][fn], afh[fm], bl0[fn], bl1[fn]);
                }
        }
    }

    // epilogue: bias + RoPE (fp32) [+ 1/8 Q-scale, exact] -> hi/lo [B,H,S,D]
    #pragma unroll
    for (int fn = 0; fn < 4; fn++) {
        const int col = n0 + wn * 32 + fn * 8 + 2 * tig;
        const int h = col / D, d = col % D;
        const float b0v = bias[col], b1v = bias[col + 1];
        const float invf = rope
            ? exp2f(-(float)d * (13.287712379549449f / 64.0f)) : 0.0f;
        #pragma unroll
        for (int fm = 0; fm < 2; fm++) {
            const int row = m0 + wm * 32 + fm * 16 + g;
            #pragma unroll
            for (int half = 0; half < 2; half++) {
                const int r = row + half * 8;
                const int bb = r >> 11, sdx = r & 2047;
                float v0 = acc[fm][fn][half * 2 + 0] + b0v;
                float v1 = acc[fm][fn][half * 2 + 1] + b1v;
                if (rope) {
                    float sn, cs;
                    sincosf((float)sdx * invf, &sn, &cs);
                    float t0 = v0 * cs - v1 * sn;
                    v1 = v1 * cs + v0 * sn;
                    v0 = t0;
                }
                if (z == 0) { v0 *= 0.125f; v1 *= 0.125f; }   // exact
                const size_t idx = (((size_t)bb * H + h) * S + sdx) * D + d;
                unsigned h0, l0, h1, l1;
                splt(v0, h0, l0); splt(v1, h1, l1);
                *(uint2*)&ohi[idx] = make_uint2(h0, h1);
                if (!vproj) *(uint2*)&olo[idx] = make_uint2(l0, l1);
            }
        }
    }
}

// ---------------------------------------------------------------------------
// Output projection: A = g_att (tf32-hi), W hi/lo. 3 CTAs/SM -> single wave.
// ---------------------------------------------------------------------------
#define OA(s,r,c)   ((s) * 2560 + (r) * 20 + (c))
#define OB(s,p,r,c) (5120 + ((s) * 2 + (p)) * 1280 + (r) * 20 + (c))

__global__ __launch_bounds__(256, 3)
void oproj_kernel(const float* __restrict__ bias, float* __restrict__ out)
{
    const unsigned* Whi = g_Whi + (size_t)3 * WN;
    const unsigned* Wlo = g_Wlo + (size_t)3 * WN;

    __shared__ unsigned osm[10240];   // 40,960 B

    const int tid = threadIdx.x;
    const int w = tid >> 5, wm = w >> 1, wn = w & 1;
    const int lane = tid & 31, g = lane >> 2, tig = lane & 3;
    const int m0 = blockIdx.y * 128, n0 = blockIdx.x * 64;
    const int ar0 = tid >> 2, ac = (tid & 3) << 2;

    float acc[2][4][4];
    #pragma unroll
    for (int a = 0; a < 2; a++)
        #pragma unroll
        for (int b2 = 0; b2 < 4; b2++)
            #pragma unroll
            for (int c = 0; c < 4; c++) acc[a][b2][c] = 0.0f;

    auto issueg = [&](int k0, int s) {
        #pragma unroll
        for (int t = 0; t < 2; t++) {
            int r = ar0 + t * 64;
            cpa16(&osm[OA(s, r, ac)], g_att + (size_t)(m0 + r) * E + k0 + ac);
        }
        size_t gi = (size_t)(n0 + ar0) * E + k0 + ac;
        cpa16(&osm[OB(s, 0, ar0, ac)], Whi + gi);
        cpa16(&osm[OB(s, 1, ar0, ac)], Wlo + gi);
        CP_COMMIT();
    };

    issueg(0, 0);
    for (int it = 0; it < E / 16; it++) {
        CP_WAIT0();
        __syncthreads();
        if (it + 1 < E / 16) issueg((it + 1) * 16, (it + 1) & 1);
        const int s = it & 1;
        #pragma unroll
        for (int kk = 0; kk < 16; kk += 8) {
            unsigned afh[2][4], bh0[4], bl0[4], bh1[4], bl1[4];
            #pragma unroll
            for (int fm = 0; fm < 2; fm++) {
                int rb = wm * 32 + fm * 16 + g;
                afh[fm][0] = osm[OA(s, rb,     kk + tig)];
                afh[fm][1] = osm[OA(s, rb + 8, kk + tig)];
                afh[fm][2] = osm[OA(s, rb,     kk + tig + 4)];
                afh[fm][3] = osm[OA(s, rb + 8, kk + tig + 4)];
            }
            #pragma unroll
            for (int fn = 0; fn < 4; fn++) {
                int cb = wn * 32 + fn * 8 + g;
                bh0[fn] = osm[OB(s, 0, cb, kk + tig)];
                bh1[fn] = osm[OB(s, 0, cb, kk + tig + 4)];
                bl0[fn] = osm[OB(s, 1, cb, kk + tig)];
                bl1[fn] = osm[OB(s, 1, cb, kk + tig + 4)];
            }
            #pragma unroll
            for (int fm = 0; fm < 2; fm++)
                #pragma unroll
                for (int fn = 0; fn < 4; fn++) {
                    mma8(acc[fm][fn], afh[fm], bh0[fn], bh1[fn]);
                    mma8(acc[fm][fn], afh[fm], bl0[fn], bl1[fn]);
                }
        }
    }

    #pragma unroll
    for (int fn = 0; fn < 4; fn++) {
        const int col = n0 + wn * 32 + fn * 8 + 2 * tig;
        const float b0v = bias[col], b1v = bias[col + 1];
        #pragma unroll
        for (int fm = 0; fm < 2; fm++) {
            const int row = m0 + wm * 32 + fm * 16 + g;
            #pragma unroll
            for (int half = 0; half < 2; half++) {
                const int r = row + half * 8;
                *(float2*)&out[(size_t)r * E + col] =
                    make_float2(acc[fm][fn][half * 2 + 0] + b0v,
                                acc[fm][fn][half * 2 + 1] + b1v);
            }
        }
    }
}

// ---------------------------------------------------------------------------
// Flash attention, split-KV. CTA = 128 q-rows x 1024-key range (blockIdx.y).
// Warp = 16 q x 32 k (4 fn). 3xTF32 scores, 1-plane PV.
// Partial (unnormalized O, m, l) -> gmem; merge kernel combines.
// smem (words): stage s @ s*7168: KH[32][76], KL @+2432, VH[32][72] @+4864.
//   P @14336 (per-warp 16x36), QLO @18944 (128x68). Total 27648 w = 110,592 B
// ---------------------------------------------------------------------------
#define STGW 7168
#define P_OFF 14336
#define QL_OFF 18944
#define QLP 68
#define ATT_SMEM_WORDS 27648

__global__ __launch_bounds__(256, 2)
void attn_kernel(const float* __restrict__ pb, const float* __restrict__ coeff)
{
    extern __shared__ unsigned sm[];

    const int tid = threadIdx.x;
    const int w = tid >> 5, lane = tid & 31, g = lane >> 2, tig = lane & 3;
    const int q0 = blockIdx.x * 128, split = blockIdx.y, bh = blockIdx.z;
    const int b = bh / H, h = bh - b * H;
    const int kbase = split * (S / 2);

    const size_t hbase = (size_t)bh * S * D;
    const float* kbp = g_kbias + (size_t)bh * S;

    // ---- prologue: stage Q-hi (stage area, pitch 76) + Q-lo (QLO) ----
    #pragma unroll
    for (int t = 0; t < 8; t++) {
        int i = tid + t * 256;
        int r = i >> 4, c4 = (i & 15) << 2;
        size_t gi = hbase + (size_t)(q0 + r) * D + c4;
        cpa16(&sm[r * 76 + c4], g_Qhi + gi);
        cpa16(&sm[QL_OFF + r * QLP + c4], g_Qlo + gi);
    }
    CP_COMMIT();
    CP_WAIT0();
    __syncthreads();

    unsigned qa[8][4];
    {
        const int qb = (w * 16 + g) * 76;
        #pragma unroll
        for (int kk = 0; kk < 8; kk++) {
            qa[kk][0] = sm[qb + kk * 8 + tig];
            qa[kk][1] = sm[qb + 8 * 76 + kk * 8 + tig];
            qa[kk][2] = sm[qb + kk * 8 + tig + 4];
            qa[kk][3] = sm[qb + 8 * 76 + kk * 8 + tig + 4];
        }
    }
    __syncthreads();

    const float coeff_h = coeff[h];
    float rowb[2];
    rowb[0] = coeff_h * pb[b * S + q0 + w * 16 + g];
    rowb[1] = coeff_h * pb[b * S + q0 + w * 16 + g + 8];

    float mi[2] = {-1e30f, -1e30f}, li[2] = {0.0f, 0.0f};
    float o[8][4];
    #pragma unroll
    for (int nf = 0; nf < 8; nf++)
        #pragma unroll
        for (int c = 0; c < 4; c++) o[nf][c] = 0.0f;

    const int psH = P_OFF + w * 576;
    const int qlb = QL_OFF + (w * 16 + g) * QLP;

    auto issuet = [&](int k0, int sb) {
        #pragma unroll
        for (int t = 0; t < 2; t++) {
            int i = tid + t * 256;
            int r = i >> 4, c4 = (i & 15) << 2;
            size_t gi = hbase + (size_t)(k0 + r) * D + c4;
            cpa16(&sm[sb + r * 76 + c4], g_Khi + gi);
            cpa16(&sm[sb + 2432 + r * 76 + c4], g_Klo + gi);
            cpa16(&sm[sb + 4864 + r * 72 + c4], g_Vhi + gi);
        }
        CP_COMMIT();
    };

    issuet(kbase, 0);
    for (int it = 0; it < S / 64; it++) {      // 32 tiles of 32 keys
        const int k0 = kbase + it * 32;
        CP_WAIT0();
        __syncthreads();
        if (it + 1 < S / 64) issuet(k0 + 32, ((it + 1) & 1) * STGW);
        const int sb = (it & 1) * STGW;

        // ---- S = Q K^T, 3xTF32 ----
        float sc[4][4];
        #pragma unroll
        for (int fn = 0; fn < 4; fn++)
            #pragma unroll
            for (int c = 0; c < 4; c++) sc[fn][c] = 0.0f;

        #pragma unroll
        for (int kk = 0; kk < 8; kk++) {
            unsigned ql[4];
            ql[0] = sm[qlb + kk * 8 + tig];
            ql[1] = sm[qlb + 8 * QLP + kk * 8 + tig];
            ql[2] = sm[qlb + kk * 8 + tig + 4];
            ql[3] = sm[qlb + 8 * QLP + kk * 8 + tig + 4];
            #pragma unroll
            for (int fn = 0; fn < 4; fn++) {
                int kb = sb + (fn * 8 + g) * 76 + kk * 8 + tig;
                unsigned kh0 = sm[kb], kh1 = sm[kb + 4];
                unsigned kl0 = sm[kb + 2432], kl1 = sm[kb + 2432 + 4];
                mma8(sc[fn], qa[kk], kh0, kh1);
                mma8(sc[fn], ql,     kh0, kh1);
                mma8(sc[fn], qa[kk], kl0, kl1);
            }
        }

        // ---- rel-pos bias + mask (Q pre-scaled by 1/8) ----
        #pragma unroll
        for (int fn = 0; fn < 4; fn++) {
            int c = k0 + fn * 8 + 2 * tig;
            float cb0 = kbp[c], cb1 = kbp[c + 1];
            sc[fn][0] += rowb[0] + cb0;
            sc[fn][1] += rowb[0] + cb1;
            sc[fn][2] += rowb[1] + cb0;
            sc[fn][3] += rowb[1] + cb1;
        }

        // ---- online softmax; P-hi only ----
        #pragma unroll
        for (int rh = 0; rh < 2; rh++) {
            float tm = -1e30f;
            #pragma unroll
            for (int fn = 0; fn < 4; fn++)
                tm = fmaxf(tm, fmaxf(sc[fn][2 * rh], sc[fn][2 * rh + 1]));
            tm = fmaxf(tm, __shfl_xor_sync(0xffffffffu, tm, 1));
            tm = fmaxf(tm, __shfl_xor_sync(0xffffffffu, tm, 2));
            float mnew = fmaxf(fmaxf(mi[rh], tm), -1e20f);
            float psum = 0.0f;
            const int pro = (g + rh * 8) * 36;
            #pragma unroll
            for (int fn = 0; fn < 4; fn++) {
                float p0 = __expf(sc[fn][2 * rh] - mnew);
                float p1 = __expf(sc[fn][2 * rh + 1] - mnew);
                psum += p0 + p1;
                sm[psH + pro + fn * 8 + 2 * tig]     = f2tf(p0);
                sm[psH + pro + fn * 8 + 2 * tig + 1] = f2tf(p1);
            }
            psum += __shfl_xor_sync(0xffffffffu, psum, 1);
            psum += __shfl_xor_sync(0xffffffffu, psum, 2);
            float scale = __expf(mi[rh] - mnew);
            li[rh] = li[rh] * scale + psum;
            mi[rh] = mnew;
            #pragma unroll
            for (int nf = 0; nf < 8; nf++) {
                o[nf][2 * rh]     *= scale;
                o[nf][2 * rh + 1] *= scale;
            }
        }
        __syncwarp();

        // ---- O += P V (V-hi only) ----
        #pragma unroll
        for (int ks = 0; ks < 4; ks++) {
            unsigned pah[4];
            pah[0] = sm[psH + g * 36 + ks * 8 + tig];
            pah[1] = sm[psH + (g + 8) * 36 + ks * 8 + tig];
            pah[2] = sm[psH + g * 36 + ks * 8 + tig + 4];
            pah[3] = sm[psH + (g + 8) * 36 + ks * 8 + tig + 4];
            #pragma unroll
            for (int nf = 0; nf < 8; nf++) {
                unsigned vh0 = sm[sb + 4864 + (ks * 8 + tig) * 72 + nf * 8 + g];
                unsigned vh1 = sm[sb + 4864 + (ks * 8 + tig + 4) * 72 + nf * 8 + g];
                mma8(o[nf], pah, vh0, vh1);
            }
        }
        __syncwarp();
    }

    // ---- store partial (unnormalized O, m, l) to gmem ----
    const int qg = q0 + w * 16 + g;
    const size_t prow0 = (size_t)split * BHS + (size_t)bh * S + qg;
    const size_t prow1 = prow0 + 8;
    if (tig == 0) {
        *(float2*)&g_pml[prow0 * 2] = make_float2(mi[0], li[0]);
        *(float2*)&g_pml[prow1 * 2] = make_float2(mi[1], li[1]);
    }
    #pragma unroll
    for (int nf = 0; nf < 8; nf++) {
        int d = nf * 8 + 2 * tig;
        *(float2*)&g_po[prow0 * D + d] = make_float2(o[nf][0], o[nf][1]);
        *(float2*)&g_po[prow1 * D + d] = make_float2(o[nf][2], o[nf][3]);
    }
}

// ---------------------------------------------------------------------------
// Merge the two split-KV partials -> g_att (tf32 plane, [B,S,E] layout)
// ---------------------------------------------------------------------------
__global__ void attn_merge_kernel()
{
    int e = blockIdx.x * 256 + threadIdx.x;    // e < BHS*D/4
    int row = e >> 4;                          // (b*H+h)*S + q
    int dq = (e & 15) << 2;

    float2 ml0 = *(float2*)&g_pml[row * 2];
    float2 ml1 = *(float2*)&g_pml[(BHS + row) * 2];
    float mf = fmaxf(ml0.x, ml1.x);
    float a0 = __expf(ml0.x - mf), a1 = __expf(ml1.x - mf);
    float inv = 1.0f / (ml0.y * a0 + ml1.y * a1);
    a0 *= inv; a1 *= inv;

    float4 o0 = *(float4*)&g_po[(size_t)row * D + dq];
    float4 o1 = *(float4*)&g_po[(size_t)BHS * D + (size_t)row * D + dq];

    int q = row & (S - 1);
    int bh = row >> 11;            // row / S
    int b = bh / H, h = bh - b * H;
    uint4 r;
    r.x = f2tf(o0.x * a0 + o1.x * a1);
    r.y = f2tf(o0.y * a0 + o1.y * a1);
    r.z = f2tf(o0.z * a0 + o1.z * a1);
    r.w = f2tf(o0.w * a0 + o1.w * a1);
    *(uint4*)&g_att[(size_t)(b * S + q) * E + h * D + dq] = r;
}

// ---------------------------------------------------------------------------
extern "C" void kernel_launch(void* const* d_in, const int* in_sizes, int n_in,
                              void* d_out, int out_size)
{
    const float* query = (const float*)d_in[0];
    const float* key   = (const float*)d_in[1];
    const float* value = (const float*)d_in[2];
    const float* pb    = (const float*)d_in[3];
    const unsigned char* mask = (const unsigned char*)d_in[4];
    const float* wq_w = (const float*)d_in[5];
    const float* wq_b = (const float*)d_in[6];
    const float* wk_w = (const float*)d_in[7];
    const float* wk_b = (const float*)d_in[8];
    const float* wv_w = (const float*)d_in[9];
    const float* wv_b = (const float*)d_in[10];
    const float* fc_w = (const float*)d_in[11];
    const float* fc_b = (const float*)d_in[12];
    const float* coeff = (const float*)d_in[13];
    float* out = (float*)d_out;

    const int attn_smem = ATT_SMEM_WORDS * (int)sizeof(unsigned);  // 110,592 B
    const int qkv_smem  = QKV_SMEM_WORDS * (int)sizeof(unsigned);  // 61,440 B
    cudaFuncSetAttribute(attn_kernel,
                         cudaFuncAttributeMaxDynamicSharedMemorySize, attn_smem);
    cudaFuncSetAttribute(qkv_kernel,
                         cudaFuncAttributeMaxDynamicSharedMemorySize, qkv_smem);

    kbias_kernel<<<(B * H * S) / 256, 256>>>(mask, pb, coeff);
    split_all_kernel<<<SPLIT_TASKS / 256, 256>>>(query, key, value,
                                                 wq_w, wk_w, wv_w, fc_w);

    dim3 g1(E / 64, BSZ / 128, 3);    // (12, 32, 3)
    qkv_kernel<<<g1, 256, qkv_smem>>>(wq_b, wk_b, wv_b);

    dim3 g2(S / 128, 2, B * H);       // (16, 2, 24) = 768 CTAs
    attn_kernel<<<g2, 256, attn_smem>>>(pb, coeff);

    attn_merge_kernel<<<(BHS * D / 4) / 256, 256>>>();

    dim3 g3(E / 64, BSZ / 128);       // (12, 32)
    oproj_kernel<<<g3, 256>>>(fc_b, out);
}

// round 13
// speedup vs baseline: 1.9763x; 1.1396x over previous
#include <cuda_runtime.h>
#include <cuda_fp16.h>
#include <math.h>

#define B 2
#define S 2048
#define E 768
#define H 12
#define D 64
#define BSZ (B*S)
#define QKV_ELEMS (B*H*S*D)
#define XN (BSZ*E)
#define WN (E*E)
#define BHS (B*H*S)
#define NSPLIT 3

// Scratch (allocation-free rule: device globals)
__device__ unsigned g_Xhi[3*XN], g_Xlo[3*XN];
__device__ unsigned g_Whi[4*WN], g_Wlo[4*WN];
__device__ unsigned g_Qhi[QKV_ELEMS], g_Qlo[QKV_ELEMS];
__device__ unsigned g_Khi[QKV_ELEMS], g_Klo[QKV_ELEMS];
__device__ __half g_Vf16[QKV_ELEMS];      // V projection, f16, [B,H,S,D]
__device__ __half g_Vt[QKV_ELEMS];        // V transposed,  f16, [B,H,D,S]
__device__ unsigned g_att[XN];            // attention out, tf32-hi plane
__device__ float g_po[NSPLIT*QKV_ELEMS];  // split-KV partial O (unnormalized)
__device__ float g_pml[NSPLIT*BHS*2];     // split-KV partial (m, l)
__device__ float g_kbias[B*H*S];

// ---------------------------------------------------------------------------
__device__ __forceinline__ unsigned f2tf(float f) {
    unsigned u;
    asm("cvt.rna.tf32.f32 %0, %1;" : "=r"(u) : "f"(f));
    return u;
}
__device__ __forceinline__ void splt(float f, unsigned& hi, unsigned& lo) {
    hi = f2tf(f);
    lo = f2tf(f - __uint_as_float(hi));
}
__device__ __forceinline__ void mma8(float* c, const unsigned* a,
                                     unsigned b0, unsigned b1) {
    asm volatile(
        "mma.sync.aligned.m16n8k8.row.col.f32.tf32.tf32.f32 "
        "{%0,%1,%2,%3},{%4,%5,%6,%7},{%8,%9},{%0,%1,%2,%3};"
        : "+f"(c[0]), "+f"(c[1]), "+f"(c[2]), "+f"(c[3])
        : "r"(a[0]), "r"(a[1]), "r"(a[2]), "r"(a[3]), "r"(b0), "r"(b1));
}
__device__ __forceinline__ void mmaf16(float* c, const unsigned* a,
                                       unsigned b0, unsigned b1) {
    asm volatile(
        "mma.sync.aligned.m16n8k16.row.col.f32.f16.f16.f32 "
        "{%0,%1,%2,%3},{%4,%5,%6,%7},{%8,%9},{%0,%1,%2,%3};"
        : "+f"(c[0]), "+f"(c[1]), "+f"(c[2]), "+f"(c[3])
        : "r"(a[0]), "r"(a[1]), "r"(a[2]), "r"(a[3]), "r"(b0), "r"(b1));
}
__device__ __forceinline__ void cpa16(void* s, const void* g) {
    unsigned sa = (unsigned)__cvta_generic_to_shared(s);
    asm volatile("cp.async.cg.shared.global [%0], [%1], 16;"
                 :: "r"(sa), "l"(g));
}
#define CP_COMMIT() asm volatile("cp.async.commit_group;")
#define CP_WAIT0()  asm volatile("cp.async.wait_group 0;" ::: "memory")

// ---------------------------------------------------------------------------
// One-time hi/lo split of all 7 inputs in a single kernel.
// ---------------------------------------------------------------------------
#define XQ4 (XN/4)
#define WQ4 (WN/4)
#define SPLIT_TASKS (3*XQ4 + 4*WQ4)

__global__ void split_all_kernel(const float* __restrict__ q,
                                 const float* __restrict__ k,
                                 const float* __restrict__ v,
                                 const float* __restrict__ wq,
                                 const float* __restrict__ wk,
                                 const float* __restrict__ wv,
                                 const float* __restrict__ fc)
{
    int i = blockIdx.x * 256 + threadIdx.x;
    const float* src;
    unsigned *dh, *dl;
    int off;
    if (i < 3 * XQ4) {
        int z = i / XQ4;
        off = i - z * XQ4;
        src = (z == 0) ? q : (z == 1) ? k : v;
        dh = g_Xhi + (size_t)z * XN;
        dl = g_Xlo + (size_t)z * XN;
    } else {
        int j = i - 3 * XQ4;
        int z = j / WQ4;
        off = j - z * WQ4;
        src = (z == 0) ? wq : (z == 1) ? wk : (z == 2) ? wv : fc;
        dh = g_Whi + (size_t)z * WN;
        dl = g_Wlo + (size_t)z * WN;
    }
    float4 vv = ((const float4*)src)[off];
    uint4 hh, ll;
    splt(vv.x, hh.x, ll.x); splt(vv.y, hh.y, ll.y);
    splt(vv.z, hh.z, ll.z); splt(vv.w, hh.w, ll.w);
    ((uint4*)dh)[off] = hh;
    ((uint4*)dl)[off] = ll;
}

// ---------------------------------------------------------------------------
__global__ void kbias_kernel(const unsigned char* __restrict__ m,
                             const float* __restrict__ pb,
                             const float* __restrict__ coeff)
{
    __shared__ int cls[4];
    int tid = threadIdx.x;
    if (tid < 4) cls[tid] = 0;
    __syncthreads();
    for (int i = tid; i < BSZ; i += 256)
        if (m[i]) atomicAdd(&cls[i & 3], 1);
    __syncthreads();
    int mode = 0;
    if (cls[1] == 0 && cls[2] == 0 && cls[3] == 0) mode = 1;      // int32
    else if (cls[0] == 0 && cls[1] == 0)           mode = 2;      // float32

    int idx = blockIdx.x * 256 + tid;
    int bh = idx / S, k = idx - bh * S;
    int b = bh / H, h = bh - b * H;
    bool v;
    int mi = b * S + k;
    if (mode == 1)      v = ((const int*)m)[mi] != 0;
    else if (mode == 2) v = ((const float*)m)[mi] != 0.0f;
    else                v = m[mi] != 0;
    g_kbias[idx] = -coeff[h] * pb[mi] + (v ? 0.0f : -1e30f);
}

// ---------------------------------------------------------------------------
// V transpose: g_Vf16 [bh][s][d] -> g_Vt [bh][d][s]
// ---------------------------------------------------------------------------
__global__ void vtrans_kernel()
{
    __shared__ __half t[32][33];
    const int bh = blockIdx.z;
    const int s0 = blockIdx.x * 32, d0 = blockIdx.y * 32;
    const __half* src = g_Vf16 + (size_t)bh * S * D;
    __half* dst = g_Vt + (size_t)bh * D * S;
    const int tx = threadIdx.x, ty = threadIdx.y;
    #pragma unroll
    for (int i = ty; i < 32; i += 8)
        t[i][tx] = src[(size_t)(s0 + i) * D + d0 + tx];
    __syncthreads();
    #pragma unroll
    for (int i = ty; i < 32; i += 8)
        dst[(size_t)(d0 + i) * S + s0 + tx] = t[tx][i];
}

// ---------------------------------------------------------------------------
// QKV projection, 3xTF32 (2xTF32 for V), double-buffered cp.async pipeline.
// CTA 128x64, 8 warps (32x32 tiles). Q pre-scaled by 1/8 (exact).
// V output goes to f16 [B,H,S,D].
// ---------------------------------------------------------------------------
#define GA(s,p,r,c) (((s) * 2 + (p)) * 2560 + (r) * 20 + (c))
#define GB(s,p,r,c) (10240 + ((s) * 2 + (p)) * 1280 + (r) * 20 + (c))
#define QKV_SMEM_WORDS 15360   // 61,440 B

__global__ __launch_bounds__(256, 2)
void qkv_kernel(const float* __restrict__ bq, const float* __restrict__ bk,
                const float* __restrict__ bv)
{
    const int z = blockIdx.z;
    const unsigned* Xhi = g_Xhi + (size_t)z * XN;
    const unsigned* Xlo = g_Xlo + (size_t)z * XN;
    const unsigned* Whi = g_Whi + (size_t)z * WN;
    const unsigned* Wlo = g_Wlo + (size_t)z * WN;
    const float* bias = (z == 0) ? bq : (z == 1) ? bk : bv;
    unsigned* ohi = (z == 0) ? g_Qhi : g_Khi;
    unsigned* olo = (z == 0) ? g_Qlo : g_Klo;
    const bool rope = (z < 2);
    const bool vproj = (z == 2);

    extern __shared__ unsigned gsm[];

    const int tid = threadIdx.x;
    const int w = tid >> 5, wm = w >> 1, wn = w & 1;
    const int lane = tid & 31, g = lane >> 2, tig = lane & 3;
    const int m0 = blockIdx.y * 128, n0 = blockIdx.x * 64;
    const int ar0 = tid >> 2, ac = (tid & 3) << 2;

    float acc[2][4][4];
    #pragma unroll
    for (int a = 0; a < 2; a++)
        #pragma unroll
        for (int b2 = 0; b2 < 4; b2++)
            #pragma unroll
            for (int c = 0; c < 4; c++) acc[a][b2][c] = 0.0f;

    auto issueg = [&](int k0, int s) {
        #pragma unroll
        for (int t = 0; t < 2; t++) {
            int r = ar0 + t * 64;
            size_t gi = (size_t)(m0 + r) * E + k0 + ac;
            cpa16(&gsm[GA(s, 0, r, ac)], Xhi + gi);
            if (!vproj) cpa16(&gsm[GA(s, 1, r, ac)], Xlo + gi);
        }
        size_t gi = (size_t)(n0 + ar0) * E + k0 + ac;
        cpa16(&gsm[GB(s, 0, ar0, ac)], Whi + gi);
        cpa16(&gsm[GB(s, 1, ar0, ac)], Wlo + gi);
        CP_COMMIT();
    };

    issueg(0, 0);
    for (int it = 0; it < E / 16; it++) {
        CP_WAIT0();
        __syncthreads();
        if (it + 1 < E / 16) issueg((it + 1) * 16, (it + 1) & 1);
        const int s = it & 1;
        #pragma unroll
        for (int kk = 0; kk < 16; kk += 8) {
            unsigned afh[2][4], afl[2][4], bh0[4], bl0[4], bh1[4], bl1[4];
            #pragma unroll
            for (int fm = 0; fm < 2; fm++) {
                int rb = wm * 32 + fm * 16 + g;
                afh[fm][0] = gsm[GA(s, 0, rb,     kk + tig)];
                afh[fm][1] = gsm[GA(s, 0, rb + 8, kk + tig)];
                afh[fm][2] = gsm[GA(s, 0, rb,     kk + tig + 4)];
                afh[fm][3] = gsm[GA(s, 0, rb + 8, kk + tig + 4)];
                if (!vproj) {
                    afl[fm][0] = gsm[GA(s, 1, rb,     kk + tig)];
                    afl[fm][1] = gsm[GA(s, 1, rb + 8, kk + tig)];
                    afl[fm][2] = gsm[GA(s, 1, rb,     kk + tig + 4)];
                    afl[fm][3] = gsm[GA(s, 1, rb + 8, kk + tig + 4)];
                }
            }
            #pragma unroll
            for (int fn = 0; fn < 4; fn++) {
                int cb = wn * 32 + fn * 8 + g;
                bh0[fn] = gsm[GB(s, 0, cb, kk + tig)];
                bh1[fn] = gsm[GB(s, 0, cb, kk + tig + 4)];
                bl0[fn] = gsm[GB(s, 1, cb, kk + tig)];
                bl1[fn] = gsm[GB(s, 1, cb, kk + tig + 4)];
            }
            #pragma unroll
            for (int fm = 0; fm < 2; fm++)
                #pragma unroll
                for (int fn = 0; fn < 4; fn++) {
                    mma8(acc[fm][fn], afh[fm], bh0[fn], bh1[fn]);
                    if (!vproj) mma8(acc[fm][fn], afl[fm], bh0[fn], bh1[fn]);
                    mma8(acc[fm][fn], afh[fm], bl0[fn], bl1[fn]);
                }
        }
    }

    // epilogue: bias + RoPE (fp32) [+ 1/8 Q-scale, exact]
    #pragma unroll
    for (int fn = 0; fn < 4; fn++) {
        const int col = n0 + wn * 32 + fn * 8 + 2 * tig;
        const int h = col / D, d = col % D;
        const float b0v = bias[col], b1v = bias[col + 1];
        const float invf = rope
            ? exp2f(-(float)d * (13.287712379549449f / 64.0f)) : 0.0f;
        #pragma unroll
        for (int fm = 0; fm < 2; fm++) {
            const int row = m0 + wm * 32 + fm * 16 + g;
            #pragma unroll
            for (int half = 0; half < 2; half++) {
                const int r = row + half * 8;
                const int bb = r >> 11, sdx = r & 2047;
                float v0 = acc[fm][fn][half * 2 + 0] + b0v;
                float v1 = acc[fm][fn][half * 2 + 1] + b1v;
                if (rope) {
                    float sn, cs;
                    sincosf((float)sdx * invf, &sn, &cs);
                    float t0 = v0 * cs - v1 * sn;
                    v1 = v1 * cs + v0 * sn;
                    v0 = t0;
                }
                if (z == 0) { v0 *= 0.125f; v1 *= 0.125f; }   // exact
                const size_t idx = (((size_t)bb * H + h) * S + sdx) * D + d;
                if (vproj) {
                    *reinterpret_cast<__half2*>(&g_Vf16[idx]) =
                        __floats2half2_rn(v0, v1);
                } else {
                    unsigned h0, l0, h1, l1;
                    splt(v0, h0, l0); splt(v1, h1, l1);
                    *(uint2*)&ohi[idx] = make_uint2(h0, h1);
                    *(uint2*)&olo[idx] = make_uint2(l0, l1);
                }
            }
        }
    }
}

// ---------------------------------------------------------------------------
// Output projection: A = g_att (tf32-hi), W hi/lo. 3 CTAs/SM -> single wave.
// ---------------------------------------------------------------------------
#define OA(s,r,c)   ((s) * 2560 + (r) * 20 + (c))
#define OB(s,p,r,c) (5120 + ((s) * 2 + (p)) * 1280 + (r) * 20 + (c))

__global__ __launch_bounds__(256, 3)
void oproj_kernel(const float* __restrict__ bias, float* __restrict__ out)
{
    const unsigned* Whi = g_Whi + (size_t)3 * WN;
    const unsigned* Wlo = g_Wlo + (size_t)3 * WN;

    __shared__ unsigned osm[10240];   // 40,960 B

    const int tid = threadIdx.x;
    const int w = tid >> 5, wm = w >> 1, wn = w & 1;
    const int lane = tid & 31, g = lane >> 2, tig = lane & 3;
    const int m0 = blockIdx.y * 128, n0 = blockIdx.x * 64;
    const int ar0 = tid >> 2, ac = (tid & 3) << 2;

    float acc[2][4][4];
    #pragma unroll
    for (int a = 0; a < 2; a++)
        #pragma unroll
        for (int b2 = 0; b2 < 4; b2++)
            #pragma unroll
            for (int c = 0; c < 4; c++) acc[a][b2][c] = 0.0f;

    auto issueg = [&](int k0, int s) {
        #pragma unroll
        for (int t = 0; t < 2; t++) {
            int r = ar0 + t * 64;
            cpa16(&osm[OA(s, r, ac)], g_att + (size_t)(m0 + r) * E + k0 + ac);
        }
        size_t gi = (size_t)(n0 + ar0) * E + k0 + ac;
        cpa16(&osm[OB(s, 0, ar0, ac)], Whi + gi);
        cpa16(&osm[OB(s, 1, ar0, ac)], Wlo + gi);
        CP_COMMIT();
    };

    issueg(0, 0);
    for (int it = 0; it < E / 16; it++) {
        CP_WAIT0();
        __syncthreads();
        if (it + 1 < E / 16) issueg((it + 1) * 16, (it + 1) & 1);
        const int s = it & 1;
        #pragma unroll
        for (int kk = 0; kk < 16; kk += 8) {
            unsigned afh[2][4], bh0[4], bl0[4], bh1[4], bl1[4];
            #pragma unroll
            for (int fm = 0; fm < 2; fm++) {
                int rb = wm * 32 + fm * 16 + g;
                afh[fm][0] = osm[OA(s, rb,     kk + tig)];
                afh[fm][1] = osm[OA(s, rb + 8, kk + tig)];
                afh[fm][2] = osm[OA(s, rb,     kk + tig + 4)];
                afh[fm][3] = osm[OA(s, rb + 8, kk + tig + 4)];
            }
            #pragma unroll
            for (int fn = 0; fn < 4; fn++) {
                int cb = wn * 32 + fn * 8 + g;
                bh0[fn] = osm[OB(s, 0, cb, kk + tig)];
                bh1[fn] = osm[OB(s, 0, cb, kk + tig + 4)];
                bl0[fn] = osm[OB(s, 1, cb, kk + tig)];
                bl1[fn] = osm[OB(s, 1, cb, kk + tig + 4)];
            }
            #pragma unroll
            for (int fm = 0; fm < 2; fm++)
                #pragma unroll
                for (int fn = 0; fn < 4; fn++) {
                    mma8(acc[fm][fn], afh[fm], bh0[fn], bh1[fn]);
                    mma8(acc[fm][fn], afh[fm], bl0[fn], bl1[fn]);
                }
        }
    }

    #pragma unroll
    for (int fn = 0; fn < 4; fn++) {
        const int col = n0 + wn * 32 + fn * 8 + 2 * tig;
        const float b0v = bias[col], b1v = bias[col + 1];
        #pragma unroll
        for (int fm = 0; fm < 2; fm++) {
            const int row = m0 + wm * 32 + fm * 16 + g;
            #pragma unroll
            for (int half = 0; half < 2; half++) {
                const int r = row + half * 8;
                *(float2*)&out[(size_t)r * E + col] =
                    make_float2(acc[fm][fn][half * 2 + 0] + b0v,
                                acc[fm][fn][half * 2 + 1] + b1v);
            }
        }
    }
}

// ---------------------------------------------------------------------------
// Flash attention, split-KV x3. CTA = 128 q-rows x ~683-key range.
// Warp = 16 q x 32 k. 3xTF32 scores; f16 PV with register-resident P
// (m16n8 f32 accum layout == m16n8k16 f16 A layout, packed half2).
// smem (words): stage s @ s*6144: KH[32][76], KL @+2432, VT[64][20] @+4864.
//   QLO @12288 (128x68). Total 20992 words = 83,968 B.
// ---------------------------------------------------------------------------
#define STGW 6144
#define VT_OFF 4864
#define QL_OFF 12288
#define QLP 68
#define ATT_SMEM_WORDS 20992

__global__ __launch_bounds__(256, 2)
void attn_kernel(const float* __restrict__ pb, const float* __restrict__ coeff)
{
    extern __shared__ unsigned sm[];

    const int tid = threadIdx.x;
    const int w = tid >> 5, lane = tid & 31, g = lane >> 2, tig = lane & 3;
    const int q0 = blockIdx.x * 128, split = blockIdx.y, bh = blockIdx.z;
    const int b = bh / H, h = bh - b * H;

    const size_t hbase = (size_t)bh * S * D;
    const float* kbp = g_kbias + (size_t)bh * S;

    // ---- prologue: stage Q-hi (stage area, pitch 76) + Q-lo (QLO) ----
    #pragma unroll
    for (int t = 0; t < 8; t++) {
        int i = tid + t * 256;
        int r = i >> 4, c4 = (i & 15) << 2;
        size_t gi = hbase + (size_t)(q0 + r) * D + c4;
        cpa16(&sm[r * 76 + c4], g_Qhi + gi);
        cpa16(&sm[QL_OFF + r * QLP + c4], g_Qlo + gi);
    }
    CP_COMMIT();
    CP_WAIT0();
    __syncthreads();

    unsigned qa[8][4];
    {
        const int qb = (w * 16 + g) * 76;
        #pragma unroll
        for (int kk = 0; kk < 8; kk++) {
            qa[kk][0] = sm[qb + kk * 8 + tig];
            qa[kk][1] = sm[qb + 8 * 76 + kk * 8 + tig];
            qa[kk][2] = sm[qb + kk * 8 + tig + 4];
            qa[kk][3] = sm[qb + 8 * 76 + kk * 8 + tig + 4];
        }
    }
    __syncthreads();

    const float coeff_h = coeff[h];
    float rowb[2];
    rowb[0] = coeff_h * pb[b * S + q0 + w * 16 + g];
    rowb[1] = coeff_h * pb[b * S + q0 + w * 16 + g + 8];

    float mi[2] = {-1e30f, -1e30f}, li[2] = {0.0f, 0.0f};
    float o[8][4];
    #pragma unroll
    for (int nf = 0; nf < 8; nf++)
        #pragma unroll
        for (int c = 0; c < 4; c++) o[nf][c] = 0.0f;

    const int qlb = QL_OFF + (w * 16 + g) * QLP;

    auto issuet = [&](int kt, int sb) {
        const int k0 = kt * 32;
        #pragma unroll
        for (int t = 0; t < 2; t++) {
            int i = tid + t * 256;
            int r = i >> 4, c4 = (i & 15) << 2;
            size_t gi = hbase + (size_t)(k0 + r) * D + c4;
            cpa16(&sm[sb + r * 76 + c4], g_Khi + gi);
            cpa16(&sm[sb + 2432 + r * 76 + c4], g_Klo + gi);
        }
        if (tid < 256) {
            int r = tid >> 2, c = (tid & 3) * 4;   // V row d=r, words
            cpa16(&sm[sb + VT_OFF + r * 20 + c],
                  g_Vt + ((size_t)bh * D + r) * S + k0 + c * 2);
        }
        CP_COMMIT();
    };

    const int kt0 = (64 * split) / NSPLIT;
    const int kt1 = (64 * (split + 1)) / NSPLIT;

    issuet(kt0, 0);
    for (int it = kt0; it < kt1; it++) {
        const int k0 = it * 32;
        CP_WAIT0();
        __syncthreads();
        if (it + 1 < kt1) issuet(it + 1, ((it - kt0 + 1) & 1) * STGW);
        const int sb = ((it - kt0) & 1) * STGW;

        // ---- S = Q K^T, 3xTF32 ----
        float sc[4][4];
        #pragma unroll
        for (int fn = 0; fn < 4; fn++)
            #pragma unroll
            for (int c = 0; c < 4; c++) sc[fn][c] = 0.0f;

        #pragma unroll
        for (int kk = 0; kk < 8; kk++) {
            unsigned ql[4];
            ql[0] = sm[qlb + kk * 8 + tig];
            ql[1] = sm[qlb + 8 * QLP + kk * 8 + tig];
            ql[2] = sm[qlb + kk * 8 + tig + 4];
            ql[3] = sm[qlb + 8 * QLP + kk * 8 + tig + 4];
            #pragma unroll
            for (int fn = 0; fn < 4; fn++) {
                int kb = sb + (fn * 8 + g) * 76 + kk * 8 + tig;
                unsigned kh0 = sm[kb], kh1 = sm[kb + 4];
                unsigned kl0 = sm[kb + 2432], kl1 = sm[kb + 2432 + 4];
                mma8(sc[fn], qa[kk], kh0, kh1);
                mma8(sc[fn], ql,     kh0, kh1);
                mma8(sc[fn], qa[kk], kl0, kl1);
            }
        }

        // ---- rel-pos bias + mask (Q pre-scaled by 1/8) ----
        #pragma unroll
        for (int fn = 0; fn < 4; fn++) {
            int c = k0 + fn * 8 + 2 * tig;
            float cb0 = kbp[c], cb1 = kbp[c + 1];
            sc[fn][0] += rowb[0] + cb0;
            sc[fn][1] += rowb[0] + cb1;
            sc[fn][2] += rowb[1] + cb0;
            sc[fn][3] += rowb[1] + cb1;
        }

        // ---- online softmax; P packed to half2 in registers ----
        unsigned ph2[4][2];
        #pragma unroll
        for (int rh = 0; rh < 2; rh++) {
            float tm = -1e30f;
            #pragma unroll
            for (int fn = 0; fn < 4; fn++)
                tm = fmaxf(tm, fmaxf(sc[fn][2 * rh], sc[fn][2 * rh + 1]));
            tm = fmaxf(tm, __shfl_xor_sync(0xffffffffu, tm, 1));
            tm = fmaxf(tm, __shfl_xor_sync(0xffffffffu, tm, 2));
            float mnew = fmaxf(fmaxf(mi[rh], tm), -1e20f);
            float psum = 0.0f;
            #pragma unroll
            for (int fn = 0; fn < 4; fn++) {
                float p0 = __expf(sc[fn][2 * rh] - mnew);
                float p1 = __expf(sc[fn][2 * rh + 1] - mnew);
                psum += p0 + p1;
                __half2 hp = __floats2half2_rn(p0, p1);
                ph2[fn][rh] = *reinterpret_cast<unsigned*>(&hp);
            }
            psum += __shfl_xor_sync(0xffffffffu, psum, 1);
            psum += __shfl_xor_sync(0xffffffffu, psum, 2);
            float scale = __expf(mi[rh] - mnew);
            li[rh] = li[rh] * scale + psum;
            mi[rh] = mnew;
            #pragma unroll
            for (int nf = 0; nf < 8; nf++) {
                o[nf][2 * rh]     *= scale;
                o[nf][2 * rh + 1] *= scale;
            }
        }

        // ---- O += P V (f16 mma, P from registers, V transposed) ----
        #pragma unroll
        for (int j = 0; j < 2; j++) {
            unsigned pa[4] = {ph2[2 * j][0], ph2[2 * j][1],
                              ph2[2 * j + 1][0], ph2[2 * j + 1][1]};
            #pragma unroll
            for (int nf = 0; nf < 8; nf++) {
                int vb = sb + VT_OFF + (nf * 8 + g) * 20 + j * 8 + tig;
                mmaf16(o[nf], pa, sm[vb], sm[vb + 4]);
            }
        }
    }

    // ---- store partial (unnormalized O, m, l) to gmem ----
    const int qg = q0 + w * 16 + g;
    const size_t prow0 = (size_t)split * BHS + (size_t)bh * S + qg;
    const size_t prow1 = prow0 + 8;
    if (tig == 0) {
        *(float2*)&g_pml[prow0 * 2] = make_float2(mi[0], li[0]);
        *(float2*)&g_pml[prow1 * 2] = make_float2(mi[1], li[1]);
    }
    #pragma unroll
    for (int nf = 0; nf < 8; nf++) {
        int d = nf * 8 + 2 * tig;
        *(float2*)&g_po[prow0 * D + d] = make_float2(o[nf][0], o[nf][1]);
        *(float2*)&g_po[prow1 * D + d] = make_float2(o[nf][2], o[nf][3]);
    }
}

// ---------------------------------------------------------------------------
// Merge the three split-KV partials -> g_att (tf32 plane, [B,S,E] layout)
// ---------------------------------------------------------------------------
__global__ void attn_merge_kernel()
{
    int e = blockIdx.x * 256 + threadIdx.x;    // e < BHS*D/4
    int row = e >> 4;                          // (b*H+h)*S + q
    int dq = (e & 15) << 2;

    float2 ml0 = *(float2*)&g_pml[row * 2];
    float2 ml1 = *(float2*)&g_pml[(BHS + row) * 2];
    float2 ml2 = *(float2*)&g_pml[(2 * BHS + row) * 2];
    float mf = fmaxf(ml0.x, fmaxf(ml1.x, ml2.x));
    float a0 = __expf(ml0.x - mf), a1 = __expf(ml1.x - mf),
          a2 = __expf(ml2.x - mf);
    float inv = 1.0f / (ml0.y * a0 + ml1.y * a1 + ml2.y * a2);
    a0 *= inv; a1 *= inv; a2 *= inv;

    float4 o0 = *(float4*)&g_po[(size_t)row * D + dq];
    float4 o1 = *(float4*)&g_po[(size_t)BHS * D + (size_t)row * D + dq];
    float4 o2 = *(float4*)&g_po[2 * (size_t)BHS * D + (size_t)row * D + dq];

    int q = row & (S - 1);
    int bh = row >> 11;
    int b = bh / H, h = bh - b * H;
    uint4 r;
    r.x = f2tf(o0.x * a0 + o1.x * a1 + o2.x * a2);
    r.y = f2tf(o0.y * a0 + o1.y * a1 + o2.y * a2);
    r.z = f2tf(o0.z * a0 + o1.z * a1 + o2.z * a2);
    r.w = f2tf(o0.w * a0 + o1.w * a1 + o2.w * a2);
    *(uint4*)&g_att[(size_t)(b * S + q) * E + h * D + dq] = r;
}

// ---------------------------------------------------------------------------
extern "C" void kernel_launch(void* const* d_in, const int* in_sizes, int n_in,
                              void* d_out, int out_size)
{
    const float* query = (const float*)d_in[0];
    const float* key   = (const float*)d_in[1];
    const float* value = (const float*)d_in[2];
    const float* pb    = (const float*)d_in[3];
    const unsigned char* mask = (const unsigned char*)d_in[4];
    const float* wq_w = (const float*)d_in[5];
    const float* wq_b = (const float*)d_in[6];
    const float* wk_w = (const float*)d_in[7];
    const float* wk_b = (const float*)d_in[8];
    const float* wv_w = (const float*)d_in[9];
    const float* wv_b = (const float*)d_in[10];
    const float* fc_w = (const float*)d_in[11];
    const float* fc_b = (const float*)d_in[12];
    const float* coeff = (const float*)d_in[13];
    float* out = (float*)d_out;

    const int attn_smem = ATT_SMEM_WORDS * (int)sizeof(unsigned);  // 83,968 B
    const int qkv_smem  = QKV_SMEM_WORDS * (int)sizeof(unsigned);  // 61,440 B
    cudaFuncSetAttribute(attn_kernel,
                         cudaFuncAttributeMaxDynamicSharedMemorySize, attn_smem);
    cudaFuncSetAttribute(qkv_kernel,
                         cudaFuncAttributeMaxDynamicSharedMemorySize, qkv_smem);

    kbias_kernel<<<(B * H * S) / 256, 256>>>(mask, pb, coeff);
    split_all_kernel<<<SPLIT_TASKS / 256, 256>>>(query, key, value,
                                                 wq_w, wk_w, wv_w, fc_w);

    dim3 g1(E / 64, BSZ / 128, 3);    // (12, 32, 3)
    qkv_kernel<<<g1, 256, qkv_smem>>>(wq_b, wk_b, wv_b);

    dim3 gt(S / 32, D / 32, B * H);   // (64, 2, 24)
    vtrans_kernel<<<gt, dim3(32, 8)>>>();

    dim3 g2(S / 128, NSPLIT, B * H);  // (16, 3, 24) = 1152 CTAs
    attn_kernel<<<g2, 256, attn_smem>>>(pb, coeff);

    attn_merge_kernel<<<(BHS * D / 4) / 256, 256>>>();

    dim3 g3(E / 64, BSZ / 128);       // (12, 32)
    oproj_kernel<<<g3, 256>>>(fc_b, out);
}

// round 14
// speedup vs baseline: 2.2622x; 1.1447x over previous
#include <cuda_runtime.h>
#include <cuda_fp16.h>
#include <math.h>

#define B 2
#define S 2048
#define E 768
#define H 12
#define D 64
#define BSZ (B*S)
#define QKV_ELEMS (B*H*S*D)
#define XN (BSZ*E)
#define WN (E*E)
#define BHS (B*H*S)
#define NSPLIT 3

// Scratch (allocation-free rule: device globals)
__device__ unsigned g_Xhi[3*XN], g_Xlo[3*XN];
__device__ unsigned g_Whi[4*WN], g_Wlo[4*WN];
__device__ unsigned g_Qh2[QKV_ELEMS/2], g_Ql2[QKV_ELEMS/2];  // Q f16 hi/lo, half2 words
__device__ unsigned g_Kh2[QKV_ELEMS/2], g_Kl2[QKV_ELEMS/2];  // K f16 hi/lo
__device__ __half g_Vf16[QKV_ELEMS];      // V projection, f16, [B,H,S,D]
__device__ __half g_Vt[QKV_ELEMS];        // V transposed,  f16, [B,H,D,S]
__device__ unsigned g_att[XN];            // attention out, tf32-hi plane
__device__ float g_po[NSPLIT*QKV_ELEMS];  // split-KV partial O (unnormalized)
__device__ float g_pml[NSPLIT*BHS*2];     // split-KV partial (m, l)
__device__ float g_kbias[B*H*S];

// ---------------------------------------------------------------------------
__device__ __forceinline__ unsigned f2tf(float f) {
    unsigned u;
    asm("cvt.rna.tf32.f32 %0, %1;" : "=r"(u) : "f"(f));
    return u;
}
__device__ __forceinline__ void splt(float f, unsigned& hi, unsigned& lo) {
    hi = f2tf(f);
    lo = f2tf(f - __uint_as_float(hi));
}
// f16 hi/lo split of a pair -> packed half2 words
__device__ __forceinline__ void splth2(float v0, float v1,
                                       unsigned& hw, unsigned& lw) {
    __half h0 = __float2half_rn(v0);
    __half l0 = __float2half_rn(v0 - __half2float(h0));
    __half h1 = __float2half_rn(v1);
    __half l1 = __float2half_rn(v1 - __half2float(h1));
    __half2 hp = __halves2half2(h0, h1);
    __half2 lp = __halves2half2(l0, l1);
    hw = *reinterpret_cast<unsigned*>(&hp);
    lw = *reinterpret_cast<unsigned*>(&lp);
}
__device__ __forceinline__ void mma8(float* c, const unsigned* a,
                                     unsigned b0, unsigned b1) {
    asm volatile(
        "mma.sync.aligned.m16n8k8.row.col.f32.tf32.tf32.f32 "
        "{%0,%1,%2,%3},{%4,%5,%6,%7},{%8,%9},{%0,%1,%2,%3};"
        : "+f"(c[0]), "+f"(c[1]), "+f"(c[2]), "+f"(c[3])
        : "r"(a[0]), "r"(a[1]), "r"(a[2]), "r"(a[3]), "r"(b0), "r"(b1));
}
__device__ __forceinline__ void mmaf16(float* c, const unsigned* a,
                                       unsigned b0, unsigned b1) {
    asm volatile(
        "mma.sync.aligned.m16n8k16.row.col.f32.f16.f16.f32 "
        "{%0,%1,%2,%3},{%4,%5,%6,%7},{%8,%9},{%0,%1,%2,%3};"
        : "+f"(c[0]), "+f"(c[1]), "+f"(c[2]), "+f"(c[3])
        : "r"(a[0]), "r"(a[1]), "r"(a[2]), "r"(a[3]), "r"(b0), "r"(b1));
}
__device__ __forceinline__ void cpa16(void* s, const void* g) {
    unsigned sa = (unsigned)__cvta_generic_to_shared(s);
    asm volatile("cp.async.cg.shared.global [%0], [%1], 16;"
                 :: "r"(sa), "l"(g));
}
#define CP_COMMIT() asm volatile("cp.async.commit_group;")
#define CP_WAIT0()  asm volatile("cp.async.wait_group 0;" ::: "memory")

// ---------------------------------------------------------------------------
// One-time hi/lo split of all 7 inputs in a single kernel.
// ---------------------------------------------------------------------------
#define XQ4 (XN/4)
#define WQ4 (WN/4)
#define SPLIT_TASKS (3*XQ4 + 4*WQ4)

__global__ void split_all_kernel(const float* __restrict__ q,
                                 const float* __restrict__ k,
                                 const float* __restrict__ v,
                                 const float* __restrict__ wq,
                                 const float* __restrict__ wk,
                                 const float* __restrict__ wv,
                                 const float* __restrict__ fc)
{
    int i = blockIdx.x * 256 + threadIdx.x;
    const float* src;
    unsigned *dh, *dl;
    int off;
    if (i < 3 * XQ4) {
        int z = i / XQ4;
        off = i - z * XQ4;
        src = (z == 0) ? q : (z == 1) ? k : v;
        dh = g_Xhi + (size_t)z * XN;
        dl = g_Xlo + (size_t)z * XN;
    } else {
        int j = i - 3 * XQ4;
        int z = j / WQ4;
        off = j - z * WQ4;
        src = (z == 0) ? wq : (z == 1) ? wk : (z == 2) ? wv : fc;
        dh = g_Whi + (size_t)z * WN;
        dl = g_Wlo + (size_t)z * WN;
    }
    float4 vv = ((const float4*)src)[off];
    uint4 hh, ll;
    splt(vv.x, hh.x, ll.x); splt(vv.y, hh.y, ll.y);
    splt(vv.z, hh.z, ll.z); splt(vv.w, hh.w, ll.w);
    ((uint4*)dh)[off] = hh;
    ((uint4*)dl)[off] = ll;
}

// ---------------------------------------------------------------------------
__global__ void kbias_kernel(const unsigned char* __restrict__ m,
                             const float* __restrict__ pb,
                             const float* __restrict__ coeff)
{
    __shared__ int cls[4];
    int tid = threadIdx.x;
    if (tid < 4) cls[tid] = 0;
    __syncthreads();
    for (int i = tid; i < BSZ; i += 256)
        if (m[i]) atomicAdd(&cls[i & 3], 1);
    __syncthreads();
    int mode = 0;
    if (cls[1] == 0 && cls[2] == 0 && cls[3] == 0) mode = 1;      // int32
    else if (cls[0] == 0 && cls[1] == 0)           mode = 2;      // float32

    int idx = blockIdx.x * 256 + tid;
    int bh = idx / S, k = idx - bh * S;
    int b = bh / H, h = bh - b * H;
    bool v;
    int mi = b * S + k;
    if (mode == 1)      v = ((const int*)m)[mi] != 0;
    else if (mode == 2) v = ((const float*)m)[mi] != 0.0f;
    else                v = m[mi] != 0;
    g_kbias[idx] = -coeff[h] * pb[mi] + (v ? 0.0f : -1e30f);
}

// ---------------------------------------------------------------------------
// V transpose: g_Vf16 [bh][s][d] -> g_Vt [bh][d][s]
// ---------------------------------------------------------------------------
__global__ void vtrans_kernel()
{
    __shared__ __half t[32][33];
    const int bh = blockIdx.z;
    const int s0 = blockIdx.x * 32, d0 = blockIdx.y * 32;
    const __half* src = g_Vf16 + (size_t)bh * S * D;
    __half* dst = g_Vt + (size_t)bh * D * S;
    const int tx = threadIdx.x, ty = threadIdx.y;
    #pragma unroll
    for (int i = ty; i < 32; i += 8)
        t[i][tx] = src[(size_t)(s0 + i) * D + d0 + tx];
    __syncthreads();
    #pragma unroll
    for (int i = ty; i < 32; i += 8)
        dst[(size_t)(d0 + i) * S + s0 + tx] = t[tx][i];
}

// ---------------------------------------------------------------------------
// QKV projection, 3xTF32 (2xTF32 for V), double-buffered cp.async pipeline.
// CTA 128x64, 8 warps (32x32 tiles). Q pre-scaled by 1/8 (exact).
// Q/K outputs -> f16 hi/lo half2 planes; V -> f16.
// ---------------------------------------------------------------------------
#define GA(s,p,r,c) (((s) * 2 + (p)) * 2560 + (r) * 20 + (c))
#define GB(s,p,r,c) (10240 + ((s) * 2 + (p)) * 1280 + (r) * 20 + (c))
#define QKV_SMEM_WORDS 15360   // 61,440 B

__global__ __launch_bounds__(256, 2)
void qkv_kernel(const float* __restrict__ bq, const float* __restrict__ bk,
                const float* __restrict__ bv)
{
    const int z = blockIdx.z;
    const unsigned* Xhi = g_Xhi + (size_t)z * XN;
    const unsigned* Xlo = g_Xlo + (size_t)z * XN;
    const unsigned* Whi = g_Whi + (size_t)z * WN;
    const unsigned* Wlo = g_Wlo + (size_t)z * WN;
    const float* bias = (z == 0) ? bq : (z == 1) ? bk : bv;
    unsigned* oh2 = (z == 0) ? g_Qh2 : g_Kh2;
    unsigned* ol2 = (z == 0) ? g_Ql2 : g_Kl2;
    const bool rope = (z < 2);
    const bool vproj = (z == 2);

    extern __shared__ unsigned gsm[];

    const int tid = threadIdx.x;
    const int w = tid >> 5, wm = w >> 1, wn = w & 1;
    const int lane = tid & 31, g = lane >> 2, tig = lane & 3;
    const int m0 = blockIdx.y * 128, n0 = blockIdx.x * 64;
    const int ar0 = tid >> 2, ac = (tid & 3) << 2;

    float acc[2][4][4];
    #pragma unroll
    for (int a = 0; a < 2; a++)
        #pragma unroll
        for (int b2 = 0; b2 < 4; b2++)
            #pragma unroll
            for (int c = 0; c < 4; c++) acc[a][b2][c] = 0.0f;

    auto issueg = [&](int k0, int s) {
        #pragma unroll
        for (int t = 0; t < 2; t++) {
            int r = ar0 + t * 64;
            size_t gi = (size_t)(m0 + r) * E + k0 + ac;
            cpa16(&gsm[GA(s, 0, r, ac)], Xhi + gi);
            if (!vproj) cpa16(&gsm[GA(s, 1, r, ac)], Xlo + gi);
        }
        size_t gi = (size_t)(n0 + ar0) * E + k0 + ac;
        cpa16(&gsm[GB(s, 0, ar0, ac)], Whi + gi);
        cpa16(&gsm[GB(s, 1, ar0, ac)], Wlo + gi);
        CP_COMMIT();
    };

    issueg(0, 0);
    for (int it = 0; it < E / 16; it++) {
        CP_WAIT0();
        __syncthreads();
        if (it + 1 < E / 16) issueg((it + 1) * 16, (it + 1) & 1);
        const int s = it & 1;
        #pragma unroll
        for (int kk = 0; kk < 16; kk += 8) {
            unsigned afh[2][4], afl[2][4], bh0[4], bl0[4], bh1[4], bl1[4];
            #pragma unroll
            for (int fm = 0; fm < 2; fm++) {
                int rb = wm * 32 + fm * 16 + g;
                afh[fm][0] = gsm[GA(s, 0, rb,     kk + tig)];
                afh[fm][1] = gsm[GA(s, 0, rb + 8, kk + tig)];
                afh[fm][2] = gsm[GA(s, 0, rb,     kk + tig + 4)];
                afh[fm][3] = gsm[GA(s, 0, rb + 8, kk + tig + 4)];
                if (!vproj) {
                    afl[fm][0] = gsm[GA(s, 1, rb,     kk + tig)];
                    afl[fm][1] = gsm[GA(s, 1, rb + 8, kk + tig)];
                    afl[fm][2] = gsm[GA(s, 1, rb,     kk + tig + 4)];
                    afl[fm][3] = gsm[GA(s, 1, rb + 8, kk + tig + 4)];
                }
            }
            #pragma unroll
            for (int fn = 0; fn < 4; fn++) {
                int cb = wn * 32 + fn * 8 + g;
                bh0[fn] = gsm[GB(s, 0, cb, kk + tig)];
                bh1[fn] = gsm[GB(s, 0, cb, kk + tig + 4)];
                bl0[fn] = gsm[GB(s, 1, cb, kk + tig)];
                bl1[fn] = gsm[GB(s, 1, cb, kk + tig + 4)];
            }
            #pragma unroll
            for (int fm = 0; fm < 2; fm++)
                #pragma unroll
                for (int fn = 0; fn < 4; fn++) {
                    mma8(acc[fm][fn], afh[fm], bh0[fn], bh1[fn]);
                    if (!vproj) mma8(acc[fm][fn], afl[fm], bh0[fn], bh1[fn]);
                    mma8(acc[fm][fn], afh[fm], bl0[fn], bl1[fn]);
                }
        }
    }

    // epilogue: bias + RoPE (fp32) [+ 1/8 Q-scale, exact]
    #pragma unroll
    for (int fn = 0; fn < 4; fn++) {
        const int col = n0 + wn * 32 + fn * 8 + 2 * tig;
        const int h = col / D, d = col % D;
        const float b0v = bias[col], b1v = bias[col + 1];
        const float invf = rope
            ? exp2f(-(float)d * (13.287712379549449f / 64.0f)) : 0.0f;
        #pragma unroll
        for (int fm = 0; fm < 2; fm++) {
            const int row = m0 + wm * 32 + fm * 16 + g;
            #pragma unroll
            for (int half = 0; half < 2; half++) {
                const int r = row + half * 8;
                const int bb = r >> 11, sdx = r & 2047;
                float v0 = acc[fm][fn][half * 2 + 0] + b0v;
                float v1 = acc[fm][fn][half * 2 + 1] + b1v;
                if (rope) {
                    float sn, cs;
                    sincosf((float)sdx * invf, &sn, &cs);
                    float t0 = v0 * cs - v1 * sn;
                    v1 = v1 * cs + v0 * sn;
                    v0 = t0;
                }
                if (z == 0) { v0 *= 0.125f; v1 *= 0.125f; }   // exact
                const size_t idx = (((size_t)bb * H + h) * S + sdx) * D + d;
                if (vproj) {
                    *reinterpret_cast<__half2*>(&g_Vf16[idx]) =
                        __floats2half2_rn(v0, v1);
                } else {
                    unsigned hw, lw;
                    splth2(v0, v1, hw, lw);
                    oh2[idx >> 1] = hw;
                    ol2[idx >> 1] = lw;
                }
            }
        }
    }
}

// ---------------------------------------------------------------------------
// Output projection: A = g_att (tf32-hi), W hi/lo. 3 CTAs/SM -> single wave.
// ---------------------------------------------------------------------------
#define OA(s,r,c)   ((s) * 2560 + (r) * 20 + (c))
#define OB(s,p,r,c) (5120 + ((s) * 2 + (p)) * 1280 + (r) * 20 + (c))

__global__ __launch_bounds__(256, 3)
void oproj_kernel(const float* __restrict__ bias, float* __restrict__ out)
{
    const unsigned* Whi = g_Whi + (size_t)3 * WN;
    const unsigned* Wlo = g_Wlo + (size_t)3 * WN;

    __shared__ unsigned osm[10240];   // 40,960 B

    const int tid = threadIdx.x;
    const int w = tid >> 5, wm = w >> 1, wn = w & 1;
    const int lane = tid & 31, g = lane >> 2, tig = lane & 3;
    const int m0 = blockIdx.y * 128, n0 = blockIdx.x * 64;
    const int ar0 = tid >> 2, ac = (tid & 3) << 2;

    float acc[2][4][4];
    #pragma unroll
    for (int a = 0; a < 2; a++)
        #pragma unroll
        for (int b2 = 0; b2 < 4; b2++)
            #pragma unroll
            for (int c = 0; c < 4; c++) acc[a][b2][c] = 0.0f;

    auto issueg = [&](int k0, int s) {
        #pragma unroll
        for (int t = 0; t < 2; t++) {
            int r = ar0 + t * 64;
            cpa16(&osm[OA(s, r, ac)], g_att + (size_t)(m0 + r) * E + k0 + ac);
        }
        size_t gi = (size_t)(n0 + ar0) * E + k0 + ac;
        cpa16(&osm[OB(s, 0, ar0, ac)], Whi + gi);
        cpa16(&osm[OB(s, 1, ar0, ac)], Wlo + gi);
        CP_COMMIT();
    };

    issueg(0, 0);
    for (int it = 0; it < E / 16; it++) {
        CP_WAIT0();
        __syncthreads();
        if (it + 1 < E / 16) issueg((it + 1) * 16, (it + 1) & 1);
        const int s = it & 1;
        #pragma unroll
        for (int kk = 0; kk < 16; kk += 8) {
            unsigned afh[2][4], bh0[4], bl0[4], bh1[4], bl1[4];
            #pragma unroll
            for (int fm = 0; fm < 2; fm++) {
                int rb = wm * 32 + fm * 16 + g;
                afh[fm][0] = osm[OA(s, rb,     kk + tig)];
                afh[fm][1] = osm[OA(s, rb + 8, kk + tig)];
                afh[fm][2] = osm[OA(s, rb,     kk + tig + 4)];
                afh[fm][3] = osm[OA(s, rb + 8, kk + tig + 4)];
            }
            #pragma unroll
            for (int fn = 0; fn < 4; fn++) {
                int cb = wn * 32 + fn * 8 + g;
                bh0[fn] = osm[OB(s, 0, cb, kk + tig)];
                bh1[fn] = osm[OB(s, 0, cb, kk + tig + 4)];
                bl0[fn] = osm[OB(s, 1, cb, kk + tig)];
                bl1[fn] = osm[OB(s, 1, cb, kk + tig + 4)];
            }
            #pragma unroll
            for (int fm = 0; fm < 2; fm++)
                #pragma unroll
                for (int fn = 0; fn < 4; fn++) {
                    mma8(acc[fm][fn], afh[fm], bh0[fn], bh1[fn]);
                    mma8(acc[fm][fn], afh[fm], bl0[fn], bl1[fn]);
                }
        }
    }

    #pragma unroll
    for (int fn = 0; fn < 4; fn++) {
        const int col = n0 + wn * 32 + fn * 8 + 2 * tig;
        const float b0v = bias[col], b1v = bias[col + 1];
        #pragma unroll
        for (int fm = 0; fm < 2; fm++) {
            const int row = m0 + wm * 32 + fm * 16 + g;
            #pragma unroll
            for (int half = 0; half < 2; half++) {
                const int r = row + half * 8;
                *(float2*)&out[(size_t)r * E + col] =
                    make_float2(acc[fm][fn][half * 2 + 0] + b0v,
                                acc[fm][fn][half * 2 + 1] + b1v);
            }
        }
    }
}

// ---------------------------------------------------------------------------
// Flash attention, split-KV x3. CTA = 128 q-rows x ~683-key range.
// Warp = 16 q x 32 k. f16 hi/lo scores (3 products, k16) == 3xTF32 precision;
// f16 PV with register-resident P.
// smem (words): stage s @ s*3584: KH2[32][36], KL2 @+1152, VT[64][20] @+2304.
//   QLO @7168 (128x36). Total 11776 words = 47,104 B.
// ---------------------------------------------------------------------------
#define KPITCH 36
#define KL_REL 1152
#define VT_OFF 2304
#define STGW 3584
#define QL_OFF 7168
#define ATT_SMEM_WORDS 11776

__global__ __launch_bounds__(256, 2)
void attn_kernel(const float* __restrict__ pb, const float* __restrict__ coeff)
{
    extern __shared__ unsigned sm[];

    const int tid = threadIdx.x;
    const int w = tid >> 5, lane = tid & 31, g = lane >> 2, tig = lane & 3;
    const int q0 = blockIdx.x * 128, split = blockIdx.y, bh = blockIdx.z;
    const int b = bh / H, h = bh - b * H;

    const float* kbp = g_kbias + (size_t)bh * S;

    // ---- prologue: stage Q-hi (stage area, pitch 36) + Q-lo (QLO) ----
    #pragma unroll
    for (int t = 0; t < 4; t++) {
        int i = tid + t * 256;
        int r = i >> 3, c4 = (i & 7) << 2;
        size_t rowb = ((size_t)bh * S + q0 + r) * (D / 2);
        cpa16(&sm[r * KPITCH + c4], g_Qh2 + rowb + c4);
        cpa16(&sm[QL_OFF + r * KPITCH + c4], g_Ql2 + rowb + c4);
    }
    CP_COMMIT();
    CP_WAIT0();
    __syncthreads();

    // Q-hi fragments -> registers (f16 A operand, 4 kk-chunks of k16)
    unsigned qa[4][4];
    {
        const int qb = (w * 16 + g) * KPITCH;
        #pragma unroll
        for (int kk = 0; kk < 4; kk++) {
            qa[kk][0] = sm[qb + kk * 8 + tig];
            qa[kk][1] = sm[qb + 8 * KPITCH + kk * 8 + tig];
            qa[kk][2] = sm[qb + kk * 8 + tig + 4];
            qa[kk][3] = sm[qb + 8 * KPITCH + kk * 8 + tig + 4];
        }
    }
    __syncthreads();

    const float coeff_h = coeff[h];
    float rowb0 = coeff_h * pb[b * S + q0 + w * 16 + g];
    float rowb1 = coeff_h * pb[b * S + q0 + w * 16 + g + 8];

    float mi[2] = {-1e30f, -1e30f}, li[2] = {0.0f, 0.0f};
    float o[8][4];
    #pragma unroll
    for (int nf = 0; nf < 8; nf++)
        #pragma unroll
        for (int c = 0; c < 4; c++) o[nf][c] = 0.0f;

    const int qlb = QL_OFF + (w * 16 + g) * KPITCH;

    auto issuet = [&](int kt, int sb) {
        const int k0 = kt * 32;
        {
            int r = tid >> 3, c4 = (tid & 7) << 2;     // 32 rows x 8 groups
            size_t rowb = ((size_t)bh * S + k0 + r) * (D / 2);
            cpa16(&sm[sb + r * KPITCH + c4], g_Kh2 + rowb + c4);
            cpa16(&sm[sb + KL_REL + r * KPITCH + c4], g_Kl2 + rowb + c4);
        }
        {
            int r = tid >> 2, c = (tid & 3) * 4;       // V: 64 d-rows x 4 cpa
            cpa16(&sm[sb + VT_OFF + r * 20 + c],
                  g_Vt + ((size_t)bh * D + r) * S + k0 + c * 2);
        }
        CP_COMMIT();
    };

    const int kt0 = (64 * split) / NSPLIT;
    const int kt1 = (64 * (split + 1)) / NSPLIT;

    issuet(kt0, 0);
    for (int it = kt0; it < kt1; it++) {
        const int k0 = it * 32;
        CP_WAIT0();
        __syncthreads();
        if (it + 1 < kt1) issuet(it + 1, ((it - kt0 + 1) & 1) * STGW);
        const int sb = ((it - kt0) & 1) * STGW;

        // ---- S = Q K^T, f16 hi/lo (hh + lh + hl), k16 ----
        float sc[4][4];
        #pragma unroll
        for (int fn = 0; fn < 4; fn++)
            #pragma unroll
            for (int c = 0; c < 4; c++) sc[fn][c] = 0.0f;

        #pragma unroll
        for (int kk = 0; kk < 4; kk++) {
            unsigned ql[4];
            ql[0] = sm[qlb + kk * 8 + tig];
            ql[1] = sm[qlb + 8 * KPITCH + kk * 8 + tig];
            ql[2] = sm[qlb + kk * 8 + tig + 4];
            ql[3] = sm[qlb + 8 * KPITCH + kk * 8 + tig + 4];
            #pragma unroll
            for (int fn = 0; fn < 4; fn++) {
                int kb = sb + (fn * 8 + g) * KPITCH + kk * 8 + tig;
                unsigned kh0 = sm[kb], kh1 = sm[kb + 4];
                unsigned kl0 = sm[kb + KL_REL], kl1 = sm[kb + KL_REL + 4];
                mmaf16(sc[fn], qa[kk], kh0, kh1);
                mmaf16(sc[fn], ql,     kh0, kh1);
                mmaf16(sc[fn], qa[kk], kl0, kl1);
            }
        }

        // ---- rel-pos bias + mask (Q pre-scaled by 1/8) ----
        #pragma unroll
        for (int fn = 0; fn < 4; fn++) {
            int c = k0 + fn * 8 + 2 * tig;
            float cb0 = kbp[c], cb1 = kbp[c + 1];
            sc[fn][0] += rowb0 + cb0;
            sc[fn][1] += rowb0 + cb1;
            sc[fn][2] += rowb1 + cb0;
            sc[fn][3] += rowb1 + cb1;
        }

        // ---- online softmax; P packed to half2 in registers ----
        unsigned ph2[4][2];
        #pragma unroll
        for (int rh = 0; rh < 2; rh++) {
            float tm = -1e30f;
            #pragma unroll
            for (int fn = 0; fn < 4; fn++)
                tm = fmaxf(tm, fmaxf(sc[fn][2 * rh], sc[fn][2 * rh + 1]));
            tm = fmaxf(tm, __shfl_xor_sync(0xffffffffu, tm, 1));
            tm = fmaxf(tm, __shfl_xor_sync(0xffffffffu, tm, 2));
            float mnew = fmaxf(fmaxf(mi[rh], tm), -1e20f);
            float psum = 0.0f;
            #pragma unroll
            for (int fn = 0; fn < 4; fn++) {
                float p0 = __expf(sc[fn][2 * rh] - mnew);
                float p1 = __expf(sc[fn][2 * rh + 1] - mnew);
                psum += p0 + p1;
                __half2 hp = __floats2half2_rn(p0, p1);
                ph2[fn][rh] = *reinterpret_cast<unsigned*>(&hp);
            }
            psum += __shfl_xor_sync(0xffffffffu, psum, 1);
            psum += __shfl_xor_sync(0xffffffffu, psum, 2);
            float scale = __expf(mi[rh] - mnew);
            li[rh] = li[rh] * scale + psum;
            mi[rh] = mnew;
            #pragma unroll
            for (int nf = 0; nf < 8; nf++) {
                o[nf][2 * rh]     *= scale;
                o[nf][2 * rh + 1] *= scale;
            }
        }

        // ---- O += P V (f16 mma, P from registers, V transposed) ----
        #pragma unroll
        for (int j = 0; j < 2; j++) {
            unsigned pa[4] = {ph2[2 * j][0], ph2[2 * j][1],
                              ph2[2 * j + 1][0], ph2[2 * j + 1][1]};
            #pragma unroll
            for (int nf = 0; nf < 8; nf++) {
                int vb = sb + VT_OFF + (nf * 8 + g) * 20 + j * 8 + tig;
                mmaf16(o[nf], pa, sm[vb], sm[vb + 4]);
            }
        }
    }

    // ---- store partial (unnormalized O, m, l) to gmem ----
    const int qg = q0 + w * 16 + g;
    const size_t prow0 = (size_t)split * BHS + (size_t)bh * S + qg;
    const size_t prow1 = prow0 + 8;
    if (tig == 0) {
        *(float2*)&g_pml[prow0 * 2] = make_float2(mi[0], li[0]);
        *(float2*)&g_pml[prow1 * 2] = make_float2(mi[1], li[1]);
    }
    #pragma unroll
    for (int nf = 0; nf < 8; nf++) {
        int d = nf * 8 + 2 * tig;
        *(float2*)&g_po[prow0 * D + d] = make_float2(o[nf][0], o[nf][1]);
        *(float2*)&g_po[prow1 * D + d] = make_float2(o[nf][2], o[nf][3]);
    }
}

// ---------------------------------------------------------------------------
// Merge the three split-KV partials -> g_att (tf32 plane, [B,S,E] layout)
// ---------------------------------------------------------------------------
__global__ void attn_merge_kernel()
{
    int e = blockIdx.x * 256 + threadIdx.x;    // e < BHS*D/4
    int row = e >> 4;                          // (b*H+h)*S + q
    int dq = (e & 15) << 2;

    float2 ml0 = *(float2*)&g_pml[row * 2];
    float2 ml1 = *(float2*)&g_pml[(BHS + row) * 2];
    float2 ml2 = *(float2*)&g_pml[(2 * BHS + row) * 2];
    float mf = fmaxf(ml0.x, fmaxf(ml1.x, ml2.x));
    float a0 = __expf(ml0.x - mf), a1 = __expf(ml1.x - mf),
          a2 = __expf(ml2.x - mf);
    float inv = 1.0f / (ml0.y * a0 + ml1.y * a1 + ml2.y * a2);
    a0 *= inv; a1 *= inv; a2 *= inv;

    float4 o0 = *(float4*)&g_po[(size_t)row * D + dq];
    float4 o1 = *(float4*)&g_po[(size_t)BHS * D + (size_t)row * D + dq];
    float4 o2 = *(float4*)&g_po[2 * (size_t)BHS * D + (size_t)row * D + dq];

    int q = row & (S - 1);
    int bh = row >> 11;
    int b = bh / H, h = bh - b * H;
    uint4 r;
    r.x = f2tf(o0.x * a0 + o1.x * a1 + o2.x * a2);
    r.y = f2tf(o0.y * a0 + o1.y * a1 + o2.y * a2);
    r.z = f2tf(o0.z * a0 + o1.z * a1 + o2.z * a2);
    r.w = f2tf(o0.w * a0 + o1.w * a1 + o2.w * a2);
    *(uint4*)&g_att[(size_t)(b * S + q) * E + h * D + dq] = r;
}

// ---------------------------------------------------------------------------
extern "C" void kernel_launch(void* const* d_in, const int* in_sizes, int n_in,
                              void* d_out, int out_size)
{
    const float* query = (const float*)d_in[0];
    const float* key   = (const float*)d_in[1];
    const float* value = (const float*)d_in[2];
    const float* pb    = (const float*)d_in[3];
    const unsigned char* mask = (const unsigned char*)d_in[4];
    const float* wq_w = (const float*)d_in[5];
    const float* wq_b = (const float*)d_in[6];
    const float* wk_w = (const float*)d_in[7];
    const float* wk_b = (const float*)d_in[8];
    const float* wv_w = (const float*)d_in[9];
    const float* wv_b = (const float*)d_in[10];
    const float* fc_w = (const float*)d_in[11];
    const float* fc_b = (const float*)d_in[12];
    const float* coeff = (const float*)d_in[13];
    float* out = (float*)d_out;

    const int attn_smem = ATT_SMEM_WORDS * (int)sizeof(unsigned);  // 47,104 B
    const int qkv_smem  = QKV_SMEM_WORDS * (int)sizeof(unsigned);  // 61,440 B
    cudaFuncSetAttribute(attn_kernel,
                         cudaFuncAttributeMaxDynamicSharedMemorySize, attn_smem);
    cudaFuncSetAttribute(qkv_kernel,
                         cudaFuncAttributeMaxDynamicSharedMemorySize, qkv_smem);

    kbias_kernel<<<(B * H * S) / 256, 256>>>(mask, pb, coeff);
    split_all_kernel<<<SPLIT_TASKS / 256, 256>>>(query, key, value,
                                                 wq_w, wk_w, wv_w, fc_w);

    dim3 g1(E / 64, BSZ / 128, 3);    // (12, 32, 3)
    qkv_kernel<<<g1, 256, qkv_smem>>>(wq_b, wk_b, wv_b);

    dim3 gt(S / 32, D / 32, B * H);   // (64, 2, 24)
    vtrans_kernel<<<gt, dim3(32, 8)>>>();

    dim3 g2(S / 128, NSPLIT, B * H);  // (16, 3, 24) = 1152 CTAs
    attn_kernel<<<g2, 256, attn_smem>>>(pb, coeff);

    attn_merge_kernel<<<(BHS * D / 4) / 256, 256>>>();

    dim3 g3(E / 64, BSZ / 128);       // (12, 32)
    oproj_kernel<<<g3, 256>>>(fc_b, out);
}

// round 15
// speedup vs baseline: 3.0139x; 1.3323x over previous
#include <cuda_runtime.h>
#include <cuda_fp16.h>
#include <math.h>

#define B 2
#define S 2048
#define E 768
#define H 12
#define D 64
#define BSZ (B*S)
#define QKV_ELEMS (B*H*S*D)
#define XN (BSZ*E)
#define WN (E*E)
#define BHS (B*H*S)
#define NSPLIT 3

// Scratch (allocation-free rule: device globals) — all f16 half2-packed words
__device__ unsigned g_Xh2[3*XN/2], g_Xl2[3*XN/2];    // query,key,value hi/lo
__device__ unsigned g_Wh2[4*WN/2], g_Wl2[4*WN/2];    // wq,wk,wv,fc hi/lo
__device__ unsigned g_Qh2[QKV_ELEMS/2], g_Ql2[QKV_ELEMS/2];
__device__ unsigned g_Kh2[QKV_ELEMS/2], g_Kl2[QKV_ELEMS/2];
__device__ __half g_Vf16[QKV_ELEMS];      // V projection, f16, [B,H,S,D]
__device__ __half g_Vt[QKV_ELEMS];        // V transposed,  f16, [B,H,D,S]
__device__ unsigned g_att2[XN/2];         // attention out, f16 half2 plane
__device__ float g_po[NSPLIT*QKV_ELEMS];  // split-KV partial O (unnormalized)
__device__ float g_pml[NSPLIT*BHS*2];     // split-KV partial (m, l)
__device__ float g_kbias[B*H*S];

// ---------------------------------------------------------------------------
__device__ __forceinline__ void splth2(float v0, float v1,
                                       unsigned& hw, unsigned& lw) {
    __half h0 = __float2half_rn(v0);
    __half l0 = __float2half_rn(v0 - __half2float(h0));
    __half h1 = __float2half_rn(v1);
    __half l1 = __float2half_rn(v1 - __half2float(h1));
    __half2 hp = __halves2half2(h0, h1);
    __half2 lp = __halves2half2(l0, l1);
    hw = *reinterpret_cast<unsigned*>(&hp);
    lw = *reinterpret_cast<unsigned*>(&lp);
}
__device__ __forceinline__ void mmaf16(float* c, const unsigned* a,
                                       unsigned b0, unsigned b1) {
    asm volatile(
        "mma.sync.aligned.m16n8k16.row.col.f32.f16.f16.f32 "
        "{%0,%1,%2,%3},{%4,%5,%6,%7},{%8,%9},{%0,%1,%2,%3};"
        : "+f"(c[0]), "+f"(c[1]), "+f"(c[2]), "+f"(c[3])
        : "r"(a[0]), "r"(a[1]), "r"(a[2]), "r"(a[3]), "r"(b0), "r"(b1));
}
__device__ __forceinline__ void cpa16(void* s, const void* g) {
    unsigned sa = (unsigned)__cvta_generic_to_shared(s);
    asm volatile("cp.async.cg.shared.global [%0], [%1], 16;"
                 :: "r"(sa), "l"(g));
}
#define CP_COMMIT() asm volatile("cp.async.commit_group;")
#define CP_WAIT0()  asm volatile("cp.async.wait_group 0;" ::: "memory")

// ---------------------------------------------------------------------------
// One-time f16 hi/lo split of all 7 inputs (4 floats -> 2+2 half2 words).
// ---------------------------------------------------------------------------
#define XQ4 (XN/4)
#define WQ4 (WN/4)
#define SPLIT_TASKS (3*XQ4 + 4*WQ4)

__global__ void split_all_kernel(const float* __restrict__ q,
                                 const float* __restrict__ k,
                                 const float* __restrict__ v,
                                 const float* __restrict__ wq,
                                 const float* __restrict__ wk,
                                 const float* __restrict__ wv,
                                 const float* __restrict__ fc)
{
    int i = blockIdx.x * 256 + threadIdx.x;
    const float* src;
    unsigned *dh, *dl;
    int off;
    if (i < 3 * XQ4) {
        int z = i / XQ4;
        off = i - z * XQ4;
        src = (z == 0) ? q : (z == 1) ? k : v;
        dh = g_Xh2 + (size_t)z * (XN / 2);
        dl = g_Xl2 + (size_t)z * (XN / 2);
    } else {
        int j = i - 3 * XQ4;
        int z = j / WQ4;
        off = j - z * WQ4;
        src = (z == 0) ? wq : (z == 1) ? wk : (z == 2) ? wv : fc;
        dh = g_Wh2 + (size_t)z * (WN / 2);
        dl = g_Wl2 + (size_t)z * (WN / 2);
    }
    float4 vv = ((const float4*)src)[off];
    uint2 hh, ll;
    splth2(vv.x, vv.y, hh.x, ll.x);
    splth2(vv.z, vv.w, hh.y, ll.y);
    ((uint2*)dh)[off] = hh;
    ((uint2*)dl)[off] = ll;
}

// ---------------------------------------------------------------------------
__global__ void kbias_kernel(const unsigned char* __restrict__ m,
                             const float* __restrict__ pb,
                             const float* __restrict__ coeff)
{
    __shared__ int cls[4];
    int tid = threadIdx.x;
    if (tid < 4) cls[tid] = 0;
    __syncthreads();
    for (int i = tid; i < BSZ; i += 256)
        if (m[i]) atomicAdd(&cls[i & 3], 1);
    __syncthreads();
    int mode = 0;
    if (cls[1] == 0 && cls[2] == 0 && cls[3] == 0) mode = 1;      // int32
    else if (cls[0] == 0 && cls[1] == 0)           mode = 2;      // float32

    int idx = blockIdx.x * 256 + tid;
    int bh = idx / S, k = idx - bh * S;
    int b = bh / H, h = bh - b * H;
    bool v;
    int mi = b * S + k;
    if (mode == 1)      v = ((const int*)m)[mi] != 0;
    else if (mode == 2) v = ((const float*)m)[mi] != 0.0f;
    else                v = m[mi] != 0;
    g_kbias[idx] = -coeff[h] * pb[mi] + (v ? 0.0f : -1e30f);
}

// ---------------------------------------------------------------------------
// V transpose: g_Vf16 [bh][s][d] -> g_Vt [bh][d][s]
// ---------------------------------------------------------------------------
__global__ void vtrans_kernel()
{
    __shared__ __half t[32][33];
    const int bh = blockIdx.z;
    const int s0 = blockIdx.x * 32, d0 = blockIdx.y * 32;
    const __half* src = g_Vf16 + (size_t)bh * S * D;
    __half* dst = g_Vt + (size_t)bh * D * S;
    const int tx = threadIdx.x, ty = threadIdx.y;
    #pragma unroll
    for (int i = ty; i < 32; i += 8)
        t[i][tx] = src[(size_t)(s0 + i) * D + d0 + tx];
    __syncthreads();
    #pragma unroll
    for (int i = ty; i < 32; i += 8)
        dst[(size_t)(d0 + i) * S + s0 + tx] = t[tx][i];
}

// ---------------------------------------------------------------------------
// QKV projection, f16 hi/lo 3-product (2-product for V), k16 mma,
// double-buffered cp.async. CTA 128x64, 8 warps (32x32 tiles).
// Q pre-scaled by 1/8 (exact). smem pitch 12 words (conflict-free).
// ---------------------------------------------------------------------------
#define QGA(s,p,r,c) ((s) * 4608 + (p) * 1536 + (r) * 12 + (c))
#define QGB(s,p,r,c) ((s) * 4608 + 3072 + (p) * 768 + (r) * 12 + (c))
#define QKV_SMEM_WORDS 9216   // 36,864 B

__global__ __launch_bounds__(256, 3)
void qkv_kernel(const float* __restrict__ bq, const float* __restrict__ bk,
                const float* __restrict__ bv)
{
    const int z = blockIdx.z;
    const unsigned* Xh2 = g_Xh2 + (size_t)z * (XN / 2);
    const unsigned* Xl2 = g_Xl2 + (size_t)z * (XN / 2);
    const unsigned* Wh2 = g_Wh2 + (size_t)z * (WN / 2);
    const unsigned* Wl2 = g_Wl2 + (size_t)z * (WN / 2);
    const float* bias = (z == 0) ? bq : (z == 1) ? bk : bv;
    unsigned* oh2 = (z == 0) ? g_Qh2 : g_Kh2;
    unsigned* ol2 = (z == 0) ? g_Ql2 : g_Kl2;
    const bool rope = (z < 2);
    const bool vproj = (z == 2);

    extern __shared__ unsigned gsm[];

    const int tid = threadIdx.x;
    const int w = tid >> 5, wm = w >> 1, wn = w & 1;
    const int lane = tid & 31, g = lane >> 2, tig = lane & 3;
    const int m0 = blockIdx.y * 128, n0 = blockIdx.x * 64;

    float acc[2][4][4];
    #pragma unroll
    for (int a = 0; a < 2; a++)
        #pragma unroll
        for (int b2 = 0; b2 < 4; b2++)
            #pragma unroll
            for (int c = 0; c < 4; c++) acc[a][b2][c] = 0.0f;

    const int sr = tid >> 1, sc4 = (tid & 1) * 4;   // A: 128 rows x 2 chunks

    auto issueg = [&](int k0, int s) {
        size_t gi = (size_t)(m0 + sr) * (E / 2) + (k0 >> 1) + sc4;
        cpa16(&gsm[QGA(s, 0, sr, sc4)], Xh2 + gi);
        if (!vproj) cpa16(&gsm[QGA(s, 1, sr, sc4)], Xl2 + gi);
        if (tid < 128) {
            int rb = tid >> 1, cb4 = (tid & 1) * 4;
            size_t gj = (size_t)(n0 + rb) * (E / 2) + (k0 >> 1) + cb4;
            cpa16(&gsm[QGB(s, 0, rb, cb4)], Wh2 + gj);
            cpa16(&gsm[QGB(s, 1, rb, cb4)], Wl2 + gj);
        }
        CP_COMMIT();
    };

    issueg(0, 0);
    for (int it = 0; it < E / 16; it++) {
        CP_WAIT0();
        __syncthreads();
        if (it + 1 < E / 16) issueg((it + 1) * 16, (it + 1) & 1);
        const int s = it & 1;

        unsigned afh[2][4], afl[2][4], bh[4][2], bl[4][2];
        #pragma unroll
        for (int fm = 0; fm < 2; fm++) {
            int rb = wm * 32 + fm * 16 + g;
            afh[fm][0] = gsm[QGA(s, 0, rb,     tig)];
            afh[fm][1] = gsm[QGA(s, 0, rb + 8, tig)];
            afh[fm][2] = gsm[QGA(s, 0, rb,     tig + 4)];
            afh[fm][3] = gsm[QGA(s, 0, rb + 8, tig + 4)];
            if (!vproj) {
                afl[fm][0] = gsm[QGA(s, 1, rb,     tig)];
                afl[fm][1] = gsm[QGA(s, 1, rb + 8, tig)];
                afl[fm][2] = gsm[QGA(s, 1, rb,     tig + 4)];
                afl[fm][3] = gsm[QGA(s, 1, rb + 8, tig + 4)];
            }
        }
        #pragma unroll
        for (int fn = 0; fn < 4; fn++) {
            int cb = wn * 32 + fn * 8 + g;
            bh[fn][0] = gsm[QGB(s, 0, cb, tig)];
            bh[fn][1] = gsm[QGB(s, 0, cb, tig + 4)];
            bl[fn][0] = gsm[QGB(s, 1, cb, tig)];
            bl[fn][1] = gsm[QGB(s, 1, cb, tig + 4)];
        }
        #pragma unroll
        for (int fm = 0; fm < 2; fm++)
            #pragma unroll
            for (int fn = 0; fn < 4; fn++) {
                mmaf16(acc[fm][fn], afh[fm], bh[fn][0], bh[fn][1]);
                if (!vproj) mmaf16(acc[fm][fn], afl[fm], bh[fn][0], bh[fn][1]);
                mmaf16(acc[fm][fn], afh[fm], bl[fn][0], bl[fn][1]);
            }
    }

    // epilogue: bias + RoPE (fp32) [+ 1/8 Q-scale, exact]
    #pragma unroll
    for (int fn = 0; fn < 4; fn++) {
        const int col = n0 + wn * 32 + fn * 8 + 2 * tig;
        const int h = col / D, d = col % D;
        const float b0v = bias[col], b1v = bias[col + 1];
        const float invf = rope
            ? exp2f(-(float)d * (13.287712379549449f / 64.0f)) : 0.0f;
        #pragma unroll
        for (int fm = 0; fm < 2; fm++) {
            const int row = m0 + wm * 32 + fm * 16 + g;
            #pragma unroll
            for (int half = 0; half < 2; half++) {
                const int r = row + half * 8;
                const int bb = r >> 11, sdx = r & 2047;
                float v0 = acc[fm][fn][half * 2 + 0] + b0v;
                float v1 = acc[fm][fn][half * 2 + 1] + b1v;
                if (rope) {
                    float sn, cs;
                    sincosf((float)sdx * invf, &sn, &cs);
                    float t0 = v0 * cs - v1 * sn;
                    v1 = v1 * cs + v0 * sn;
                    v0 = t0;
                }
                if (z == 0) { v0 *= 0.125f; v1 *= 0.125f; }   // exact
                const size_t idx = (((size_t)bb * H + h) * S + sdx) * D + d;
                if (vproj) {
                    *reinterpret_cast<__half2*>(&g_Vf16[idx]) =
                        __floats2half2_rn(v0, v1);
                } else {
                    unsigned hw, lw;
                    splth2(v0, v1, hw, lw);
                    oh2[idx >> 1] = hw;
                    ol2[idx >> 1] = lw;
                }
            }
        }
    }
}

// ---------------------------------------------------------------------------
// Output projection: A = g_att2 (f16 single plane), W f16 hi/lo (2 products).
// ---------------------------------------------------------------------------
#define POA(s,r,c)   ((s) * 3072 + (r) * 12 + (c))
#define POB(s,p,r,c) ((s) * 3072 + 1536 + (p) * 768 + (r) * 12 + (c))
#define OPJ_SMEM_WORDS 6144   // 24,576 B

__global__ __launch_bounds__(256, 3)
void oproj_kernel(const float* __restrict__ bias, float* __restrict__ out)
{
    const unsigned* Wh2 = g_Wh2 + (size_t)3 * (WN / 2);
    const unsigned* Wl2 = g_Wl2 + (size_t)3 * (WN / 2);

    extern __shared__ unsigned gsm[];

    const int tid = threadIdx.x;
    const int w = tid >> 5, wm = w >> 1, wn = w & 1;
    const int lane = tid & 31, g = lane >> 2, tig = lane & 3;
    const int m0 = blockIdx.y * 128, n0 = blockIdx.x * 64;
    const int sr = tid >> 1, sc4 = (tid & 1) * 4;

    float acc[2][4][4];
    #pragma unroll
    for (int a = 0; a < 2; a++)
        #pragma unroll
        for (int b2 = 0; b2 < 4; b2++)
            #pragma unroll
            for (int c = 0; c < 4; c++) acc[a][b2][c] = 0.0f;

    auto issueg = [&](int k0, int s) {
        size_t gi = (size_t)(m0 + sr) * (E / 2) + (k0 >> 1) + sc4;
        cpa16(&gsm[POA(s, sr, sc4)], g_att2 + gi);
        if (tid < 128) {
            int rb = tid >> 1, cb4 = (tid & 1) * 4;
            size_t gj = (size_t)(n0 + rb) * (E / 2) + (k0 >> 1) + cb4;
            cpa16(&gsm[POB(s, 0, rb, cb4)], Wh2 + gj);
            cpa16(&gsm[POB(s, 1, rb, cb4)], Wl2 + gj);
        }
        CP_COMMIT();
    };

    issueg(0, 0);
    for (int it = 0; it < E / 16; it++) {
        CP_WAIT0();
        __syncthreads();
        if (it + 1 < E / 16) issueg((it + 1) * 16, (it + 1) & 1);
        const int s = it & 1;

        unsigned afh[2][4], bh[4][2], bl[4][2];
        #pragma unroll
        for (int fm = 0; fm < 2; fm++) {
            int rb = wm * 32 + fm * 16 + g;
            afh[fm][0] = gsm[POA(s, rb,     tig)];
            afh[fm][1] = gsm[POA(s, rb + 8, tig)];
            afh[fm][2] = gsm[POA(s, rb,     tig + 4)];
            afh[fm][3] = gsm[POA(s, rb + 8, tig + 4)];
        }
        #pragma unroll
        for (int fn = 0; fn < 4; fn++) {
            int cb = wn * 32 + fn * 8 + g;
            bh[fn][0] = gsm[POB(s, 0, cb, tig)];
            bh[fn][1] = gsm[POB(s, 0, cb, tig + 4)];
            bl[fn][0] = gsm[POB(s, 1, cb, tig)];
            bl[fn][1] = gsm[POB(s, 1, cb, tig + 4)];
        }
        #pragma unroll
        for (int fm = 0; fm < 2; fm++)
            #pragma unroll
            for (int fn = 0; fn < 4; fn++) {
                mmaf16(acc[fm][fn], afh[fm], bh[fn][0], bh[fn][1]);
                mmaf16(acc[fm][fn], afh[fm], bl[fn][0], bl[fn][1]);
            }
    }

    #pragma unroll
    for (int fn = 0; fn < 4; fn++) {
        const int col = n0 + wn * 32 + fn * 8 + 2 * tig;
        const float b0v = bias[col], b1v = bias[col + 1];
        #pragma unroll
        for (int fm = 0; fm < 2; fm++) {
            const int row = m0 + wm * 32 + fm * 16 + g;
            #pragma unroll
            for (int half = 0; half < 2; half++) {
                const int r = row + half * 8;
                *(float2*)&out[(size_t)r * E + col] =
                    make_float2(acc[fm][fn][half * 2 + 0] + b0v,
                                acc[fm][fn][half * 2 + 1] + b1v);
            }
        }
    }
}

// ---------------------------------------------------------------------------
// Flash attention, split-KV x3 (unchanged from R14).
// smem (words): stage s @ s*3584: KH2[32][36], KL2 @+1152, VT[64][20] @+2304.
//   QLO @7168 (128x36). Total 11776 words = 47,104 B.
// ---------------------------------------------------------------------------
#define KPITCH 36
#define KL_REL 1152
#define VT_OFF 2304
#define STGW 3584
#define QL_OFF 7168
#define ATT_SMEM_WORDS 11776

__global__ __launch_bounds__(256, 2)
void attn_kernel(const float* __restrict__ pb, const float* __restrict__ coeff)
{
    extern __shared__ unsigned sm[];

    const int tid = threadIdx.x;
    const int w = tid >> 5, lane = tid & 31, g = lane >> 2, tig = lane & 3;
    const int q0 = blockIdx.x * 128, split = blockIdx.y, bh = blockIdx.z;
    const int b = bh / H, h = bh - b * H;

    const float* kbp = g_kbias + (size_t)bh * S;

    #pragma unroll
    for (int t = 0; t < 4; t++) {
        int i = tid + t * 256;
        int r = i >> 3, c4 = (i & 7) << 2;
        size_t rowb = ((size_t)bh * S + q0 + r) * (D / 2);
        cpa16(&sm[r * KPITCH + c4], g_Qh2 + rowb + c4);
        cpa16(&sm[QL_OFF + r * KPITCH + c4], g_Ql2 + rowb + c4);
    }
    CP_COMMIT();
    CP_WAIT0();
    __syncthreads();

    unsigned qa[4][4];
    {
        const int qb = (w * 16 + g) * KPITCH;
        #pragma unroll
        for (int kk = 0; kk < 4; kk++) {
            qa[kk][0] = sm[qb + kk * 8 + tig];
            qa[kk][1] = sm[qb + 8 * KPITCH + kk * 8 + tig];
            qa[kk][2] = sm[qb + kk * 8 + tig + 4];
            qa[kk][3] = sm[qb + 8 * KPITCH + kk * 8 + tig + 4];
        }
    }
    __syncthreads();

    const float coeff_h = coeff[h];
    float rowb0 = coeff_h * pb[b * S + q0 + w * 16 + g];
    float rowb1 = coeff_h * pb[b * S + q0 + w * 16 + g + 8];

    float mi[2] = {-1e30f, -1e30f}, li[2] = {0.0f, 0.0f};
    float o[8][4];
    #pragma unroll
    for (int nf = 0; nf < 8; nf++)
        #pragma unroll
        for (int c = 0; c < 4; c++) o[nf][c] = 0.0f;

    const int qlb = QL_OFF + (w * 16 + g) * KPITCH;

    auto issuet = [&](int kt, int sb) {
        const int k0 = kt * 32;
        {
            int r = tid >> 3, c4 = (tid & 7) << 2;
            size_t rowb = ((size_t)bh * S + k0 + r) * (D / 2);
            cpa16(&sm[sb + r * KPITCH + c4], g_Kh2 + rowb + c4);
            cpa16(&sm[sb + KL_REL + r * KPITCH + c4], g_Kl2 + rowb + c4);
        }
        {
            int r = tid >> 2, c = (tid & 3) * 4;
            cpa16(&sm[sb + VT_OFF + r * 20 + c],
                  g_Vt + ((size_t)bh * D + r) * S + k0 + c * 2);
        }
        CP_COMMIT();
    };

    const int kt0 = (64 * split) / NSPLIT;
    const int kt1 = (64 * (split + 1)) / NSPLIT;

    issuet(kt0, 0);
    for (int it = kt0; it < kt1; it++) {
        const int k0 = it * 32;
        CP_WAIT0();
        __syncthreads();
        if (it + 1 < kt1) issuet(it + 1, ((it - kt0 + 1) & 1) * STGW);
        const int sb = ((it - kt0) & 1) * STGW;

        float sc[4][4];
        #pragma unroll
        for (int fn = 0; fn < 4; fn++)
            #pragma unroll
            for (int c = 0; c < 4; c++) sc[fn][c] = 0.0f;

        #pragma unroll
        for (int kk = 0; kk < 4; kk++) {
            unsigned ql[4];
            ql[0] = sm[qlb + kk * 8 + tig];
            ql[1] = sm[qlb + 8 * KPITCH + kk * 8 + tig];
            ql[2] = sm[qlb + kk * 8 + tig + 4];
            ql[3] = sm[qlb + 8 * KPITCH + kk * 8 + tig + 4];
            #pragma unroll
            for (int fn = 0; fn < 4; fn++) {
                int kb = sb + (fn * 8 + g) * KPITCH + kk * 8 + tig;
                unsigned kh0 = sm[kb], kh1 = sm[kb + 4];
                unsigned kl0 = sm[kb + KL_REL], kl1 = sm[kb + KL_REL + 4];
                mmaf16(sc[fn], qa[kk], kh0, kh1);
                mmaf16(sc[fn], ql,     kh0, kh1);
                mmaf16(sc[fn], qa[kk], kl0, kl1);
            }
        }

        #pragma unroll
        for (int fn = 0; fn < 4; fn++) {
            int c = k0 + fn * 8 + 2 * tig;
            float cb0 = kbp[c], cb1 = kbp[c + 1];
            sc[fn][0] += rowb0 + cb0;
            sc[fn][1] += rowb0 + cb1;
            sc[fn][2] += rowb1 + cb0;
            sc[fn][3] += rowb1 + cb1;
        }

        unsigned ph2[4][2];
        #pragma unroll
        for (int rh = 0; rh < 2; rh++) {
            float tm = -1e30f;
            #pragma unroll
            for (int fn = 0; fn < 4; fn++)
                tm = fmaxf(tm, fmaxf(sc[fn][2 * rh], sc[fn][2 * rh + 1]));
            tm = fmaxf(tm, __shfl_xor_sync(0xffffffffu, tm, 1));
            tm = fmaxf(tm, __shfl_xor_sync(0xffffffffu, tm, 2));
            float mnew = fmaxf(fmaxf(mi[rh], tm), -1e20f);
            float psum = 0.0f;
            #pragma unroll
            for (int fn = 0; fn < 4; fn++) {
                float p0 = __expf(sc[fn][2 * rh] - mnew);
                float p1 = __expf(sc[fn][2 * rh + 1] - mnew);
                psum += p0 + p1;
                __half2 hp = __floats2half2_rn(p0, p1);
                ph2[fn][rh] = *reinterpret_cast<unsigned*>(&hp);
            }
            psum += __shfl_xor_sync(0xffffffffu, psum, 1);
            psum += __shfl_xor_sync(0xffffffffu, psum, 2);
            float scale = __expf(mi[rh] - mnew);
            li[rh] = li[rh] * scale + psum;
            mi[rh] = mnew;
            #pragma unroll
            for (int nf = 0; nf < 8; nf++) {
                o[nf][2 * rh]     *= scale;
                o[nf][2 * rh + 1] *= scale;
            }
        }

        #pragma unroll
        for (int j = 0; j < 2; j++) {
            unsigned pa[4] = {ph2[2 * j][0], ph2[2 * j][1],
                              ph2[2 * j + 1][0], ph2[2 * j + 1][1]};
            #pragma unroll
            for (int nf = 0; nf < 8; nf++) {
                int vb = sb + VT_OFF + (nf * 8 + g) * 20 + j * 8 + tig;
                mmaf16(o[nf], pa, sm[vb], sm[vb + 4]);
            }
        }
    }

    const int qg = q0 + w * 16 + g;
    const size_t prow0 = (size_t)split * BHS + (size_t)bh * S + qg;
    const size_t prow1 = prow0 + 8;
    if (tig == 0) {
        *(float2*)&g_pml[prow0 * 2] = make_float2(mi[0], li[0]);
        *(float2*)&g_pml[prow1 * 2] = make_float2(mi[1], li[1]);
    }
    #pragma unroll
    for (int nf = 0; nf < 8; nf++) {
        int d = nf * 8 + 2 * tig;
        *(float2*)&g_po[prow0 * D + d] = make_float2(o[nf][0], o[nf][1]);
        *(float2*)&g_po[prow1 * D + d] = make_float2(o[nf][2], o[nf][3]);
    }
}

// ---------------------------------------------------------------------------
// Merge the three split-KV partials -> g_att2 (f16 plane, [B,S,E] layout)
// ---------------------------------------------------------------------------
__global__ void attn_merge_kernel()
{
    int e = blockIdx.x * 256 + threadIdx.x;    // e < BHS*D/4
    int row = e >> 4;                          // (b*H+h)*S + q
    int dq = (e & 15) << 2;

    float2 ml0 = *(float2*)&g_pml[row * 2];
    float2 ml1 = *(float2*)&g_pml[(BHS + row) * 2];
    float2 ml2 = *(float2*)&g_pml[(2 * BHS + row) * 2];
    float mf = fmaxf(ml0.x, fmaxf(ml1.x, ml2.x));
    float a0 = __expf(ml0.x - mf), a1 = __expf(ml1.x - mf),
          a2 = __expf(ml2.x - mf);
    float inv = 1.0f / (ml0.y * a0 + ml1.y * a1 + ml2.y * a2);
    a0 *= inv; a1 *= inv; a2 *= inv;

    float4 o0 = *(float4*)&g_po[(size_t)row * D + dq];
    float4 o1 = *(float4*)&g_po[(size_t)BHS * D + (size_t)row * D + dq];
    float4 o2 = *(float4*)&g_po[2 * (size_t)BHS * D + (size_t)row * D + dq];

    int q = row & (S - 1);
    int bh = row >> 11;
    int b = bh / H, h = bh - b * H;
    __half2 w0 = __floats2half2_rn(o0.x * a0 + o1.x * a1 + o2.x * a2,
                                   o0.y * a0 + o1.y * a1 + o2.y * a2);
    __half2 w1 = __floats2half2_rn(o0.z * a0 + o1.z * a1 + o2.z * a2,
                                   o0.w * a0 + o1.w * a1 + o2.w * a2);
    size_t wi = ((size_t)(b * S + q) * E + h * D + dq) >> 1;
    *(uint2*)&g_att2[wi] = make_uint2(*reinterpret_cast<unsigned*>(&w0),
                                      *reinterpret_cast<unsigned*>(&w1));
}

// ---------------------------------------------------------------------------
extern "C" void kernel_launch(void* const* d_in, const int* in_sizes, int n_in,
                              void* d_out, int out_size)
{
    const float* query = (const float*)d_in[0];
    const float* key   = (const float*)d_in[1];
    const float* value = (const float*)d_in[2];
    const float* pb    = (const float*)d_in[3];
    const unsigned char* mask = (const unsigned char*)d_in[4];
    const float* wq_w = (const float*)d_in[5];
    const float* wq_b = (const float*)d_in[6];
    const float* wk_w = (const float*)d_in[7];
    const float* wk_b = (const float*)d_in[8];
    const float* wv_w = (const float*)d_in[9];
    const float* wv_b = (const float*)d_in[10];
    const float* fc_w = (const float*)d_in[11];
    const float* fc_b = (const float*)d_in[12];
    const float* coeff = (const float*)d_in[13];
    float* out = (float*)d_out;

    const int attn_smem = ATT_SMEM_WORDS * (int)sizeof(unsigned);  // 47,104 B
    const int qkv_smem  = QKV_SMEM_WORDS * (int)sizeof(unsigned);  // 36,864 B
    const int opj_smem  = OPJ_SMEM_WORDS * (int)sizeof(unsigned);  // 24,576 B
    cudaFuncSetAttribute(attn_kernel,
                         cudaFuncAttributeMaxDynamicSharedMemorySize, attn_smem);
    cudaFuncSetAttribute(qkv_kernel,
                         cudaFuncAttributeMaxDynamicSharedMemorySize, qkv_smem);
    cudaFuncSetAttribute(oproj_kernel,
                         cudaFuncAttributeMaxDynamicSharedMemorySize, opj_smem);

    kbias_kernel<<<(B * H * S) / 256, 256>>>(mask, pb, coeff);
    split_all_kernel<<<SPLIT_TASKS / 256, 256>>>(query, key, value,
                                                 wq_w, wk_w, wv_w, fc_w);

    dim3 g1(E / 64, BSZ / 128, 3);    // (12, 32, 3)
    qkv_kernel<<<g1, 256, qkv_smem>>>(wq_b, wk_b, wv_b);

    dim3 gt(S / 32, D / 32, B * H);   // (64, 2, 24)
    vtrans_kernel<<<gt, dim3(32, 8)>>>();

    dim3 g2(S / 128, NSPLIT, B * H);  // (16, 3, 24) = 1152 CTAs
    attn_kernel<<<g2, 256, attn_smem>>>(pb, coeff);

    attn_merge_kernel<<<(BHS * D / 4) / 256, 256>>>();

    dim3 g3(E / 64, BSZ / 128);       // (12, 32)
    oproj_kernel<<<g3, 256, opj_smem>>>(fc_b, out);
}

// round 16
// speedup vs baseline: 3.2904x; 1.0917x over previous
#include <cuda_runtime.h>
#include <cuda_fp16.h>
#include <math.h>

#define B 2
#define S 2048
#define E 768
#define H 12
#define D 64
#define BSZ (B*S)
#define QKV_ELEMS (B*H*S*D)
#define XN (BSZ*E)
#define WN (E*E)
#define BHS (B*H*S)
#define NSPLIT 3

// Scratch (allocation-free rule: device globals) — all f16 half2-packed words
__device__ unsigned g_Xh2[3*XN/2], g_Xl2[3*XN/2];    // query,key,value hi/lo
__device__ unsigned g_Wh2[4*WN/2], g_Wl2[4*WN/2];    // wq,wk,wv,fc hi/lo
__device__ unsigned g_Qh2[QKV_ELEMS/2], g_Ql2[QKV_ELEMS/2];
__device__ unsigned g_Kh2[QKV_ELEMS/2], g_Kl2[QKV_ELEMS/2];
__device__ __half g_Vt[QKV_ELEMS];        // V transposed, f16, [B,H,D,S]
__device__ unsigned g_att2[XN/2];         // attention out, f16 half2 plane
__device__ float g_po[NSPLIT*QKV_ELEMS];  // split-KV partial O (unnormalized)
__device__ float g_pml[NSPLIT*BHS*2];     // split-KV partial (m, l)
__device__ float g_kbias[B*H*S];

// ---------------------------------------------------------------------------
__device__ __forceinline__ void splth2(float v0, float v1,
                                       unsigned& hw, unsigned& lw) {
    __half h0 = __float2half_rn(v0);
    __half l0 = __float2half_rn(v0 - __half2float(h0));
    __half h1 = __float2half_rn(v1);
    __half l1 = __float2half_rn(v1 - __half2float(h1));
    __half2 hp = __halves2half2(h0, h1);
    __half2 lp = __halves2half2(l0, l1);
    hw = *reinterpret_cast<unsigned*>(&hp);
    lw = *reinterpret_cast<unsigned*>(&lp);
}
__device__ __forceinline__ void mmaf16(float* c, const unsigned* a,
                                       unsigned b0, unsigned b1) {
    asm volatile(
        "mma.sync.aligned.m16n8k16.row.col.f32.f16.f16.f32 "
        "{%0,%1,%2,%3},{%4,%5,%6,%7},{%8,%9},{%0,%1,%2,%3};"
        : "+f"(c[0]), "+f"(c[1]), "+f"(c[2]), "+f"(c[3])
        : "r"(a[0]), "r"(a[1]), "r"(a[2]), "r"(a[3]), "r"(b0), "r"(b1));
}
__device__ __forceinline__ void cpa16(void* s, const void* g) {
    unsigned sa = (unsigned)__cvta_generic_to_shared(s);
    asm volatile("cp.async.cg.shared.global [%0], [%1], 16;"
                 :: "r"(sa), "l"(g));
}
#define CP_COMMIT() asm volatile("cp.async.commit_group;")
#define CP_WAIT0()  asm volatile("cp.async.wait_group 0;" ::: "memory")

// ---------------------------------------------------------------------------
// prep: f16 hi/lo split of all 7 inputs + kbias, one kernel.
// ---------------------------------------------------------------------------
#define XQ4 (XN/4)
#define WQ4 (WN/4)
#define SPLIT_CTAS ((3*XQ4 + 4*WQ4) / 256)   // 11520
#define KB_CTAS (BHS / 256)                  // 192

__global__ void prep_kernel(const float* __restrict__ q,
                            const float* __restrict__ k,
                            const float* __restrict__ v,
                            const float* __restrict__ wq,
                            const float* __restrict__ wk,
                            const float* __restrict__ wv,
                            const float* __restrict__ fc,
                            const unsigned char* __restrict__ m,
                            const float* __restrict__ pb,
                            const float* __restrict__ coeff)
{
    if (blockIdx.x < SPLIT_CTAS) {
        int i = blockIdx.x * 256 + threadIdx.x;
        const float* src;
        unsigned *dh, *dl;
        int off;
        if (i < 3 * XQ4) {
            int z = i / XQ4;
            off = i - z * XQ4;
            src = (z == 0) ? q : (z == 1) ? k : v;
            dh = g_Xh2 + (size_t)z * (XN / 2);
            dl = g_Xl2 + (size_t)z * (XN / 2);
        } else {
            int j = i - 3 * XQ4;
            int z = j / WQ4;
            off = j - z * WQ4;
            src = (z == 0) ? wq : (z == 1) ? wk : (z == 2) ? wv : fc;
            dh = g_Wh2 + (size_t)z * (WN / 2);
            dl = g_Wl2 + (size_t)z * (WN / 2);
        }
        float4 vv = ((const float4*)src)[off];
        uint2 hh, ll;
        splth2(vv.x, vv.y, hh.x, ll.x);
        splth2(vv.z, vv.w, hh.y, ll.y);
        ((uint2*)dh)[off] = hh;
        ((uint2*)dl)[off] = ll;
    } else {
        __shared__ int cls[4];
        int tid = threadIdx.x;
        if (tid < 4) cls[tid] = 0;
        __syncthreads();
        for (int i = tid; i < BSZ; i += 256)
            if (m[i]) atomicAdd(&cls[i & 3], 1);
        __syncthreads();
        int mode = 0;
        if (cls[1] == 0 && cls[2] == 0 && cls[3] == 0) mode = 1;  // int32
        else if (cls[0] == 0 && cls[1] == 0)           mode = 2;  // float32

        int idx = (blockIdx.x - SPLIT_CTAS) * 256 + tid;
        int bh = idx / S, kk = idx - bh * S;
        int b = bh / H, h = bh - b * H;
        bool vv;
        int mi = b * S + kk;
        if (mode == 1)      vv = ((const int*)m)[mi] != 0;
        else if (mode == 2) vv = ((const float*)m)[mi] != 0.0f;
        else                vv = m[mi] != 0;
        g_kbias[idx] = -coeff[h] * pb[mi] + (vv ? 0.0f : -1e30f);
    }
}

// ---------------------------------------------------------------------------
// QKV projection, f16 hi/lo 3-product (2-product for V), k32 steps,
// double-buffered cp.async. CTA 128x64, 8 warps (32x32 tiles).
// Q pre-scaled by 1/8 (exact). V written transposed to g_Vt.
// smem pitch 20 words (conflict-free).
// ---------------------------------------------------------------------------
#define QGA(s,p,r,c) ((s) * 7680 + (p) * 2560 + (r) * 20 + (c))
#define QGB(s,p,r,c) ((s) * 7680 + 5120 + (p) * 1280 + (r) * 20 + (c))
#define QKV_SMEM_WORDS 15360   // 61,440 B

__global__ __launch_bounds__(256, 3)
void qkv_kernel(const float* __restrict__ bq, const float* __restrict__ bk,
                const float* __restrict__ bv)
{
    const int z = blockIdx.z;
    const unsigned* Xh2 = g_Xh2 + (size_t)z * (XN / 2);
    const unsigned* Xl2 = g_Xl2 + (size_t)z * (XN / 2);
    const unsigned* Wh2 = g_Wh2 + (size_t)z * (WN / 2);
    const unsigned* Wl2 = g_Wl2 + (size_t)z * (WN / 2);
    const float* bias = (z == 0) ? bq : (z == 1) ? bk : bv;
    unsigned* oh2 = (z == 0) ? g_Qh2 : g_Kh2;
    unsigned* ol2 = (z == 0) ? g_Ql2 : g_Kl2;
    const bool rope = (z < 2);
    const bool vproj = (z == 2);

    extern __shared__ unsigned gsm[];

    const int tid = threadIdx.x;
    const int w = tid >> 5, wm = w >> 1, wn = w & 1;
    const int lane = tid & 31, g = lane >> 2, tig = lane & 3;
    const int m0 = blockIdx.y * 128, n0 = blockIdx.x * 64;

    float acc[2][4][4];
    #pragma unroll
    for (int a = 0; a < 2; a++)
        #pragma unroll
        for (int b2 = 0; b2 < 4; b2++)
            #pragma unroll
            for (int c = 0; c < 4; c++) acc[a][b2][c] = 0.0f;

    auto issueg = [&](int k0, int s) {
        #pragma unroll
        for (int t = 0; t < 2; t++) {           // A: 128 rows x 4 chunks
            int i = tid + t * 256;
            int r = i >> 2, c4 = (i & 3) << 2;
            size_t gi = (size_t)(m0 + r) * (E / 2) + (k0 >> 1) + c4;
            cpa16(&gsm[QGA(s, 0, r, c4)], Xh2 + gi);
            if (!vproj) cpa16(&gsm[QGA(s, 1, r, c4)], Xl2 + gi);
        }
        {                                        // B: 64 rows x 4 chunks
            int rb = tid >> 2, cb4 = (tid & 3) << 2;
            size_t gj = (size_t)(n0 + rb) * (E / 2) + (k0 >> 1) + cb4;
            cpa16(&gsm[QGB(s, 0, rb, cb4)], Wh2 + gj);
            cpa16(&gsm[QGB(s, 1, rb, cb4)], Wl2 + gj);
        }
        CP_COMMIT();
    };

    issueg(0, 0);
    for (int it = 0; it < E / 32; it++) {
        CP_WAIT0();
        __syncthreads();
        if (it + 1 < E / 32) issueg((it + 1) * 32, (it + 1) & 1);
        const int s = it & 1;
        #pragma unroll
        for (int kk = 0; kk < 2; kk++) {
            unsigned afh[2][4], afl[2][4], bh[4][2], bl[4][2];
            #pragma unroll
            for (int fm = 0; fm < 2; fm++) {
                int rb = wm * 32 + fm * 16 + g;
                afh[fm][0] = gsm[QGA(s, 0, rb,     kk * 8 + tig)];
                afh[fm][1] = gsm[QGA(s, 0, rb + 8, kk * 8 + tig)];
                afh[fm][2] = gsm[QGA(s, 0, rb,     kk * 8 + tig + 4)];
                afh[fm][3] = gsm[QGA(s, 0, rb + 8, kk * 8 + tig + 4)];
                if (!vproj) {
                    afl[fm][0] = gsm[QGA(s, 1, rb,     kk * 8 + tig)];
                    afl[fm][1] = gsm[QGA(s, 1, rb + 8, kk * 8 + tig)];
                    afl[fm][2] = gsm[QGA(s, 1, rb,     kk * 8 + tig + 4)];
                    afl[fm][3] = gsm[QGA(s, 1, rb + 8, kk * 8 + tig + 4)];
                }
            }
            #pragma unroll
            for (int fn = 0; fn < 4; fn++) {
                int cb = wn * 32 + fn * 8 + g;
                bh[fn][0] = gsm[QGB(s, 0, cb, kk * 8 + tig)];
                bh[fn][1] = gsm[QGB(s, 0, cb, kk * 8 + tig + 4)];
                bl[fn][0] = gsm[QGB(s, 1, cb, kk * 8 + tig)];
                bl[fn][1] = gsm[QGB(s, 1, cb, kk * 8 + tig + 4)];
            }
            #pragma unroll
            for (int fm = 0; fm < 2; fm++)
                #pragma unroll
                for (int fn = 0; fn < 4; fn++) {
                    mmaf16(acc[fm][fn], afh[fm], bh[fn][0], bh[fn][1]);
                    if (!vproj)
                        mmaf16(acc[fm][fn], afl[fm], bh[fn][0], bh[fn][1]);
                    mmaf16(acc[fm][fn], afh[fm], bl[fn][0], bl[fn][1]);
                }
        }
    }

    // epilogue: bias + RoPE (fp32) [+ 1/8 Q-scale, exact]
    #pragma unroll
    for (int fn = 0; fn < 4; fn++) {
        const int col = n0 + wn * 32 + fn * 8 + 2 * tig;
        const int h = col / D, d = col % D;
        const float b0v = bias[col], b1v = bias[col + 1];
        const float invf = rope
            ? exp2f(-(float)d * (13.287712379549449f / 64.0f)) : 0.0f;
        #pragma unroll
        for (int fm = 0; fm < 2; fm++) {
            const int row = m0 + wm * 32 + fm * 16 + g;
            #pragma unroll
            for (int half = 0; half < 2; half++) {
                const int r = row + half * 8;
                const int bb = r >> 11, sdx = r & 2047;
                float v0 = acc[fm][fn][half * 2 + 0] + b0v;
                float v1 = acc[fm][fn][half * 2 + 1] + b1v;
                if (rope) {
                    float sn, cs;
                    sincosf((float)sdx * invf, &sn, &cs);
                    float t0 = v0 * cs - v1 * sn;
                    v1 = v1 * cs + v0 * sn;
                    v0 = t0;
                }
                if (z == 0) { v0 *= 0.125f; v1 *= 0.125f; }   // exact
                if (vproj) {
                    // write V transposed: [bh][d][s]
                    size_t vt = (((size_t)bb * H + h) * D + d) * S + sdx;
                    g_Vt[vt]     = __float2half_rn(v0);
                    g_Vt[vt + S] = __float2half_rn(v1);
                } else {
                    const size_t idx = (((size_t)bb * H + h) * S + sdx) * D + d;
                    unsigned hw, lw;
                    splth2(v0, v1, hw, lw);
                    oh2[idx >> 1] = hw;
                    ol2[idx >> 1] = lw;
                }
            }
        }
    }
}

// ---------------------------------------------------------------------------
// Output projection: A = g_att2 (f16 plane), W f16 hi/lo (2 products), k32.
// ---------------------------------------------------------------------------
#define POA(s,r,c)   ((s) * 5120 + (r) * 20 + (c))
#define POB(s,p,r,c) ((s) * 5120 + 2560 + (p) * 1280 + (r) * 20 + (c))
#define OPJ_SMEM_WORDS 10240   // 40,960 B

__global__ __launch_bounds__(256, 3)
void oproj_kernel(const float* __restrict__ bias, float* __restrict__ out)
{
    const unsigned* Wh2 = g_Wh2 + (size_t)3 * (WN / 2);
    const unsigned* Wl2 = g_Wl2 + (size_t)3 * (WN / 2);

    extern __shared__ unsigned gsm[];

    const int tid = threadIdx.x;
    const int w = tid >> 5, wm = w >> 1, wn = w & 1;
    const int lane = tid & 31, g = lane >> 2, tig = lane & 3;
    const int m0 = blockIdx.y * 128, n0 = blockIdx.x * 64;

    float acc[2][4][4];
    #pragma unroll
    for (int a = 0; a < 2; a++)
        #pragma unroll
        for (int b2 = 0; b2 < 4; b2++)
            #pragma unroll
            for (int c = 0; c < 4; c++) acc[a][b2][c] = 0.0f;

    auto issueg = [&](int k0, int s) {
        #pragma unroll
        for (int t = 0; t < 2; t++) {
            int i = tid + t * 256;
            int r = i >> 2, c4 = (i & 3) << 2;
            size_t gi = (size_t)(m0 + r) * (E / 2) + (k0 >> 1) + c4;
            cpa16(&gsm[POA(s, r, c4)], g_att2 + gi);
        }
        {
            int rb = tid >> 2, cb4 = (tid & 3) << 2;
            size_t gj = (size_t)(n0 + rb) * (E / 2) + (k0 >> 1) + cb4;
            cpa16(&gsm[POB(s, 0, rb, cb4)], Wh2 + gj);
            cpa16(&gsm[POB(s, 1, rb, cb4)], Wl2 + gj);
        }
        CP_COMMIT();
    };

    issueg(0, 0);
    for (int it = 0; it < E / 32; it++) {
        CP_WAIT0();
        __syncthreads();
        if (it + 1 < E / 32) issueg((it + 1) * 32, (it + 1) & 1);
        const int s = it & 1;
        #pragma unroll
        for (int kk = 0; kk < 2; kk++) {
            unsigned afh[2][4], bh[4][2], bl[4][2];
            #pragma unroll
            for (int fm = 0; fm < 2; fm++) {
                int rb = wm * 32 + fm * 16 + g;
                afh[fm][0] = gsm[POA(s, rb,     kk * 8 + tig)];
                afh[fm][1] = gsm[POA(s, rb + 8, kk * 8 + tig)];
                afh[fm][2] = gsm[POA(s, rb,     kk * 8 + tig + 4)];
                afh[fm][3] = gsm[POA(s, rb + 8, kk * 8 + tig + 4)];
            }
            #pragma unroll
            for (int fn = 0; fn < 4; fn++) {
                int cb = wn * 32 + fn * 8 + g;
                bh[fn][0] = gsm[POB(s, 0, cb, kk * 8 + tig)];
                bh[fn][1] = gsm[POB(s, 0, cb, kk * 8 + tig + 4)];
                bl[fn][0] = gsm[POB(s, 1, cb, kk * 8 + tig)];
                bl[fn][1] = gsm[POB(s, 1, cb, kk * 8 + tig + 4)];
            }
            #pragma unroll
            for (int fm = 0; fm < 2; fm++)
                #pragma unroll
                for (int fn = 0; fn < 4; fn++) {
                    mmaf16(acc[fm][fn], afh[fm], bh[fn][0], bh[fn][1]);
                    mmaf16(acc[fm][fn], afh[fm], bl[fn][0], bl[fn][1]);
                }
        }
    }

    #pragma unroll
    for (int fn = 0; fn < 4; fn++) {
        const int col = n0 + wn * 32 + fn * 8 + 2 * tig;
        const float b0v = bias[col], b1v = bias[col + 1];
        #pragma unroll
        for (int fm = 0; fm < 2; fm++) {
            const int row = m0 + wm * 32 + fm * 16 + g;
            #pragma unroll
            for (int half = 0; half < 2; half++) {
                const int r = row + half * 8;
                *(float2*)&out[(size_t)r * E + col] =
                    make_float2(acc[fm][fn][half * 2 + 0] + b0v,
                                acc[fm][fn][half * 2 + 1] + b1v);
            }
        }
    }
}

// ---------------------------------------------------------------------------
// Flash attention, split-KV x3 (unchanged from R15).
// smem (words): stage s @ s*3584: KH2[32][36], KL2 @+1152, VT[64][20] @+2304.
//   QLO @7168 (128x36). Total 11776 words = 47,104 B.
// ---------------------------------------------------------------------------
#define KPITCH 36
#define KL_REL 1152
#define VT_OFF 2304
#define STGW 3584
#define QL_OFF 7168
#define ATT_SMEM_WORDS 11776

__global__ __launch_bounds__(256, 2)
void attn_kernel(const float* __restrict__ pb, const float* __restrict__ coeff)
{
    extern __shared__ unsigned sm[];

    const int tid = threadIdx.x;
    const int w = tid >> 5, lane = tid & 31, g = lane >> 2, tig = lane & 3;
    const int q0 = blockIdx.x * 128, split = blockIdx.y, bh = blockIdx.z;
    const int b = bh / H, h = bh - b * H;

    const float* kbp = g_kbias + (size_t)bh * S;

    #pragma unroll
    for (int t = 0; t < 4; t++) {
        int i = tid + t * 256;
        int r = i >> 3, c4 = (i & 7) << 2;
        size_t rowb = ((size_t)bh * S + q0 + r) * (D / 2);
        cpa16(&sm[r * KPITCH + c4], g_Qh2 + rowb + c4);
        cpa16(&sm[QL_OFF + r * KPITCH + c4], g_Ql2 + rowb + c4);
    }
    CP_COMMIT();
    CP_WAIT0();
    __syncthreads();

    unsigned qa[4][4];
    {
        const int qb = (w * 16 + g) * KPITCH;
        #pragma unroll
        for (int kk = 0; kk < 4; kk++) {
            qa[kk][0] = sm[qb + kk * 8 + tig];
            qa[kk][1] = sm[qb + 8 * KPITCH + kk * 8 + tig];
            qa[kk][2] = sm[qb + kk * 8 + tig + 4];
            qa[kk][3] = sm[qb + 8 * KPITCH + kk * 8 + tig + 4];
        }
    }
    __syncthreads();

    const float coeff_h = coeff[h];
    float rowb0 = coeff_h * pb[b * S + q0 + w * 16 + g];
    float rowb1 = coeff_h * pb[b * S + q0 + w * 16 + g + 8];

    float mi[2] = {-1e30f, -1e30f}, li[2] = {0.0f, 0.0f};
    float o[8][4];
    #pragma unroll
    for (int nf = 0; nf < 8; nf++)
        #pragma unroll
        for (int c = 0; c < 4; c++) o[nf][c] = 0.0f;

    const int qlb = QL_OFF + (w * 16 + g) * KPITCH;

    auto issuet = [&](int kt, int sb) {
        const int k0 = kt * 32;
        {
            int r = tid >> 3, c4 = (tid & 7) << 2;
            size_t rowb = ((size_t)bh * S + k0 + r) * (D / 2);
            cpa16(&sm[sb + r * KPITCH + c4], g_Kh2 + rowb + c4);
            cpa16(&sm[sb + KL_REL + r * KPITCH + c4], g_Kl2 + rowb + c4);
        }
        {
            int r = tid >> 2, c = (tid & 3) * 4;
            cpa16(&sm[sb + VT_OFF + r * 20 + c],
                  g_Vt + ((size_t)bh * D + r) * S + k0 + c * 2);
        }
        CP_COMMIT();
    };

    const int kt0 = (64 * split) / NSPLIT;
    const int kt1 = (64 * (split + 1)) / NSPLIT;

    issuet(kt0, 0);
    for (int it = kt0; it < kt1; it++) {
        const int k0 = it * 32;
        CP_WAIT0();
        __syncthreads();
        if (it + 1 < kt1) issuet(it + 1, ((it - kt0 + 1) & 1) * STGW);
        const int sb = ((it - kt0) & 1) * STGW;

        float sc[4][4];
        #pragma unroll
        for (int fn = 0; fn < 4; fn++)
            #pragma unroll
            for (int c = 0; c < 4; c++) sc[fn][c] = 0.0f;

        #pragma unroll
        for (int kk = 0; kk < 4; kk++) {
            unsigned ql[4];
            ql[0] = sm[qlb + kk * 8 + tig];
            ql[1] = sm[qlb + 8 * KPITCH + kk * 8 + tig];
            ql[2] = sm[qlb + kk * 8 + tig + 4];
            ql[3] = sm[qlb + 8 * KPITCH + kk * 8 + tig + 4];
            #pragma unroll
            for (int fn = 0; fn < 4; fn++) {
                int kb = sb + (fn * 8 + g) * KPITCH + kk * 8 + tig;
                unsigned kh0 = sm[kb], kh1 = sm[kb + 4];
                unsigned kl0 = sm[kb + KL_REL], kl1 = sm[kb + KL_REL + 4];
                mmaf16(sc[fn], qa[kk], kh0, kh1);
                mmaf16(sc[fn], ql,     kh0, kh1);
                mmaf16(sc[fn], qa[kk], kl0, kl1);
            }
        }

        #pragma unroll
        for (int fn = 0; fn < 4; fn++) {
            int c = k0 + fn * 8 + 2 * tig;
            float cb0 = kbp[c], cb1 = kbp[c + 1];
            sc[fn][0] += rowb0 + cb0;
            sc[fn][1] += rowb0 + cb1;
            sc[fn][2] += rowb1 + cb0;
            sc[fn][3] += rowb1 + cb1;
        }

        unsigned ph2[4][2];
        #pragma unroll
        for (int rh = 0; rh < 2; rh++) {
            float tm = -1e30f;
            #pragma unroll
            for (int fn = 0; fn < 4; fn++)
                tm = fmaxf(tm, fmaxf(sc[fn][2 * rh], sc[fn][2 * rh + 1]));
            tm = fmaxf(tm, __shfl_xor_sync(0xffffffffu, tm, 1));
            tm = fmaxf(tm, __shfl_xor_sync(0xffffffffu, tm, 2));
            float mnew = fmaxf(fmaxf(mi[rh], tm), -1e20f);
            float psum = 0.0f;
            #pragma unroll
            for (int fn = 0; fn < 4; fn++) {
                float p0 = __expf(sc[fn][2 * rh] - mnew);
                float p1 = __expf(sc[fn][2 * rh + 1] - mnew);
                psum += p0 + p1;
                __half2 hp = __floats2half2_rn(p0, p1);
                ph2[fn][rh] = *reinterpret_cast<unsigned*>(&hp);
            }
            psum += __shfl_xor_sync(0xffffffffu, psum, 1);
            psum += __shfl_xor_sync(0xffffffffu, psum, 2);
            float scale = __expf(mi[rh] - mnew);
            li[rh] = li[rh] * scale + psum;
            mi[rh] = mnew;
            #pragma unroll
            for (int nf = 0; nf < 8; nf++) {
                o[nf][2 * rh]     *= scale;
                o[nf][2 * rh + 1] *= scale;
            }
        }

        #pragma unroll
        for (int j = 0; j < 2; j++) {
            unsigned pa[4] = {ph2[2 * j][0], ph2[2 * j][1],
                              ph2[2 * j + 1][0], ph2[2 * j + 1][1]};
            #pragma unroll
            for (int nf = 0; nf < 8; nf++) {
                int vb = sb + VT_OFF + (nf * 8 + g) * 20 + j * 8 + tig;
                mmaf16(o[nf], pa, sm[vb], sm[vb + 4]);
            }
        }
    }

    const int qg = q0 + w * 16 + g;
    const size_t prow0 = (size_t)split * BHS + (size_t)bh * S + qg;
    const size_t prow1 = prow0 + 8;
    if (tig == 0) {
        *(float2*)&g_pml[prow0 * 2] = make_float2(mi[0], li[0]);
        *(float2*)&g_pml[prow1 * 2] = make_float2(mi[1], li[1]);
    }
    #pragma unroll
    for (int nf = 0; nf < 8; nf++) {
        int d = nf * 8 + 2 * tig;
        *(float2*)&g_po[prow0 * D + d] = make_float2(o[nf][0], o[nf][1]);
        *(float2*)&g_po[prow1 * D + d] = make_float2(o[nf][2], o[nf][3]);
    }
}

// ---------------------------------------------------------------------------
// Merge the three split-KV partials -> g_att2 (f16 plane, [B,S,E] layout)
// ---------------------------------------------------------------------------
__global__ void attn_merge_kernel()
{
    int e = blockIdx.x * 256 + threadIdx.x;    // e < BHS*D/4
    int row = e >> 4;                          // (b*H+h)*S + q
    int dq = (e & 15) << 2;

    float2 ml0 = *(float2*)&g_pml[row * 2];
    float2 ml1 = *(float2*)&g_pml[(BHS + row) * 2];
    float2 ml2 = *(float2*)&g_pml[(2 * BHS + row) * 2];
    float mf = fmaxf(ml0.x, fmaxf(ml1.x, ml2.x));
    float a0 = __expf(ml0.x - mf), a1 = __expf(ml1.x - mf),
          a2 = __expf(ml2.x - mf);
    float inv = 1.0f / (ml0.y * a0 + ml1.y * a1 + ml2.y * a2);
    a0 *= inv; a1 *= inv; a2 *= inv;

    float4 o0 = *(float4*)&g_po[(size_t)row * D + dq];
    float4 o1 = *(float4*)&g_po[(size_t)BHS * D + (size_t)row * D + dq];
    float4 o2 = *(float4*)&g_po[2 * (size_t)BHS * D + (size_t)row * D + dq];

    int q = row & (S - 1);
    int bh = row >> 11;
    int b = bh / H, h = bh - b * H;
    __half2 w0 = __floats2half2_rn(o0.x * a0 + o1.x * a1 + o2.x * a2,
                                   o0.y * a0 + o1.y * a1 + o2.y * a2);
    __half2 w1 = __floats2half2_rn(o0.z * a0 + o1.z * a1 + o2.z * a2,
                                   o0.w * a0 + o1.w * a1 + o2.w * a2);
    size_t wi = ((size_t)(b * S + q) * E + h * D + dq) >> 1;
    *(uint2*)&g_att2[wi] = make_uint2(*reinterpret_cast<unsigned*>(&w0),
                                      *reinterpret_cast<unsigned*>(&w1));
}

// ---------------------------------------------------------------------------
extern "C" void kernel_launch(void* const* d_in, const int* in_sizes, int n_in,
                              void* d_out, int out_size)
{
    const float* query = (const float*)d_in[0];
    const float* key   = (const float*)d_in[1];
    const float* value = (const float*)d_in[2];
    const float* pb    = (const float*)d_in[3];
    const unsigned char* mask = (const unsigned char*)d_in[4];
    const float* wq_w = (const float*)d_in[5];
    const float* wq_b = (const float*)d_in[6];
    const float* wk_w = (const float*)d_in[7];
    const float* wk_b = (const float*)d_in[8];
    const float* wv_w = (const float*)d_in[9];
    const float* wv_b = (const float*)d_in[10];
    const float* fc_w = (const float*)d_in[11];
    const float* fc_b = (const float*)d_in[12];
    const float* coeff = (const float*)d_in[13];
    float* out = (float*)d_out;

    const int attn_smem = ATT_SMEM_WORDS * (int)sizeof(unsigned);  // 47,104 B
    const int qkv_smem  = QKV_SMEM_WORDS * (int)sizeof(unsigned);  // 61,440 B
    const int opj_smem  = OPJ_SMEM_WORDS * (int)sizeof(unsigned);  // 40,960 B
    cudaFuncSetAttribute(attn_kernel,
                         cudaFuncAttributeMaxDynamicSharedMemorySize, attn_smem);
    cudaFuncSetAttribute(qkv_kernel,
                         cudaFuncAttributeMaxDynamicSharedMemorySize, qkv_smem);
    cudaFuncSetAttribute(oproj_kernel,
                         cudaFuncAttributeMaxDynamicSharedMemorySize, opj_smem);

    prep_kernel<<<SPLIT_CTAS + KB_CTAS, 256>>>(query, key, value,
                                               wq_w, wk_w, wv_w, fc_w,
                                               mask, pb, coeff);

    dim3 g1(E / 64, BSZ / 128, 3);    // (12, 32, 3)
    qkv_kernel<<<g1, 256, qkv_smem>>>(wq_b, wk_b, wv_b);

    dim3 g2(S / 128, NSPLIT, B * H);  // (16, 3, 24) = 1152 CTAs
    attn_kernel<<<g2, 256, attn_smem>>>(pb, coeff);

    attn_merge_kernel<<<(BHS * D / 4) / 256, 256>>>();

    dim3 g3(E / 64, BSZ / 128);       // (12, 32)
    oproj_kernel<<<g3, 256, opj_smem>>>(fc_b, out);
}

// round 17
// speedup vs baseline: 3.3075x; 1.0052x over previous
#include <cuda_runtime.h>
#include <cuda_fp16.h>
#include <math.h>

#define B 2
#define S 2048
#define E 768
#define H 12
#define D 64
#define BSZ (B*S)
#define QKV_ELEMS (B*H*S*D)
#define XN (BSZ*E)
#define WN (E*E)
#define BHS (B*H*S)
#define NSPLIT 3
#define LOG2E 1.4426950408889634f

// Scratch (allocation-free rule: device globals) — all f16 half2-packed words
__device__ unsigned g_Xh2[3*XN/2], g_Xl2[3*XN/2];
__device__ unsigned g_Wh2[4*WN/2], g_Wl2[4*WN/2];
__device__ unsigned g_Qh2[QKV_ELEMS/2], g_Ql2[QKV_ELEMS/2];
__device__ unsigned g_Kh2[QKV_ELEMS/2], g_Kl2[QKV_ELEMS/2];
__device__ __half g_Vt[QKV_ELEMS];        // V transposed, f16, [B,H,D,S]
__device__ unsigned g_att2[XN/2];         // attention out, f16 half2 plane
__device__ float g_po[NSPLIT*QKV_ELEMS];  // split-KV partial O (unnormalized)
__device__ float g_pml[NSPLIT*BHS*2];     // split-KV partial (m, l), log2-dom
__device__ float g_kbias[B*H*S];

// ---------------------------------------------------------------------------
__device__ __forceinline__ void splth2(float v0, float v1,
                                       unsigned& hw, unsigned& lw) {
    __half h0 = __float2half_rn(v0);
    __half l0 = __float2half_rn(v0 - __half2float(h0));
    __half h1 = __float2half_rn(v1);
    __half l1 = __float2half_rn(v1 - __half2float(h1));
    __half2 hp = __halves2half2(h0, h1);
    __half2 lp = __halves2half2(l0, l1);
    hw = *reinterpret_cast<unsigned*>(&hp);
    lw = *reinterpret_cast<unsigned*>(&lp);
}
__device__ __forceinline__ float ex2(float x) {
    float r;
    asm("ex2.approx.f32 %0, %1;" : "=f"(r) : "f"(x));
    return r;
}
__device__ __forceinline__ void mmaf16(float* c, const unsigned* a,
                                       unsigned b0, unsigned b1) {
    asm volatile(
        "mma.sync.aligned.m16n8k16.row.col.f32.f16.f16.f32 "
        "{%0,%1,%2,%3},{%4,%5,%6,%7},{%8,%9},{%0,%1,%2,%3};"
        : "+f"(c[0]), "+f"(c[1]), "+f"(c[2]), "+f"(c[3])
        : "r"(a[0]), "r"(a[1]), "r"(a[2]), "r"(a[3]), "r"(b0), "r"(b1));
}
__device__ __forceinline__ void cpa16(void* s, const void* g) {
    unsigned sa = (unsigned)__cvta_generic_to_shared(s);
    asm volatile("cp.async.cg.shared.global [%0], [%1], 16;"
                 :: "r"(sa), "l"(g));
}
#define CP_COMMIT() asm volatile("cp.async.commit_group;")
#define CP_WAIT0()  asm volatile("cp.async.wait_group 0;" ::: "memory")

// ---------------------------------------------------------------------------
// prep: f16 hi/lo split of all 7 inputs + kbias (log2 domain), one kernel.
// ---------------------------------------------------------------------------
#define XQ4 (XN/4)
#define WQ4 (WN/4)
#define SPLIT_CTAS ((3*XQ4 + 4*WQ4) / 256)   // 11520
#define KB_CTAS (BHS / 256)                  // 192

__global__ void prep_kernel(const float* __restrict__ q,
                            const float* __restrict__ k,
                            const float* __restrict__ v,
                            const float* __restrict__ wq,
                            const float* __restrict__ wk,
                            const float* __restrict__ wv,
                            const float* __restrict__ fc,
                            const unsigned char* __restrict__ m,
                            const float* __restrict__ pb,
                            const float* __restrict__ coeff)
{
    if (blockIdx.x < SPLIT_CTAS) {
        int i = blockIdx.x * 256 + threadIdx.x;
        const float* src;
        unsigned *dh, *dl;
        int off;
        if (i < 3 * XQ4) {
            int z = i / XQ4;
            off = i - z * XQ4;
            src = (z == 0) ? q : (z == 1) ? k : v;
            dh = g_Xh2 + (size_t)z * (XN / 2);
            dl = g_Xl2 + (size_t)z * (XN / 2);
        } else {
            int j = i - 3 * XQ4;
            int z = j / WQ4;
            off = j - z * WQ4;
            src = (z == 0) ? wq : (z == 1) ? wk : (z == 2) ? wv : fc;
            dh = g_Wh2 + (size_t)z * (WN / 2);
            dl = g_Wl2 + (size_t)z * (WN / 2);
        }
        float4 vv = ((const float4*)src)[off];
        uint2 hh, ll;
        splth2(vv.x, vv.y, hh.x, ll.x);
        splth2(vv.z, vv.w, hh.y, ll.y);
        ((uint2*)dh)[off] = hh;
        ((uint2*)dl)[off] = ll;
    } else {
        __shared__ int cls[4];
        int tid = threadIdx.x;
        if (tid < 4) cls[tid] = 0;
        __syncthreads();
        for (int i = tid; i < BSZ; i += 256)
            if (m[i]) atomicAdd(&cls[i & 3], 1);
        __syncthreads();
        int mode = 0;
        if (cls[1] == 0 && cls[2] == 0 && cls[3] == 0) mode = 1;  // int32
        else if (cls[0] == 0 && cls[1] == 0)           mode = 2;  // float32

        int idx = (blockIdx.x - SPLIT_CTAS) * 256 + tid;
        int bh = idx / S, kk = idx - bh * S;
        int b = bh / H, h = bh - b * H;
        bool vv;
        int mi = b * S + kk;
        if (mode == 1)      vv = ((const int*)m)[mi] != 0;
        else if (mode == 2) vv = ((const float*)m)[mi] != 0.0f;
        else                vv = m[mi] != 0;
        g_kbias[idx] = (-coeff[h] * pb[mi] + (vv ? 0.0f : -1e30f)) * LOG2E;
    }
}

// ---------------------------------------------------------------------------
// QKV projection, f16 hi/lo 3-product (2-product for V), k32 steps,
// double-buffered cp.async. CTA 128x64, 8 warps (32x32 tiles).
// Q pre-scaled by log2e/8 (log2-domain softmax). V written transposed.
// ---------------------------------------------------------------------------
#define QGA(s,p,r,c) ((s) * 7680 + (p) * 2560 + (r) * 20 + (c))
#define QGB(s,p,r,c) ((s) * 7680 + 5120 + (p) * 1280 + (r) * 20 + (c))
#define QKV_SMEM_WORDS 15360   // 61,440 B

__global__ __launch_bounds__(256, 3)
void qkv_kernel(const float* __restrict__ bq, const float* __restrict__ bk,
                const float* __restrict__ bv)
{
    const int z = blockIdx.z;
    const unsigned* Xh2 = g_Xh2 + (size_t)z * (XN / 2);
    const unsigned* Xl2 = g_Xl2 + (size_t)z * (XN / 2);
    const unsigned* Wh2 = g_Wh2 + (size_t)z * (WN / 2);
    const unsigned* Wl2 = g_Wl2 + (size_t)z * (WN / 2);
    const float* bias = (z == 0) ? bq : (z == 1) ? bk : bv;
    unsigned* oh2 = (z == 0) ? g_Qh2 : g_Kh2;
    unsigned* ol2 = (z == 0) ? g_Ql2 : g_Kl2;
    const bool rope = (z < 2);
    const bool vproj = (z == 2);

    extern __shared__ unsigned gsm[];

    const int tid = threadIdx.x;
    const int w = tid >> 5, wm = w >> 1, wn = w & 1;
    const int lane = tid & 31, g = lane >> 2, tig = lane & 3;
    const int m0 = blockIdx.y * 128, n0 = blockIdx.x * 64;

    float acc[2][4][4];
    #pragma unroll
    for (int a = 0; a < 2; a++)
        #pragma unroll
        for (int b2 = 0; b2 < 4; b2++)
            #pragma unroll
            for (int c = 0; c < 4; c++) acc[a][b2][c] = 0.0f;

    auto issueg = [&](int k0, int s) {
        #pragma unroll
        for (int t = 0; t < 2; t++) {
            int i = tid + t * 256;
            int r = i >> 2, c4 = (i & 3) << 2;
            size_t gi = (size_t)(m0 + r) * (E / 2) + (k0 >> 1) + c4;
            cpa16(&gsm[QGA(s, 0, r, c4)], Xh2 + gi);
            if (!vproj) cpa16(&gsm[QGA(s, 1, r, c4)], Xl2 + gi);
        }
        {
            int rb = tid >> 2, cb4 = (tid & 3) << 2;
            size_t gj = (size_t)(n0 + rb) * (E / 2) + (k0 >> 1) + cb4;
            cpa16(&gsm[QGB(s, 0, rb, cb4)], Wh2 + gj);
            cpa16(&gsm[QGB(s, 1, rb, cb4)], Wl2 + gj);
        }
        CP_COMMIT();
    };

    issueg(0, 0);
    for (int it = 0; it < E / 32; it++) {
        CP_WAIT0();
        __syncthreads();
        if (it + 1 < E / 32) issueg((it + 1) * 32, (it + 1) & 1);
        const int s = it & 1;
        #pragma unroll
        for (int kk = 0; kk < 2; kk++) {
            unsigned afh[2][4], afl[2][4], bh[4][2], bl[4][2];
            #pragma unroll
            for (int fm = 0; fm < 2; fm++) {
                int rb = wm * 32 + fm * 16 + g;
                afh[fm][0] = gsm[QGA(s, 0, rb,     kk * 8 + tig)];
                afh[fm][1] = gsm[QGA(s, 0, rb + 8, kk * 8 + tig)];
                afh[fm][2] = gsm[QGA(s, 0, rb,     kk * 8 + tig + 4)];
                afh[fm][3] = gsm[QGA(s, 0, rb + 8, kk * 8 + tig + 4)];
                if (!vproj) {
                    afl[fm][0] = gsm[QGA(s, 1, rb,     kk * 8 + tig)];
                    afl[fm][1] = gsm[QGA(s, 1, rb + 8, kk * 8 + tig)];
                    afl[fm][2] = gsm[QGA(s, 1, rb,     kk * 8 + tig + 4)];
                    afl[fm][3] = gsm[QGA(s, 1, rb + 8, kk * 8 + tig + 4)];
                }
            }
            #pragma unroll
            for (int fn = 0; fn < 4; fn++) {
                int cb = wn * 32 + fn * 8 + g;
                bh[fn][0] = gsm[QGB(s, 0, cb, kk * 8 + tig)];
                bh[fn][1] = gsm[QGB(s, 0, cb, kk * 8 + tig + 4)];
                bl[fn][0] = gsm[QGB(s, 1, cb, kk * 8 + tig)];
                bl[fn][1] = gsm[QGB(s, 1, cb, kk * 8 + tig + 4)];
            }
            #pragma unroll
            for (int fm = 0; fm < 2; fm++)
                #pragma unroll
                for (int fn = 0; fn < 4; fn++) {
                    mmaf16(acc[fm][fn], afh[fm], bh[fn][0], bh[fn][1]);
                    if (!vproj)
                        mmaf16(acc[fm][fn], afl[fm], bh[fn][0], bh[fn][1]);
                    mmaf16(acc[fm][fn], afh[fm], bl[fn][0], bl[fn][1]);
                }
        }
    }

    // epilogue: bias + RoPE (fp32) [+ log2e/8 Q-scale]
    #pragma unroll
    for (int fn = 0; fn < 4; fn++) {
        const int col = n0 + wn * 32 + fn * 8 + 2 * tig;
        const int h = col / D, d = col % D;
        const float b0v = bias[col], b1v = bias[col + 1];
        const float invf = rope
            ? exp2f(-(float)d * (13.287712379549449f / 64.0f)) : 0.0f;
        #pragma unroll
        for (int fm = 0; fm < 2; fm++) {
            const int row = m0 + wm * 32 + fm * 16 + g;
            #pragma unroll
            for (int half = 0; half < 2; half++) {
                const int r = row + half * 8;
                const int bb = r >> 11, sdx = r & 2047;
                float v0 = acc[fm][fn][half * 2 + 0] + b0v;
                float v1 = acc[fm][fn][half * 2 + 1] + b1v;
                if (rope) {
                    float sn, cs;
                    sincosf((float)sdx * invf, &sn, &cs);
                    float t0 = v0 * cs - v1 * sn;
                    v1 = v1 * cs + v0 * sn;
                    v0 = t0;
                }
                if (z == 0) {
                    v0 *= 0.125f * LOG2E;
                    v1 *= 0.125f * LOG2E;
                }
                if (vproj) {
                    size_t vt = (((size_t)bb * H + h) * D + d) * S + sdx;
                    g_Vt[vt]     = __float2half_rn(v0);
                    g_Vt[vt + S] = __float2half_rn(v1);
                } else {
                    const size_t idx = (((size_t)bb * H + h) * S + sdx) * D + d;
                    unsigned hw, lw;
                    splth2(v0, v1, hw, lw);
                    oh2[idx >> 1] = hw;
                    ol2[idx >> 1] = lw;
                }
            }
        }
    }
}

// ---------------------------------------------------------------------------
// Output projection: A = g_att2 (f16 plane), W f16 hi/lo (2 products), k32.
// ---------------------------------------------------------------------------
#define POA(s,r,c)   ((s) * 5120 + (r) * 20 + (c))
#define POB(s,p,r,c) ((s) * 5120 + 2560 + (p) * 1280 + (r) * 20 + (c))
#define OPJ_SMEM_WORDS 10240   // 40,960 B

__global__ __launch_bounds__(256, 3)
void oproj_kernel(const float* __restrict__ bias, float* __restrict__ out)
{
    const unsigned* Wh2 = g_Wh2 + (size_t)3 * (WN / 2);
    const unsigned* Wl2 = g_Wl2 + (size_t)3 * (WN / 2);

    extern __shared__ unsigned gsm[];

    const int tid = threadIdx.x;
    const int w = tid >> 5, wm = w >> 1, wn = w & 1;
    const int lane = tid & 31, g = lane >> 2, tig = lane & 3;
    const int m0 = blockIdx.y * 128, n0 = blockIdx.x * 64;

    float acc[2][4][4];
    #pragma unroll
    for (int a = 0; a < 2; a++)
        #pragma unroll
        for (int b2 = 0; b2 < 4; b2++)
            #pragma unroll
            for (int c = 0; c < 4; c++) acc[a][b2][c] = 0.0f;

    auto issueg = [&](int k0, int s) {
        #pragma unroll
        for (int t = 0; t < 2; t++) {
            int i = tid + t * 256;
            int r = i >> 2, c4 = (i & 3) << 2;
            size_t gi = (size_t)(m0 + r) * (E / 2) + (k0 >> 1) + c4;
            cpa16(&gsm[POA(s, r, c4)], g_att2 + gi);
        }
        {
            int rb = tid >> 2, cb4 = (tid & 3) << 2;
            size_t gj = (size_t)(n0 + rb) * (E / 2) + (k0 >> 1) + cb4;
            cpa16(&gsm[POB(s, 0, rb, cb4)], Wh2 + gj);
            cpa16(&gsm[POB(s, 1, rb, cb4)], Wl2 + gj);
        }
        CP_COMMIT();
    };

    issueg(0, 0);
    for (int it = 0; it < E / 32; it++) {
        CP_WAIT0();
        __syncthreads();
        if (it + 1 < E / 32) issueg((it + 1) * 32, (it + 1) & 1);
        const int s = it & 1;
        #pragma unroll
        for (int kk = 0; kk < 2; kk++) {
            unsigned afh[2][4], bh[4][2], bl[4][2];
            #pragma unroll
            for (int fm = 0; fm < 2; fm++) {
                int rb = wm * 32 + fm * 16 + g;
                afh[fm][0] = gsm[POA(s, rb,     kk * 8 + tig)];
                afh[fm][1] = gsm[POA(s, rb + 8, kk * 8 + tig)];
                afh[fm][2] = gsm[POA(s, rb,     kk * 8 + tig + 4)];
                afh[fm][3] = gsm[POA(s, rb + 8, kk * 8 + tig + 4)];
            }
            #pragma unroll
            for (int fn = 0; fn < 4; fn++) {
                int cb = wn * 32 + fn * 8 + g;
                bh[fn][0] = gsm[POB(s, 0, cb, kk * 8 + tig)];
                bh[fn][1] = gsm[POB(s, 0, cb, kk * 8 + tig + 4)];
                bl[fn][0] = gsm[POB(s, 1, cb, kk * 8 + tig)];
                bl[fn][1] = gsm[POB(s, 1, cb, kk * 8 + tig + 4)];
            }
            #pragma unroll
            for (int fm = 0; fm < 2; fm++)
                #pragma unroll
                for (int fn = 0; fn < 4; fn++) {
                    mmaf16(acc[fm][fn], afh[fm], bh[fn][0], bh[fn][1]);
                    mmaf16(acc[fm][fn], afh[fm], bl[fn][0], bl[fn][1]);
                }
        }
    }

    #pragma unroll
    for (int fn = 0; fn < 4; fn++) {
        const int col = n0 + wn * 32 + fn * 8 + 2 * tig;
        const float b0v = bias[col], b1v = bias[col + 1];
        #pragma unroll
        for (int fm = 0; fm < 2; fm++) {
            const int row = m0 + wm * 32 + fm * 16 + g;
            #pragma unroll
            for (int half = 0; half < 2; half++) {
                const int r = row + half * 8;
                *(float2*)&out[(size_t)r * E + col] =
                    make_float2(acc[fm][fn][half * 2 + 0] + b0v,
                                acc[fm][fn][half * 2 + 1] + b1v);
            }
        }
    }
}

// ---------------------------------------------------------------------------
// Flash attention, split-KV x3. Q-hi AND Q-lo persistent in smem (frees regs
// for 3 CTAs/SM). log2-domain softmax (raw ex2).
// smem (words): stage s @ s*3584: KH2[32][36], KL2 @+1152, VT[64][20] @+2304.
//   QH @7168 (128x36), QL @11776 (128x36). Total 16384 words = 65,536 B.
// ---------------------------------------------------------------------------
#define KPITCH 36
#define KL_REL 1152
#define VT_OFF 2304
#define STGW 3584
#define QH_OFF 7168
#define QL_OFF 11776
#define ATT_SMEM_WORDS 16384

__global__ __launch_bounds__(256, 3)
void attn_kernel(const float* __restrict__ pb, const float* __restrict__ coeff)
{
    extern __shared__ unsigned sm[];

    const int tid = threadIdx.x;
    const int w = tid >> 5, lane = tid & 31, g = lane >> 2, tig = lane & 3;
    const int q0 = blockIdx.x * 128, split = blockIdx.y, bh = blockIdx.z;
    const int b = bh / H, h = bh - b * H;

    const float* kbp = g_kbias + (size_t)bh * S;

    // ---- prologue: Q-hi -> QH, Q-lo -> QL (persistent) ----
    #pragma unroll
    for (int t = 0; t < 4; t++) {
        int i = tid + t * 256;
        int r = i >> 3, c4 = (i & 7) << 2;
        size_t rowb = ((size_t)bh * S + q0 + r) * (D / 2);
        cpa16(&sm[QH_OFF + r * KPITCH + c4], g_Qh2 + rowb + c4);
        cpa16(&sm[QL_OFF + r * KPITCH + c4], g_Ql2 + rowb + c4);
    }
    CP_COMMIT();

    const float coeff_h = coeff[h];
    float rowb0 = coeff_h * pb[b * S + q0 + w * 16 + g] * LOG2E;
    float rowb1 = coeff_h * pb[b * S + q0 + w * 16 + g + 8] * LOG2E;

    float mi[2] = {-1e30f, -1e30f}, li[2] = {0.0f, 0.0f};
    float o[8][4];
    #pragma unroll
    for (int nf = 0; nf < 8; nf++)
        #pragma unroll
        for (int c = 0; c < 4; c++) o[nf][c] = 0.0f;

    const int qhb = QH_OFF + (w * 16 + g) * KPITCH;
    const int qlb = QL_OFF + (w * 16 + g) * KPITCH;

    auto issuet = [&](int kt, int sb) {
        const int k0 = kt * 32;
        {
            int r = tid >> 3, c4 = (tid & 7) << 2;
            size_t rowb = ((size_t)bh * S + k0 + r) * (D / 2);
            cpa16(&sm[sb + r * KPITCH + c4], g_Kh2 + rowb + c4);
            cpa16(&sm[sb + KL_REL + r * KPITCH + c4], g_Kl2 + rowb + c4);
        }
        {
            int r = tid >> 2, c = (tid & 3) * 4;
            cpa16(&sm[sb + VT_OFF + r * 20 + c],
                  g_Vt + ((size_t)bh * D + r) * S + k0 + c * 2);
        }
        CP_COMMIT();
    };

    const int kt0 = (64 * split) / NSPLIT;
    const int kt1 = (64 * (split + 1)) / NSPLIT;

    issuet(kt0, 0);
    for (int it = kt0; it < kt1; it++) {
        const int k0 = it * 32;
        CP_WAIT0();
        __syncthreads();
        if (it + 1 < kt1) issuet(it + 1, ((it - kt0 + 1) & 1) * STGW);
        const int sb = ((it - kt0) & 1) * STGW;

        // ---- S' = (QK^T + bias) in log2 domain; f16 hi/lo 3-product ----
        float sc[4][4];
        #pragma unroll
        for (int fn = 0; fn < 4; fn++)
            #pragma unroll
            for (int c = 0; c < 4; c++) sc[fn][c] = 0.0f;

        #pragma unroll
        for (int kk = 0; kk < 4; kk++) {
            unsigned qh[4], ql[4];
            qh[0] = sm[qhb + kk * 8 + tig];
            qh[1] = sm[qhb + 8 * KPITCH + kk * 8 + tig];
            qh[2] = sm[qhb + kk * 8 + tig + 4];
            qh[3] = sm[qhb + 8 * KPITCH + kk * 8 + tig + 4];
            ql[0] = sm[qlb + kk * 8 + tig];
            ql[1] = sm[qlb + 8 * KPITCH + kk * 8 + tig];
            ql[2] = sm[qlb + kk * 8 + tig + 4];
            ql[3] = sm[qlb + 8 * KPITCH + kk * 8 + tig + 4];
            #pragma unroll
            for (int fn = 0; fn < 4; fn++) {
                int kb = sb + (fn * 8 + g) * KPITCH + kk * 8 + tig;
                unsigned kh0 = sm[kb], kh1 = sm[kb + 4];
                unsigned kl0 = sm[kb + KL_REL], kl1 = sm[kb + KL_REL + 4];
                mmaf16(sc[fn], qh, kh0, kh1);
                mmaf16(sc[fn], ql, kh0, kh1);
                mmaf16(sc[fn], qh, kl0, kl1);
            }
        }

        #pragma unroll
        for (int fn = 0; fn < 4; fn++) {
            int c = k0 + fn * 8 + 2 * tig;
            float cb0 = kbp[c], cb1 = kbp[c + 1];
            sc[fn][0] += rowb0 + cb0;
            sc[fn][1] += rowb0 + cb1;
            sc[fn][2] += rowb1 + cb0;
            sc[fn][3] += rowb1 + cb1;
        }

        // ---- online softmax (log2 domain, raw ex2) ----
        unsigned ph2[4][2];
        #pragma unroll
        for (int rh = 0; rh < 2; rh++) {
            float tm = -1e30f;
            #pragma unroll
            for (int fn = 0; fn < 4; fn++)
                tm = fmaxf(tm, fmaxf(sc[fn][2 * rh], sc[fn][2 * rh + 1]));
            tm = fmaxf(tm, __shfl_xor_sync(0xffffffffu, tm, 1));
            tm = fmaxf(tm, __shfl_xor_sync(0xffffffffu, tm, 2));
            float mnew = fmaxf(fmaxf(mi[rh], tm), -1e20f);
            float psum = 0.0f;
            #pragma unroll
            for (int fn = 0; fn < 4; fn++) {
                float p0 = ex2(sc[fn][2 * rh] - mnew);
                float p1 = ex2(sc[fn][2 * rh + 1] - mnew);
                psum += p0 + p1;
                __half2 hp = __floats2half2_rn(p0, p1);
                ph2[fn][rh] = *reinterpret_cast<unsigned*>(&hp);
            }
            psum += __shfl_xor_sync(0xffffffffu, psum, 1);
            psum += __shfl_xor_sync(0xffffffffu, psum, 2);
            float scale = ex2(mi[rh] - mnew);
            li[rh] = li[rh] * scale + psum;
            mi[rh] = mnew;
            #pragma unroll
            for (int nf = 0; nf < 8; nf++) {
                o[nf][2 * rh]     *= scale;
                o[nf][2 * rh + 1] *= scale;
            }
        }

        // ---- O += P V (f16 mma, P from registers, V transposed) ----
        #pragma unroll
        for (int j = 0; j < 2; j++) {
            unsigned pa[4] = {ph2[2 * j][0], ph2[2 * j][1],
                              ph2[2 * j + 1][0], ph2[2 * j + 1][1]};
            #pragma unroll
            for (int nf = 0; nf < 8; nf++) {
                int vb = sb + VT_OFF + (nf * 8 + g) * 20 + j * 8 + tig;
                mmaf16(o[nf], pa, sm[vb], sm[vb + 4]);
            }
        }
    }

    // ---- store partial (unnormalized O, m, l) to gmem ----
    const int qg = q0 + w * 16 + g;
    const size_t prow0 = (size_t)split * BHS + (size_t)bh * S + qg;
    const size_t prow1 = prow0 + 8;
    if (tig == 0) {
        *(float2*)&g_pml[prow0 * 2] = make_float2(mi[0], li[0]);
        *(float2*)&g_pml[prow1 * 2] = make_float2(mi[1], li[1]);
    }
    #pragma unroll
    for (int nf = 0; nf < 8; nf++) {
        int d = nf * 8 + 2 * tig;
        *(float2*)&g_po[prow0 * D + d] = make_float2(o[nf][0], o[nf][1]);
        *(float2*)&g_po[prow1 * D + d] = make_float2(o[nf][2], o[nf][3]);
    }
}

// ---------------------------------------------------------------------------
// Merge the three split-KV partials (log2 domain) -> g_att2 (f16 plane)
// ---------------------------------------------------------------------------
__global__ void attn_merge_kernel()
{
    int e = blockIdx.x * 256 + threadIdx.x;    // e < BHS*D/4
    int row = e >> 4;                          // (b*H+h)*S + q
    int dq = (e & 15) << 2;

    float2 ml0 = *(float2*)&g_pml[row * 2];
    float2 ml1 = *(float2*)&g_pml[(BHS + row) * 2];
    float2 ml2 = *(float2*)&g_pml[(2 * BHS + row) * 2];
    float mf = fmaxf(ml0.x, fmaxf(ml1.x, ml2.x));
    float a0, a1, a2;
    asm("ex2.approx.f32 %0, %1;" : "=f"(a0) : "f"(ml0.x - mf));
    asm("ex2.approx.f32 %0, %1;" : "=f"(a1) : "f"(ml1.x - mf));
    asm("ex2.approx.f32 %0, %1;" : "=f"(a2) : "f"(ml2.x - mf));
    float inv = 1.0f / (ml0.y * a0 + ml1.y * a1 + ml2.y * a2);
    a0 *= inv; a1 *= inv; a2 *= inv;

    float4 o0 = *(float4*)&g_po[(size_t)row * D + dq];
    float4 o1 = *(float4*)&g_po[(size_t)BHS * D + (size_t)row * D + dq];
    float4 o2 = *(float4*)&g_po[2 * (size_t)BHS * D + (size_t)row * D + dq];

    int q = row & (S - 1);
    int bh = row >> 11;
    int b = bh / H, h = bh - b * H;
    __half2 w0 = __floats2half2_rn(o0.x * a0 + o1.x * a1 + o2.x * a2,
                                   o0.y * a0 + o1.y * a1 + o2.y * a2);
    __half2 w1 = __floats2half2_rn(o0.z * a0 + o1.z * a1 + o2.z * a2,
                                   o0.w * a0 + o1.w * a1 + o2.w * a2);
    size_t wi = ((size_t)(b * S + q) * E + h * D + dq) >> 1;
    *(uint2*)&g_att2[wi] = make_uint2(*reinterpret_cast<unsigned*>(&w0),
                                      *reinterpret_cast<unsigned*>(&w1));
}

// ---------------------------------------------------------------------------
extern "C" void kernel_launch(void* const* d_in, const int* in_sizes, int n_in,
                              void* d_out, int out_size)
{
    const float* query = (const float*)d_in[0];
    const float* key   = (const float*)d_in[1];
    const float* value = (const float*)d_in[2];
    const float* pb    = (const float*)d_in[3];
    const unsigned char* mask = (const unsigned char*)d_in[4];
    const float* wq_w = (const float*)d_in[5];
    const float* wq_b = (const float*)d_in[6];
    const float* wk_w = (const float*)d_in[7];
    const float* wk_b = (const float*)d_in[8];
    const float* wv_w = (const float*)d_in[9];
    const float* wv_b = (const float*)d_in[10];
    const float* fc_w = (const float*)d_in[11];
    const float* fc_b = (const float*)d_in[12];
    const float* coeff = (const float*)d_in[13];
    float* out = (float*)d_out;

    const int attn_smem = ATT_SMEM_WORDS * (int)sizeof(unsigned);  // 65,536 B
    const int qkv_smem  = QKV_SMEM_WORDS * (int)sizeof(unsigned);  // 61,440 B
    const int opj_smem  = OPJ_SMEM_WORDS * (int)sizeof(unsigned);  // 40,960 B
    cudaFuncSetAttribute(attn_kernel,
                         cudaFuncAttributeMaxDynamicSharedMemorySize, attn_smem);
    cudaFuncSetAttribute(qkv_kernel,
                         cudaFuncAttributeMaxDynamicSharedMemorySize, qkv_smem);
    cudaFuncSetAttribute(oproj_kernel,
                         cudaFuncAttributeMaxDynamicSharedMemorySize, opj_smem);

    prep_kernel<<<SPLIT_CTAS + KB_CTAS, 256>>>(query, key, value,
                                               wq_w, wk_w, wv_w, fc_w,
                                               mask, pb, coeff);

    dim3 g1(E / 64, BSZ / 128, 3);    // (12, 32, 3)
    qkv_kernel<<<g1, 256, qkv_smem>>>(wq_b, wk_b, wv_b);

    dim3 g2(S / 128, NSPLIT, B * H);  // (16, 3, 24) = 1152 CTAs
    attn_kernel<<<g2, 256, attn_smem>>>(pb, coeff);

    attn_merge_kernel<<<(BHS * D / 4) / 256, 256>>>();

    dim3 g3(E / 64, BSZ / 128);       // (12, 32)
    oproj_kernel<<<g3, 256, opj_smem>>>(fc_b, out);
}